// round 9
// baseline (speedup 1.0000x reference)
#include <cuda_runtime.h>
#include <math.h>

#define BB    8
#define NN    2048
#define KKN   20
#define PP    64
#define PSZ   32
#define DD    1024
#define TT    65
#define TOK   (BB*TT)     // 520
#define INNER 512
#define NHEAD 8
#define DHEAD 64
#define MLPD  2048
#define DEPTH 6
#define EPSV  1e-5f
#define NBIN  64

// ---------------- scratch (static device globals; no runtime allocation) ----
__device__ float  g_h0 [BB*3*NN];                     // transposed xyz [B,3,N]
__device__ float  g_H  [BB*512*NN];                   // concat features [B,512,N]
__device__ float  g_xx[BB*NN];
__device__ int    g_idx[BB*NN*KKN];
__device__ float  g_y [(size_t)BB*NN*KKN*256];        // 335MB scratch: dist matrix, then conv y
__device__ float  g_ft [BB*NN*128];                   // row-major features [B*N][Cld]
__device__ float  g_fpadB[BB*16*NN];                  // zero-padded xyz [B,16,N]
__device__ double g_sumd[256*NBIN];
__device__ double g_ssqd[256*NBIN];
__device__ float  g_mu [1024];
__device__ float  g_rs [1024];
__device__ float  g_t  [TOK*DD];
__device__ float  g_hn [TOK*DD];
__device__ float  g_qkv[TOK*3*INNER];
__device__ float  g_z  [TOK*INNER];
__device__ float  g_ff [TOK*MLPD];

// ------- stage 0: transpose x + build padded B operand + conv1 ft rows -------
__global__ void k_transpose_x(const float* __restrict__ x) {
    int id = blockIdx.x*256 + threadIdx.x;
    if (id >= BB*NN) return;
    int b = id / NN, n = id % NN;
    float v[3];
    #pragma unroll
    for (int c = 0; c < 3; c++) {
        v[c] = x[id*3 + c];
        g_h0[(b*3+c)*NN + n] = v[c];
        g_fpadB[(b*16+c)*NN + n] = v[c];
    }
    #pragma unroll
    for (int c = 3; c < 16; c++) g_fpadB[(b*16+c)*NN + n] = 0.f;
    #pragma unroll
    for (int c = 0; c < 16; c++) g_ft[(size_t)id*16 + c] = (c < 3) ? v[c] : 0.f;
}

// ---------------- xx = sum_c x^2 ---------------------------------------------
__global__ void k_xx(const float* __restrict__ src, int Ctot, int coff, int C) {
    int id = blockIdx.x*256 + threadIdx.x;
    if (id >= BB*NN) return;
    int b = id / NN, m = id % NN;
    float s = 0.f;
    for (int c = 0; c < C; c++) {
        float v = src[((size_t)b*Ctot + coff + c)*NN + m];
        s = fmaf(v, v, s);
    }
    g_xx[id] = s;
}

// ---------------- build row-major feature copy [B*N][Kpad] -------------------
__global__ void k_featT(const float* __restrict__ src, int Ctot, int coff, int C,
                        int Kpad, float* __restrict__ out) {
    int id = blockIdx.x*256 + threadIdx.x;
    if (id >= BB*NN*Kpad) return;
    int c = id % Kpad; int rem = id / Kpad;
    int n = rem % NN, b = rem / NN;
    out[id] = (c < C) ? src[((size_t)b*Ctot + coff + c)*NN + n] : 0.f;
}

// ---------------- generic tiled fp32 GEMM (64x64) ----------------------------
// epi: 0 plain, 4 dist
__global__ void k_gemm(const float* __restrict__ A, const float* __restrict__ Bm,
                       const float* __restrict__ bias, const float* __restrict__ xx,
                       float* dst,
                       int M, int Nc, int Kc, long sA, long sB, long sC, int epi) {
    __shared__ __align__(16) float As[16][64];
    __shared__ __align__(16) float Bs[16][64];
    int tid = threadIdx.x;
    int tx = tid & 15, ty = tid >> 4;
    int row0 = blockIdx.y*64, col0 = blockIdx.x*64;
    const float* Ap = A + (size_t)blockIdx.z*sA;
    const float* Bp = Bm + (size_t)blockIdx.z*sB;
    float acc[4][4] = {};
    int r = tid >> 2, kq = tid & 3;
    for (int kt = 0; kt < Kc; kt += 16) {
        float4 a4 = make_float4(0.f, 0.f, 0.f, 0.f);
        int row = row0 + r;
        if (row < M) a4 = *(const float4*)&Ap[(size_t)row*Kc + kt + kq*4];
        As[kq*4+0][r] = a4.x; As[kq*4+1][r] = a4.y;
        As[kq*4+2][r] = a4.z; As[kq*4+3][r] = a4.w;
        #pragma unroll
        for (int i = 0; i < 4; i++) {
            int kr = (tid >> 6) + i*4;
            Bs[kr][tid & 63] = Bp[(size_t)(kt + kr)*Nc + col0 + (tid & 63)];
        }
        __syncthreads();
        #pragma unroll
        for (int kk = 0; kk < 16; kk++) {
            float4 a = *(const float4*)&As[kk][ty*4];
            float4 bq = *(const float4*)&Bs[kk][tx*4];
            acc[0][0] = fmaf(a.x, bq.x, acc[0][0]); acc[0][1] = fmaf(a.x, bq.y, acc[0][1]);
            acc[0][2] = fmaf(a.x, bq.z, acc[0][2]); acc[0][3] = fmaf(a.x, bq.w, acc[0][3]);
            acc[1][0] = fmaf(a.y, bq.x, acc[1][0]); acc[1][1] = fmaf(a.y, bq.y, acc[1][1]);
            acc[1][2] = fmaf(a.y, bq.z, acc[1][2]); acc[1][3] = fmaf(a.y, bq.w, acc[1][3]);
            acc[2][0] = fmaf(a.z, bq.x, acc[2][0]); acc[2][1] = fmaf(a.z, bq.y, acc[2][1]);
            acc[2][2] = fmaf(a.z, bq.z, acc[2][2]); acc[2][3] = fmaf(a.z, bq.w, acc[2][3]);
            acc[3][0] = fmaf(a.w, bq.x, acc[3][0]); acc[3][1] = fmaf(a.w, bq.y, acc[3][1]);
            acc[3][2] = fmaf(a.w, bq.z, acc[3][2]); acc[3][3] = fmaf(a.w, bq.w, acc[3][3]);
        }
        __syncthreads();
    }
    float* Dp = dst + (size_t)blockIdx.z*sC;
    const float* xxz = (epi == 4) ? (xx + (size_t)blockIdx.z*Nc) : nullptr;
    #pragma unroll
    for (int i = 0; i < 4; i++) {
        int row = row0 + ty*4 + i;
        if (row >= M) continue;
        #pragma unroll
        for (int j = 0; j < 4; j++) {
            int col = col0 + tx*4 + j;
            float v = acc[i][j];
            if (epi == 4) v = 2.0f*v - xxz[row] - xxz[col];
            Dp[(size_t)row*Nc + col] = v;
        }
    }
}

// ---------------- 128x128-tile fp32 GEMM (8x8/thread), optional symmetry -----
__global__ void __launch_bounds__(256) k_gemm128(
        const float* __restrict__ A, const float* __restrict__ Bm,
        const float* __restrict__ xx, float* __restrict__ dst,
        int M, int Nc, int Kc,
        long sA, long sB, long sC, int lda, int ldb, int epi, int sym) {
    int bx = blockIdx.x, by = blockIdx.y;
    if (sym && bx < by) return;
    __shared__ __align__(16) float As[16][128];
    __shared__ __align__(16) float Bs[16][128];
    int tid = threadIdx.x;
    int tx = tid & 15, ty = tid >> 4;
    int row0 = by*128, col0 = bx*128;
    const float* Ap = A + (size_t)blockIdx.z*sA;
    const float* Bp = Bm + (size_t)blockIdx.z*sB;
    float acc[8][8] = {};
    int ar = tid >> 1, ak = (tid & 1)*8;
    int bkr = tid >> 4, bc4 = (tid & 15)*8;
    for (int kt = 0; kt < Kc; kt += 16) {
        float4 a0 = make_float4(0.f,0.f,0.f,0.f), a1 = a0;
        int arow = row0 + ar;
        if (arow < M) {
            a0 = *(const float4*)&Ap[(size_t)arow*lda + kt + ak];
            a1 = *(const float4*)&Ap[(size_t)arow*lda + kt + ak + 4];
        }
        As[ak+0][ar] = a0.x; As[ak+1][ar] = a0.y; As[ak+2][ar] = a0.z; As[ak+3][ar] = a0.w;
        As[ak+4][ar] = a1.x; As[ak+5][ar] = a1.y; As[ak+6][ar] = a1.z; As[ak+7][ar] = a1.w;
        *(float4*)&Bs[bkr][bc4]   = *(const float4*)&Bp[(size_t)(kt+bkr)*ldb + col0 + bc4];
        *(float4*)&Bs[bkr][bc4+4] = *(const float4*)&Bp[(size_t)(kt+bkr)*ldb + col0 + bc4 + 4];
        __syncthreads();
        #pragma unroll
        for (int kk = 0; kk < 16; kk++) {
            float av[8], bv[8];
            *(float4*)&av[0] = *(const float4*)&As[kk][ty*8];
            *(float4*)&av[4] = *(const float4*)&As[kk][ty*8+4];
            *(float4*)&bv[0] = *(const float4*)&Bs[kk][tx*8];
            *(float4*)&bv[4] = *(const float4*)&Bs[kk][tx*8+4];
            #pragma unroll
            for (int i = 0; i < 8; i++)
                #pragma unroll
                for (int j = 0; j < 8; j++)
                    acc[i][j] = fmaf(av[i], bv[j], acc[i][j]);
        }
        __syncthreads();
    }
    float* Dp = dst + (size_t)blockIdx.z*sC;
    if (epi == 4) {
        const float* xxz = xx + (size_t)blockIdx.z*Nc;
        float xr[8], xc[8];
        #pragma unroll
        for (int i = 0; i < 8; i++) xr[i] = xxz[row0 + ty*8 + i];
        #pragma unroll
        for (int j = 0; j < 8; j++) xc[j] = xxz[col0 + tx*8 + j];
        #pragma unroll
        for (int i = 0; i < 8; i++) {
            int row = row0 + ty*8 + i;
            float v[8];
            #pragma unroll
            for (int j = 0; j < 8; j++) v[j] = 2.0f*acc[i][j] - xr[i] - xc[j];
            *(float4*)&Dp[(size_t)row*Nc + col0 + tx*8]     = *(float4*)&v[0];
            *(float4*)&Dp[(size_t)row*Nc + col0 + tx*8 + 4] = *(float4*)&v[4];
        }
        if (sym && bx != by) {
            #pragma unroll
            for (int j = 0; j < 8; j++) {
                int col = col0 + tx*8 + j;
                float tv[8];
                #pragma unroll
                for (int i = 0; i < 8; i++) tv[i] = 2.0f*acc[i][j] - xr[i] - xc[j];
                *(float4*)&Dp[(size_t)col*Nc + row0 + ty*8]     = *(float4*)&tv[0];
                *(float4*)&Dp[(size_t)col*Nc + row0 + ty*8 + 4] = *(float4*)&tv[4];
            }
        }
    } else {
        #pragma unroll
        for (int i = 0; i < 8; i++) {
            int row = row0 + ty*8 + i;
            if (row >= M) continue;
            *(float4*)&Dp[(size_t)row*Nc + col0 + tx*8]     = *(float4*)&acc[i][0];
            *(float4*)&Dp[(size_t)row*Nc + col0 + tx*8 + 4] = *(float4*)&acc[i][4];
        }
    }
}

// ---------------- 64x128-tile GEMM for transformer (TM=4, TN=8) --------------
// epi: 0 plain, 2 gelu(v+bias), 3 v+bias+dst residual
__global__ void __launch_bounds__(256) k_gemmT(
        const float* __restrict__ A, const float* __restrict__ Bm,
        const float* __restrict__ bias, float* __restrict__ dst,
        int M, int Nc, int Kc, int epi) {
    __shared__ __align__(16) float As[16][64];
    __shared__ __align__(16) float Bs[16][128];
    int tid = threadIdx.x;
    int tx = tid & 15, ty = tid >> 4;
    int row0 = blockIdx.y*64, col0 = blockIdx.x*128;
    float acc[4][8] = {};
    int ar = tid >> 2, ak = (tid & 3)*4;
    int bkr = tid >> 4, bc = (tid & 15)*8;
    for (int kt = 0; kt < Kc; kt += 16) {
        float4 a4 = make_float4(0.f,0.f,0.f,0.f);
        int arow = row0 + ar;
        if (arow < M) a4 = *(const float4*)&A[(size_t)arow*Kc + kt + ak];
        As[ak+0][ar] = a4.x; As[ak+1][ar] = a4.y;
        As[ak+2][ar] = a4.z; As[ak+3][ar] = a4.w;
        *(float4*)&Bs[bkr][bc]   = *(const float4*)&Bm[(size_t)(kt+bkr)*Nc + col0 + bc];
        *(float4*)&Bs[bkr][bc+4] = *(const float4*)&Bm[(size_t)(kt+bkr)*Nc + col0 + bc + 4];
        __syncthreads();
        #pragma unroll
        for (int kk = 0; kk < 16; kk++) {
            float av[4], bv[8];
            *(float4*)&av[0] = *(const float4*)&As[kk][ty*4];
            *(float4*)&bv[0] = *(const float4*)&Bs[kk][tx*8];
            *(float4*)&bv[4] = *(const float4*)&Bs[kk][tx*8+4];
            #pragma unroll
            for (int i = 0; i < 4; i++)
                #pragma unroll
                for (int j = 0; j < 8; j++)
                    acc[i][j] = fmaf(av[i], bv[j], acc[i][j]);
        }
        __syncthreads();
    }
    #pragma unroll
    for (int i = 0; i < 4; i++) {
        int row = row0 + ty*4 + i;
        if (row >= M) continue;
        float* dp = dst + (size_t)row*Nc;
        #pragma unroll
        for (int j = 0; j < 8; j++) {
            int col = col0 + tx*8 + j;
            float v = acc[i][j];
            if (epi >= 2) v += bias[col];
            if (epi == 2) v = 0.5f*v*(1.0f + erff(v*0.70710678118654752f));
            if (epi == 3) v += dp[col];
            dp[col] = v;
        }
    }
}

// ---------------- top-20: bitonic sort of 64 u64 keys per lane + warp merge --
__global__ void __launch_bounds__(128) k_topk2(const float* __restrict__ dist) {
    __shared__ unsigned long long smk[4*32*20];
    int w = threadIdx.x >> 5, lane = threadIdx.x & 31;
    int bn = blockIdx.x*4 + w;
    const float* dp = dist + (size_t)bn*NN;
    unsigned long long a[64];
    #pragma unroll
    for (int i = 0; i < 64; i++) {
        int m = i*32 + lane;
        unsigned int u = __float_as_uint(dp[m]);
        u ^= ((unsigned int)((int)u >> 31)) | 0x80000000u;   // monotone map
        a[i] = ((unsigned long long)u << 32) | (unsigned int)(2047 - m);
    }
    #pragma unroll
    for (int k = 2; k <= 64; k <<= 1) {
        #pragma unroll
        for (int j = k >> 1; j > 0; j >>= 1) {
            #pragma unroll
            for (int i = 0; i < 64; i++) {
                int l = i ^ j;
                if (l > i) {
                    bool up = ((i & k) == 0);
                    unsigned long long x = a[i], y = a[l];
                    bool sw = up ? (x < y) : (x > y);
                    a[i] = sw ? y : x;
                    a[l] = sw ? x : y;
                }
            }
        }
    }
    unsigned long long* ms = &smk[(w*32 + lane)*20];
    #pragma unroll
    for (int j = 0; j < 20; j++) ms[j] = a[j];
    __syncwarp();
    int pos = 0;
    unsigned long long cur = a[0];
    #pragma unroll
    for (int j = 0; j < 20; j++) {
        unsigned long long mx = cur;
        #pragma unroll
        for (int off = 16; off; off >>= 1) {
            unsigned long long o = __shfl_xor_sync(0xffffffffu, mx, off);
            if (o > mx) mx = o;
        }
        if (lane == 0) g_idx[bn*KKN + j] = 2047 - (int)(mx & 0xffffffffu);
        if (cur == mx) { pos++; cur = (pos < 20) ? ms[pos] : 0ull; }
    }
}

// -------- EdgeConv: coalesced gather from row-major ft + conv + BN sums ------
template<int O>
__global__ void k_edgeconv(const float* __restrict__ ft, int Cld, int C,
                           const float* __restrict__ w) {
    __shared__ __align__(16) float ctr[128];
    __shared__ __align__(16) float nd[KKN*128];
    __shared__ int sidx[KKN];
    int bn = blockIdx.x;
    int b = bn >> 11;
    int t = threadIdx.x;
    if (t < KKN) sidx[t] = g_idx[bn*KKN + t];
    for (int e = t; e < C; e += O)
        ctr[e] = ft[(size_t)bn*Cld + e];
    __syncthreads();
    for (int e = t; e < KKN*C; e += O) {
        int kk = e / C, c = e - kk*C;
        nd[e] = ft[((size_t)(b*NN + sidx[kk]))*Cld + c] - ctr[c];
    }
    __syncthreads();

    int o = t;
    float acc[KKN];
    #pragma unroll
    for (int kk = 0; kk < KKN; kk++) acc[kk] = 0.f;
    float base = 0.f;
    const float* wr = w + (size_t)o*2*C;
    if ((C & 3) == 0) {
        for (int c = 0; c < C; c += 4) {
            float4 w1 = *(const float4*)&wr[c];
            float4 w2 = *(const float4*)&wr[C + c];
            float4 ct = *(const float4*)&ctr[c];
            base = fmaf(w2.x, ct.x, fmaf(w2.y, ct.y, fmaf(w2.z, ct.z, fmaf(w2.w, ct.w, base))));
            #pragma unroll
            for (int kk = 0; kk < KKN; kk++) {
                float4 nv = *(const float4*)&nd[kk*C + c];
                acc[kk] = fmaf(w1.x, nv.x, fmaf(w1.y, nv.y,
                          fmaf(w1.z, nv.z, fmaf(w1.w, nv.w, acc[kk]))));
            }
        }
    } else {
        for (int c = 0; c < C; c++) {
            float w1 = wr[c], w2 = wr[C + c], ct = ctr[c];
            base = fmaf(w2, ct, base);
            #pragma unroll
            for (int kk = 0; kk < KKN; kk++) acc[kk] = fmaf(w1, nd[kk*C + c], acc[kk]);
        }
    }
    double s = 0.0, ss = 0.0;
    float* yp = g_y + ((size_t)bn*KKN)*O + o;
    #pragma unroll
    for (int kk = 0; kk < KKN; kk++) {
        float v = acc[kk] + base;
        yp[(size_t)kk*O] = v;
        double vd = (double)v;
        s += vd; ss += vd*vd;
    }
    int bin = bn & (NBIN-1);
    atomicAdd(&g_sumd[o*NBIN + bin], s);
    atomicAdd(&g_ssqd[o*NBIN + bin], ss);
}

// ---------------- finalize BN stats ------------------------------------------
template<int O>
__global__ void k_finstats() {
    int o = threadIdx.x;
    if (o >= O) return;
    double s = 0.0, ss = 0.0;
    #pragma unroll 8
    for (int i = 0; i < NBIN; i++) { s += g_sumd[o*NBIN + i]; ss += g_ssqd[o*NBIN + i]; }
    const double cnt = (double)BB*NN*KKN;
    double mu = s / cnt;
    double var = ss / cnt - mu*mu;
    g_mu[o] = (float)mu;
    g_rs[o] = rsqrtf((float)var + EPSV);
}

// ---------------- BN normalize + leaky + max over k --------------------------
template<int O>
__global__ void k_bnmax(const float* __restrict__ g, const float* __restrict__ bb, int coff) {
    int id = blockIdx.x*256 + threadIdx.x;
    if (id >= BB*NN*O) return;
    int o = id % O, bn = id / O;
    float mu = g_mu[o], rs = g_rs[o];
    float gg = g[o], bv = bb[o];
    const float* yp = g_y + ((size_t)bn*KKN)*O + o;
    float mx = -INFINITY;
    #pragma unroll
    for (int kk = 0; kk < KKN; kk++) {
        float v = (yp[(size_t)kk*O] - mu)*rs*gg + bv;
        v = v >= 0.f ? v : 0.2f*v;
        mx = fmaxf(mx, v);
    }
    int b = bn >> 11, n = bn & 2047;
    g_H[((size_t)b*512 + coff + o)*NN + n] = mx;
}

// ---------------- conv5 BN stats (block per channel, double accum) -----------
__global__ void k_stats5() {
    int d = blockIdx.x, t = threadIdx.x;
    double s = 0.0, ss = 0.0;
    for (int b = 0; b < BB; b++) {
        const float* yp = g_y + ((size_t)(b*1024 + d))*NN;
        for (int n = t; n < NN; n += 256) {
            double v = (double)yp[n];
            s += v; ss += v*v;
        }
    }
    __shared__ double sred[8], ssred[8];
    for (int off = 16; off; off >>= 1) {
        s  += __shfl_xor_sync(0xffffffffu, s, off);
        ss += __shfl_xor_sync(0xffffffffu, ss, off);
    }
    if ((t & 31) == 0) { sred[t >> 5] = s; ssred[t >> 5] = ss; }
    __syncthreads();
    if (t == 0) {
        s = 0.0; ss = 0.0;
        for (int i = 0; i < 8; i++) { s += sred[i]; ss += ssred[i]; }
        double mu = s*(1.0/16384.0);
        double var = ss*(1.0/16384.0) - mu*mu;
        g_mu[d] = (float)mu;
        g_rs[d] = rsqrtf((float)var + EPSV);
    }
}

// ---------------- BN+leaky+patch max-pool + cls token ------------------------
__global__ void k_pool(const float* __restrict__ g5, const float* __restrict__ b5,
                       const float* __restrict__ cls) {
    int id = blockIdx.x*256 + threadIdx.x;
    if (id >= BB*DD*PP) return;
    int p = id % PP, d = (id / PP) % DD, b = id / (PP*DD);
    float mu = g_mu[d], r = g_rs[d], gg = g5[d], bv = b5[d];
    const float* yp = g_y + ((size_t)(b*1024 + d))*NN + p*PSZ;
    float mx = -INFINITY;
    #pragma unroll
    for (int s_ = 0; s_ < PSZ; s_++) {
        float v = (yp[s_] - mu)*r*gg + bv;
        v = v >= 0.f ? v : 0.2f*v;
        mx = fmaxf(mx, v);
    }
    g_t[((size_t)(b*TT + 1 + p))*DD + d] = mx;
    if (p == 0) g_t[((size_t)(b*TT))*DD + d] = cls[d];
}

// ---------------- two-pass LN (optional fused +pos residual into t) ----------
__global__ void k_ln(const float* __restrict__ pos, const float* __restrict__ g,
                     const float* __restrict__ b, float* __restrict__ out) {
    int row = blockIdx.x, t = threadIdx.x;
    float* xp = g_t + (size_t)row*DD;
    float v0 = xp[t], v1 = xp[t+256], v2 = xp[t+512], v3 = xp[t+768];
    if (pos) {
        const float* pp = pos + (size_t)row*DD;
        v0 += pp[t]; v1 += pp[t+256]; v2 += pp[t+512]; v3 += pp[t+768];
        xp[t] = v0; xp[t+256] = v1; xp[t+512] = v2; xp[t+768] = v3;
    }
    __shared__ float red[8];
    __shared__ float bc[2];
    float s = v0+v1+v2+v3;
    for (int off = 16; off; off >>= 1) s += __shfl_xor_sync(0xffffffffu, s, off);
    if ((t & 31) == 0) red[t >> 5] = s;
    __syncthreads();
    if (t == 0) {
        s = 0.f;
        for (int i = 0; i < 8; i++) s += red[i];
        bc[0] = s*(1.0f/1024.0f);
    }
    __syncthreads();
    float mu = bc[0];
    float d0 = v0-mu, d1 = v1-mu, d2 = v2-mu, d3 = v3-mu;
    float ss = d0*d0 + d1*d1 + d2*d2 + d3*d3;
    for (int off = 16; off; off >>= 1) ss += __shfl_xor_sync(0xffffffffu, ss, off);
    if ((t & 31) == 0) red[t >> 5] = ss;
    __syncthreads();
    if (t == 0) {
        ss = 0.f;
        for (int i = 0; i < 8; i++) ss += red[i];
        bc[1] = rsqrtf(ss*(1.0f/1024.0f) + EPSV);
    }
    __syncthreads();
    float r = bc[1];
    float* op = out + (size_t)row*DD;
    op[t]     = d0*r*g[t]     + b[t];
    op[t+256] = d1*r*g[t+256] + b[t+256];
    op[t+512] = d2*r*g[t+512] + b[t+512];
    op[t+768] = d3*r*g[t+768] + b[t+768];
}

// block per (b,h); dynamic smem q/k/v[65][64] + probs[65][66]
__global__ void k_attn(const float* __restrict__ qkv, float* __restrict__ z) {
    extern __shared__ float sm[];
    float* q = sm;
    float* k = q + TT*DHEAD;
    float* v = k + TT*DHEAD;
    float* s = v + TT*DHEAD;        // [65][66]
    int b = blockIdx.x >> 3, h = blockIdx.x & 7;
    int t = threadIdx.x;            // 128
    for (int e = t; e < TT*DHEAD; e += 128) {
        int tt = e >> 6, d = e & 63;
        size_t base = ((size_t)(b*TT + tt))*(3*INNER) + h*64 + d;
        q[e] = qkv[base]; k[e] = qkv[base + 512]; v[e] = qkv[base + 1024];
    }
    __syncthreads();
    for (int e = t; e < TT*TT; e += 128) {
        int i = e / TT, j = e - i*TT;
        float acc = 0.f;
        #pragma unroll
        for (int d = 0; d < 64; d++) acc = fmaf(q[i*64+d], k[j*64+d], acc);
        s[i*66 + j] = acc*0.125f;
    }
    __syncthreads();
    int w = t >> 5, lane = t & 31;
    for (int i = w; i < TT; i += 4) {
        float a0 = s[i*66 + lane], a1 = s[i*66 + 32 + lane];
        float a2 = (lane == 0) ? s[i*66 + 64] : -INFINITY;
        float mx = fmaxf(fmaxf(a0, a1), a2);
        for (int off = 16; off; off >>= 1) mx = fmaxf(mx, __shfl_xor_sync(0xffffffffu, mx, off));
        float e0 = expf(a0 - mx), e1 = expf(a1 - mx);
        float e2 = (lane == 0) ? expf(a2 - mx) : 0.f;
        float sum = e0 + e1 + e2;
        for (int off = 16; off; off >>= 1) sum += __shfl_xor_sync(0xffffffffu, sum, off);
        float inv = 1.0f / sum;
        s[i*66 + lane] = e0*inv; s[i*66 + 32 + lane] = e1*inv;
        if (lane == 0) s[i*66 + 64] = e2*inv;
    }
    __syncthreads();
    for (int e = t; e < TT*DHEAD; e += 128) {
        int i = e >> 6, d = e & 63;
        float acc = 0.f;
        for (int j = 0; j < TT; j++) acc = fmaf(s[i*66 + j], v[j*64 + d], acc);
        z[((size_t)(b*TT + i))*INNER + h*64 + d] = acc;
    }
}

__global__ void k_out(float* __restrict__ out) {
    int id = blockIdx.x*256 + threadIdx.x;
    if (id >= BB*PP*DD) return;
    int d = id % DD, p = (id / DD) % PP, b = id / (DD*PP);
    out[id] = g_t[((size_t)(b*TT + 1 + p))*DD + d];
}

// =============================================================================
extern "C" void kernel_launch(void* const* d_in, const int* in_sizes, int n_in,
                              void* d_out, int out_size) {
    const float* x    = (const float*)d_in[0];
    const float* pos  = (const float*)d_in[1];
    const float* w1   = (const float*)d_in[2];
    const float* g1   = (const float*)d_in[3];
    const float* b1   = (const float*)d_in[4];
    const float* w2   = (const float*)d_in[5];
    const float* g2   = (const float*)d_in[6];
    const float* b2   = (const float*)d_in[7];
    const float* w3   = (const float*)d_in[8];
    const float* g3   = (const float*)d_in[9];
    const float* b3   = (const float*)d_in[10];
    const float* w4   = (const float*)d_in[11];
    const float* g4   = (const float*)d_in[12];
    const float* b4   = (const float*)d_in[13];
    const float* w5   = (const float*)d_in[14];
    const float* g5   = (const float*)d_in[15];
    const float* b5   = (const float*)d_in[16];
    const float* cls  = (const float*)d_in[17];
    const float* ln1g = (const float*)d_in[18];
    const float* ln1b = (const float*)d_in[19];
    const float* wqkv = (const float*)d_in[20];
    const float* wout = (const float*)d_in[21];
    const float* bout = (const float*)d_in[22];
    const float* ln2g = (const float*)d_in[23];
    const float* ln2b = (const float*)d_in[24];
    const float* wff1 = (const float*)d_in[25];
    const float* bff1 = (const float*)d_in[26];
    const float* wff2 = (const float*)d_in[27];
    const float* bff2 = (const float*)d_in[28];

    void* p;
    float *h0P, *HP, *xxP, *yP, *ftP, *fbP, *tP, *hnP, *qkvP, *zP, *ffP;
    double *sumdP, *ssqdP;
    cudaGetSymbolAddress(&p, g_h0);    h0P   = (float*)p;
    cudaGetSymbolAddress(&p, g_H);     HP    = (float*)p;
    cudaGetSymbolAddress(&p, g_xx);    xxP   = (float*)p;
    cudaGetSymbolAddress(&p, g_y);     yP    = (float*)p;
    cudaGetSymbolAddress(&p, g_ft);    ftP   = (float*)p;
    cudaGetSymbolAddress(&p, g_fpadB); fbP   = (float*)p;
    cudaGetSymbolAddress(&p, g_sumd);  sumdP = (double*)p;
    cudaGetSymbolAddress(&p, g_ssqd);  ssqdP = (double*)p;
    cudaGetSymbolAddress(&p, g_t);     tP    = (float*)p;
    cudaGetSymbolAddress(&p, g_hn);    hnP   = (float*)p;
    cudaGetSymbolAddress(&p, g_qkv);   qkvP  = (float*)p;
    cudaGetSymbolAddress(&p, g_z);     zP    = (float*)p;
    cudaGetSymbolAddress(&p, g_ff);    ffP   = (float*)p;

    int attn_smem = (3*TT*DHEAD + TT*66) * sizeof(float);
    cudaFuncSetAttribute(k_attn, cudaFuncAttributeMaxDynamicSharedMemorySize, attn_smem);

    k_transpose_x<<<(BB*NN + 255)/256, 256>>>(x);

    dim3 gDist64(NN/64, NN/64, BB);
    dim3 gDist128(NN/128, NN/128, BB);

    // ---- EdgeConv 1: C=3 -> O=64 ----
    k_xx<<<(BB*NN + 255)/256, 256>>>(h0P, 3, 0, 3);
    k_gemm<<<gDist64, 256>>>(ftP, fbP, nullptr, xxP, yP,
        NN, NN, 16, (long)NN*16, (long)16*NN, (long)NN*NN, 4);
    k_topk2<<<BB*NN/4, 128>>>(yP);
    cudaMemsetAsync(sumdP, 0, 256*NBIN*sizeof(double));
    cudaMemsetAsync(ssqdP, 0, 256*NBIN*sizeof(double));
    k_edgeconv<64><<<BB*NN, 64>>>(ftP, 16, 3, w1);
    k_finstats<64><<<1, 64>>>();
    k_bnmax<64><<<(BB*NN*64 + 255)/256, 256>>>(g1, b1, 0);

    // ---- EdgeConv 2: x1 (coff 0, C=64) -> O=64 ----
    k_xx<<<(BB*NN + 255)/256, 256>>>(HP, 512, 0, 64);
    k_featT<<<(BB*NN*64 + 255)/256, 256>>>(HP, 512, 0, 64, 64, ftP);
    k_gemm128<<<gDist128, 256>>>(ftP, HP, xxP, yP,
        NN, NN, 64, (long)NN*64, (long)512*NN, (long)NN*NN, 64, NN, 4, 1);
    k_topk2<<<BB*NN/4, 128>>>(yP);
    cudaMemsetAsync(sumdP, 0, 256*NBIN*sizeof(double));
    cudaMemsetAsync(ssqdP, 0, 256*NBIN*sizeof(double));
    k_edgeconv<64><<<BB*NN, 64>>>(ftP, 64, 64, w2);
    k_finstats<64><<<1, 64>>>();
    k_bnmax<64><<<(BB*NN*64 + 255)/256, 256>>>(g2, b2, 64);

    // ---- EdgeConv 3: x2 (coff 64, C=64) -> O=128 ----
    k_xx<<<(BB*NN + 255)/256, 256>>>(HP, 512, 64, 64);
    k_featT<<<(BB*NN*64 + 255)/256, 256>>>(HP, 512, 64, 64, 64, ftP);
    k_gemm128<<<gDist128, 256>>>(ftP, HP + (size_t)64*NN, xxP, yP,
        NN, NN, 64, (long)NN*64, (long)512*NN, (long)NN*NN, 64, NN, 4, 1);
    k_topk2<<<BB*NN/4, 128>>>(yP);
    cudaMemsetAsync(sumdP, 0, 256*NBIN*sizeof(double));
    cudaMemsetAsync(ssqdP, 0, 256*NBIN*sizeof(double));
    k_edgeconv<128><<<BB*NN, 128>>>(ftP, 64, 64, w3);
    k_finstats<128><<<1, 128>>>();
    k_bnmax<128><<<(BB*NN*128 + 255)/256, 256>>>(g3, b3, 128);

    // ---- EdgeConv 4: x3 (coff 128, C=128) -> O=256 ----
    k_xx<<<(BB*NN + 255)/256, 256>>>(HP, 512, 128, 128);
    k_featT<<<(BB*NN*128 + 255)/256, 256>>>(HP, 512, 128, 128, 128, ftP);
    k_gemm128<<<gDist128, 256>>>(ftP, HP + (size_t)128*NN, xxP, yP,
        NN, NN, 128, (long)NN*128, (long)512*NN, (long)NN*NN, 128, NN, 4, 1);
    k_topk2<<<BB*NN/4, 128>>>(yP);
    cudaMemsetAsync(sumdP, 0, 256*NBIN*sizeof(double));
    cudaMemsetAsync(ssqdP, 0, 256*NBIN*sizeof(double));
    k_edgeconv<256><<<BB*NN, 256>>>(ftP, 128, 128, w4);
    k_finstats<256><<<1, 256>>>();
    k_bnmax<256><<<(BB*NN*256 + 255)/256, 256>>>(g4, b4, 256);

    // ---- conv5: y[b] = w5[1024,512] @ H[b][512,2048] ----
    k_gemm128<<<dim3(NN/128, 1024/128, BB), 256>>>(
        w5, HP, nullptr, yP, 1024, NN, 512,
        0L, (long)512*NN, (long)1024*NN, 512, NN, 0, 0);
    k_stats5<<<1024, 256>>>();
    k_pool<<<(BB*DD*PP + 255)/256, 256>>>(g5, b5, cls);

    // ---- transformer ----
    for (int i = 0; i < DEPTH; i++) {
        k_ln<<<TOK, 256>>>(pos, ln1g + (size_t)i*DD, ln1b + (size_t)i*DD, hnP);
        k_gemmT<<<dim3((3*INNER)/128, (TOK + 63)/64), 256>>>(
            hnP, wqkv + (size_t)i*DD*3*INNER, nullptr, qkvP, TOK, 3*INNER, DD, 0);
        k_attn<<<BB*NHEAD, 128, attn_smem>>>(qkvP, zP);
        k_gemmT<<<dim3(DD/128, (TOK + 63)/64), 256>>>(
            zP, wout + (size_t)i*INNER*DD, bout + (size_t)i*DD, tP, TOK, DD, INNER, 3);
        k_ln<<<TOK, 256>>>(nullptr, ln2g + (size_t)i*DD, ln2b + (size_t)i*DD, hnP);
        k_gemmT<<<dim3(MLPD/128, (TOK + 63)/64), 256>>>(
            hnP, wff1 + (size_t)i*DD*MLPD, bff1 + (size_t)i*MLPD, ffP, TOK, MLPD, DD, 2);
        k_gemmT<<<dim3(DD/128, (TOK + 63)/64), 256>>>(
            ffP, wff2 + (size_t)i*MLPD*DD, bff2 + (size_t)i*DD, tP, TOK, DD, MLPD, 3);
    }

    k_out<<<(BB*PP*DD + 255)/256, 256>>>((float*)d_out);
}

// round 11
// speedup vs baseline: 1.1902x; 1.1902x over previous
#include <cuda_runtime.h>
#include <math.h>

#define BB    8
#define NN    2048
#define KKN   20
#define PP    64
#define PSZ   32
#define DD    1024
#define TT    65
#define TOK   (BB*TT)     // 520
#define INNER 512
#define NHEAD 8
#define DHEAD 64
#define MLPD  2048
#define DEPTH 6
#define EPSV  1e-5f
#define NBIN  64

// ---------------- scratch (static device globals; no runtime allocation) ----
__device__ float  g_h0 [BB*3*NN];                     // transposed xyz [B,3,N]
__device__ float  g_H  [BB*512*NN];                   // concat features [B,512,N]
__device__ float  g_xx[BB*NN];
__device__ int    g_idx[BB*NN*KKN];
__device__ float  g_y [(size_t)BB*NN*KKN*256];        // 335MB scratch: dist matrix, then conv y
__device__ float  g_ft [BB*NN*128];                   // row-major features [B*N][Cld]
__device__ float  g_fpadB[BB*16*NN];                  // zero-padded xyz [B,16,N]
__device__ double g_sumd[256*NBIN];
__device__ double g_ssqd[256*NBIN];
__device__ float  g_mu [1024];
__device__ float  g_rs [1024];
__device__ float  g_t  [TOK*DD];
__device__ float  g_hn [TOK*DD];
__device__ float  g_qkv[TOK*3*INNER];
__device__ float  g_z  [TOK*INNER];
__device__ float  g_ff [TOK*MLPD];

// ------- stage 0: transpose x + build padded B operand + conv1 ft rows -------
__global__ void k_transpose_x(const float* __restrict__ x) {
    int id = blockIdx.x*256 + threadIdx.x;
    if (id >= BB*NN) return;
    int b = id / NN, n = id % NN;
    float v[3];
    #pragma unroll
    for (int c = 0; c < 3; c++) {
        v[c] = x[id*3 + c];
        g_h0[(b*3+c)*NN + n] = v[c];
        g_fpadB[(b*16+c)*NN + n] = v[c];
    }
    #pragma unroll
    for (int c = 3; c < 16; c++) g_fpadB[(b*16+c)*NN + n] = 0.f;
    #pragma unroll
    for (int c = 0; c < 16; c++) g_ft[(size_t)id*16 + c] = (c < 3) ? v[c] : 0.f;
}

// ---------------- xx = sum_c x^2 ---------------------------------------------
__global__ void k_xx(const float* __restrict__ src, int Ctot, int coff, int C) {
    int id = blockIdx.x*256 + threadIdx.x;
    if (id >= BB*NN) return;
    int b = id / NN, m = id % NN;
    float s = 0.f;
    for (int c = 0; c < C; c++) {
        float v = src[((size_t)b*Ctot + coff + c)*NN + m];
        s = fmaf(v, v, s);
    }
    g_xx[id] = s;
}

// ---------------- build row-major feature copy [B*N][Kpad] -------------------
__global__ void k_featT(const float* __restrict__ src, int Ctot, int coff, int C,
                        int Kpad, float* __restrict__ out) {
    int id = blockIdx.x*256 + threadIdx.x;
    if (id >= BB*NN*Kpad) return;
    int c = id % Kpad; int rem = id / Kpad;
    int n = rem % NN, b = rem / NN;
    out[id] = (c < C) ? src[((size_t)b*Ctot + coff + c)*NN + n] : 0.f;
}

// ---------------- generic tiled fp32 GEMM (64x64) ----------------------------
// epi: 0 plain, 1 +bias, 2 gelu(x+bias), 3 x+bias+dst residual, 4 dist
__global__ void k_gemm(const float* __restrict__ A, const float* __restrict__ Bm,
                       const float* __restrict__ bias, const float* __restrict__ xx,
                       float* dst,
                       int M, int Nc, int Kc, long sA, long sB, long sC, int epi) {
    __shared__ __align__(16) float As[16][64];
    __shared__ __align__(16) float Bs[16][64];
    int tid = threadIdx.x;
    int tx = tid & 15, ty = tid >> 4;
    int row0 = blockIdx.y*64, col0 = blockIdx.x*64;
    const float* Ap = A + (size_t)blockIdx.z*sA;
    const float* Bp = Bm + (size_t)blockIdx.z*sB;
    float acc[4][4] = {};
    int r = tid >> 2, kq = tid & 3;
    for (int kt = 0; kt < Kc; kt += 16) {
        float4 a4 = make_float4(0.f, 0.f, 0.f, 0.f);
        int row = row0 + r;
        if (row < M) a4 = *(const float4*)&Ap[(size_t)row*Kc + kt + kq*4];
        As[kq*4+0][r] = a4.x; As[kq*4+1][r] = a4.y;
        As[kq*4+2][r] = a4.z; As[kq*4+3][r] = a4.w;
        #pragma unroll
        for (int i = 0; i < 4; i++) {
            int kr = (tid >> 6) + i*4;
            Bs[kr][tid & 63] = Bp[(size_t)(kt + kr)*Nc + col0 + (tid & 63)];
        }
        __syncthreads();
        #pragma unroll
        for (int kk = 0; kk < 16; kk++) {
            float4 a = *(const float4*)&As[kk][ty*4];
            float4 bq = *(const float4*)&Bs[kk][tx*4];
            acc[0][0] = fmaf(a.x, bq.x, acc[0][0]); acc[0][1] = fmaf(a.x, bq.y, acc[0][1]);
            acc[0][2] = fmaf(a.x, bq.z, acc[0][2]); acc[0][3] = fmaf(a.x, bq.w, acc[0][3]);
            acc[1][0] = fmaf(a.y, bq.x, acc[1][0]); acc[1][1] = fmaf(a.y, bq.y, acc[1][1]);
            acc[1][2] = fmaf(a.y, bq.z, acc[1][2]); acc[1][3] = fmaf(a.y, bq.w, acc[1][3]);
            acc[2][0] = fmaf(a.z, bq.x, acc[2][0]); acc[2][1] = fmaf(a.z, bq.y, acc[2][1]);
            acc[2][2] = fmaf(a.z, bq.z, acc[2][2]); acc[2][3] = fmaf(a.z, bq.w, acc[2][3]);
            acc[3][0] = fmaf(a.w, bq.x, acc[3][0]); acc[3][1] = fmaf(a.w, bq.y, acc[3][1]);
            acc[3][2] = fmaf(a.w, bq.z, acc[3][2]); acc[3][3] = fmaf(a.w, bq.w, acc[3][3]);
        }
        __syncthreads();
    }
    float* Dp = dst + (size_t)blockIdx.z*sC;
    const float* xxz = (epi == 4) ? (xx + (size_t)blockIdx.z*Nc) : nullptr;
    #pragma unroll
    for (int i = 0; i < 4; i++) {
        int row = row0 + ty*4 + i;
        if (row >= M) continue;
        #pragma unroll
        for (int j = 0; j < 4; j++) {
            int col = col0 + tx*4 + j;
            float v = acc[i][j];
            if (epi == 1 || epi == 2 || epi == 3) v += bias[col];
            if (epi == 2) v = 0.5f*v*(1.0f + erff(v*0.70710678118654752f));
            if (epi == 3) v += Dp[(size_t)row*Nc + col];
            if (epi == 4) v = 2.0f*v - xxz[row] - xxz[col];
            Dp[(size_t)row*Nc + col] = v;
        }
    }
}

// ---------------- 128x128-tile fp32 GEMM (8x8/thread), optional symmetry -----
__global__ void __launch_bounds__(256) k_gemm128(
        const float* __restrict__ A, const float* __restrict__ Bm,
        const float* __restrict__ xx, float* __restrict__ dst,
        int M, int Nc, int Kc,
        long sA, long sB, long sC, int lda, int ldb, int epi, int sym) {
    int bx = blockIdx.x, by = blockIdx.y;
    if (sym && bx < by) return;
    __shared__ __align__(16) float As[16][128];
    __shared__ __align__(16) float Bs[16][128];
    int tid = threadIdx.x;
    int tx = tid & 15, ty = tid >> 4;
    int row0 = by*128, col0 = bx*128;
    const float* Ap = A + (size_t)blockIdx.z*sA;
    const float* Bp = Bm + (size_t)blockIdx.z*sB;
    float acc[8][8] = {};
    int ar = tid >> 1, ak = (tid & 1)*8;
    int bkr = tid >> 4, bc4 = (tid & 15)*8;
    for (int kt = 0; kt < Kc; kt += 16) {
        float4 a0 = make_float4(0.f,0.f,0.f,0.f), a1 = a0;
        int arow = row0 + ar;
        if (arow < M) {
            a0 = *(const float4*)&Ap[(size_t)arow*lda + kt + ak];
            a1 = *(const float4*)&Ap[(size_t)arow*lda + kt + ak + 4];
        }
        As[ak+0][ar] = a0.x; As[ak+1][ar] = a0.y; As[ak+2][ar] = a0.z; As[ak+3][ar] = a0.w;
        As[ak+4][ar] = a1.x; As[ak+5][ar] = a1.y; As[ak+6][ar] = a1.z; As[ak+7][ar] = a1.w;
        *(float4*)&Bs[bkr][bc4]   = *(const float4*)&Bp[(size_t)(kt+bkr)*ldb + col0 + bc4];
        *(float4*)&Bs[bkr][bc4+4] = *(const float4*)&Bp[(size_t)(kt+bkr)*ldb + col0 + bc4 + 4];
        __syncthreads();
        #pragma unroll
        for (int kk = 0; kk < 16; kk++) {
            float av[8], bv[8];
            *(float4*)&av[0] = *(const float4*)&As[kk][ty*8];
            *(float4*)&av[4] = *(const float4*)&As[kk][ty*8+4];
            *(float4*)&bv[0] = *(const float4*)&Bs[kk][tx*8];
            *(float4*)&bv[4] = *(const float4*)&Bs[kk][tx*8+4];
            #pragma unroll
            for (int i = 0; i < 8; i++)
                #pragma unroll
                for (int j = 0; j < 8; j++)
                    acc[i][j] = fmaf(av[i], bv[j], acc[i][j]);
        }
        __syncthreads();
    }
    float* Dp = dst + (size_t)blockIdx.z*sC;
    if (epi == 4) {
        const float* xxz = xx + (size_t)blockIdx.z*Nc;
        float xr[8], xc[8];
        #pragma unroll
        for (int i = 0; i < 8; i++) xr[i] = xxz[row0 + ty*8 + i];
        #pragma unroll
        for (int j = 0; j < 8; j++) xc[j] = xxz[col0 + tx*8 + j];
        #pragma unroll
        for (int i = 0; i < 8; i++) {
            int row = row0 + ty*8 + i;
            float v[8];
            #pragma unroll
            for (int j = 0; j < 8; j++) v[j] = 2.0f*acc[i][j] - xr[i] - xc[j];
            *(float4*)&Dp[(size_t)row*Nc + col0 + tx*8]     = *(float4*)&v[0];
            *(float4*)&Dp[(size_t)row*Nc + col0 + tx*8 + 4] = *(float4*)&v[4];
        }
        if (sym && bx != by) {
            #pragma unroll
            for (int j = 0; j < 8; j++) {
                int col = col0 + tx*8 + j;
                float tv[8];
                #pragma unroll
                for (int i = 0; i < 8; i++) tv[i] = 2.0f*acc[i][j] - xr[i] - xc[j];
                *(float4*)&Dp[(size_t)col*Nc + row0 + ty*8]     = *(float4*)&tv[0];
                *(float4*)&Dp[(size_t)col*Nc + row0 + ty*8 + 4] = *(float4*)&tv[4];
            }
        }
    } else {
        #pragma unroll
        for (int i = 0; i < 8; i++) {
            int row = row0 + ty*8 + i;
            if (row >= M) continue;
            *(float4*)&Dp[(size_t)row*Nc + col0 + tx*8]     = *(float4*)&acc[i][0];
            *(float4*)&Dp[(size_t)row*Nc + col0 + tx*8 + 4] = *(float4*)&acc[i][4];
        }
    }
}

// ---------------- top-20: bitonic sort of 64 u64 keys per lane + warp merge --
__global__ void __launch_bounds__(128) k_topk2(const float* __restrict__ dist) {
    __shared__ unsigned long long smk[4*32*20];
    int w = threadIdx.x >> 5, lane = threadIdx.x & 31;
    int bn = blockIdx.x*4 + w;
    const float* dp = dist + (size_t)bn*NN;
    unsigned long long a[64];
    #pragma unroll
    for (int i = 0; i < 64; i++) {
        int m = i*32 + lane;
        unsigned int u = __float_as_uint(dp[m]);
        u ^= ((unsigned int)((int)u >> 31)) | 0x80000000u;   // monotone map
        a[i] = ((unsigned long long)u << 32) | (unsigned int)(2047 - m);
    }
    #pragma unroll
    for (int k = 2; k <= 64; k <<= 1) {
        #pragma unroll
        for (int j = k >> 1; j > 0; j >>= 1) {
            #pragma unroll
            for (int i = 0; i < 64; i++) {
                int l = i ^ j;
                if (l > i) {
                    bool up = ((i & k) == 0);
                    unsigned long long x = a[i], y = a[l];
                    bool sw = up ? (x < y) : (x > y);
                    a[i] = sw ? y : x;
                    a[l] = sw ? x : y;
                }
            }
        }
    }
    unsigned long long* ms = &smk[(w*32 + lane)*20];
    #pragma unroll
    for (int j = 0; j < 20; j++) ms[j] = a[j];
    __syncwarp();
    int pos = 0;
    unsigned long long cur = a[0];
    #pragma unroll
    for (int j = 0; j < 20; j++) {
        unsigned long long mx = cur;
        #pragma unroll
        for (int off = 16; off; off >>= 1) {
            unsigned long long o = __shfl_xor_sync(0xffffffffu, mx, off);
            if (o > mx) mx = o;
        }
        if (lane == 0) g_idx[bn*KKN + j] = 2047 - (int)(mx & 0xffffffffu);
        if (cur == mx) { pos++; cur = (pos < 20) ? ms[pos] : 0ull; }
    }
}

// -------- EdgeConv: coalesced gather from row-major ft + conv + BN sums ------
template<int O>
__global__ void k_edgeconv(const float* __restrict__ ft, int Cld, int C,
                           const float* __restrict__ w) {
    __shared__ __align__(16) float ctr[128];
    __shared__ __align__(16) float nd[KKN*128];
    __shared__ int sidx[KKN];
    int bn = blockIdx.x;
    int b = bn >> 11;
    int t = threadIdx.x;
    if (t < KKN) sidx[t] = g_idx[bn*KKN + t];
    for (int e = t; e < C; e += O)
        ctr[e] = ft[(size_t)bn*Cld + e];
    __syncthreads();
    for (int e = t; e < KKN*C; e += O) {
        int kk = e / C, c = e - kk*C;
        nd[e] = ft[((size_t)(b*NN + sidx[kk]))*Cld + c] - ctr[c];
    }
    __syncthreads();

    int o = t;
    float acc[KKN];
    #pragma unroll
    for (int kk = 0; kk < KKN; kk++) acc[kk] = 0.f;
    float base = 0.f;
    const float* wr = w + (size_t)o*2*C;
    if ((C & 3) == 0) {
        for (int c = 0; c < C; c += 4) {
            float4 w1 = *(const float4*)&wr[c];
            float4 w2 = *(const float4*)&wr[C + c];
            float4 ct = *(const float4*)&ctr[c];
            base = fmaf(w2.x, ct.x, fmaf(w2.y, ct.y, fmaf(w2.z, ct.z, fmaf(w2.w, ct.w, base))));
            #pragma unroll
            for (int kk = 0; kk < KKN; kk++) {
                float4 nv = *(const float4*)&nd[kk*C + c];
                acc[kk] = fmaf(w1.x, nv.x, fmaf(w1.y, nv.y,
                          fmaf(w1.z, nv.z, fmaf(w1.w, nv.w, acc[kk]))));
            }
        }
    } else {
        for (int c = 0; c < C; c++) {
            float w1 = wr[c], w2 = wr[C + c], ct = ctr[c];
            base = fmaf(w2, ct, base);
            #pragma unroll
            for (int kk = 0; kk < KKN; kk++) acc[kk] = fmaf(w1, nd[kk*C + c], acc[kk]);
        }
    }
    double s = 0.0, ss = 0.0;
    float* yp = g_y + ((size_t)bn*KKN)*O + o;
    #pragma unroll
    for (int kk = 0; kk < KKN; kk++) {
        float v = acc[kk] + base;
        yp[(size_t)kk*O] = v;
        double vd = (double)v;
        s += vd; ss += vd*vd;
    }
    int bin = bn & (NBIN-1);
    atomicAdd(&g_sumd[o*NBIN + bin], s);
    atomicAdd(&g_ssqd[o*NBIN + bin], ss);
}

// ---------------- finalize BN stats ------------------------------------------
template<int O>
__global__ void k_finstats() {
    int o = threadIdx.x;
    if (o >= O) return;
    double s = 0.0, ss = 0.0;
    #pragma unroll 8
    for (int i = 0; i < NBIN; i++) { s += g_sumd[o*NBIN + i]; ss += g_ssqd[o*NBIN + i]; }
    const double cnt = (double)BB*NN*KKN;
    double mu = s / cnt;
    double var = ss / cnt - mu*mu;
    g_mu[o] = (float)mu;
    g_rs[o] = rsqrtf((float)var + EPSV);
}

// ---------------- BN normalize + leaky + max over k --------------------------
template<int O>
__global__ void k_bnmax(const float* __restrict__ g, const float* __restrict__ bb, int coff) {
    int id = blockIdx.x*256 + threadIdx.x;
    if (id >= BB*NN*O) return;
    int o = id % O, bn = id / O;
    float mu = g_mu[o], rs = g_rs[o];
    float gg = g[o], bv = bb[o];
    const float* yp = g_y + ((size_t)bn*KKN)*O + o;
    float mx = -INFINITY;
    #pragma unroll
    for (int kk = 0; kk < KKN; kk++) {
        float v = (yp[(size_t)kk*O] - mu)*rs*gg + bv;
        v = v >= 0.f ? v : 0.2f*v;
        mx = fmaxf(mx, v);
    }
    int b = bn >> 11, n = bn & 2047;
    g_H[((size_t)b*512 + coff + o)*NN + n] = mx;
}

// ---------------- conv5 BN stats (block per channel, double accum) -----------
__global__ void k_stats5() {
    int d = blockIdx.x, t = threadIdx.x;
    double s = 0.0, ss = 0.0;
    for (int b = 0; b < BB; b++) {
        const float* yp = g_y + ((size_t)(b*1024 + d))*NN;
        for (int n = t; n < NN; n += 256) {
            double v = (double)yp[n];
            s += v; ss += v*v;
        }
    }
    __shared__ double sred[8], ssred[8];
    for (int off = 16; off; off >>= 1) {
        s  += __shfl_xor_sync(0xffffffffu, s, off);
        ss += __shfl_xor_sync(0xffffffffu, ss, off);
    }
    if ((t & 31) == 0) { sred[t >> 5] = s; ssred[t >> 5] = ss; }
    __syncthreads();
    if (t == 0) {
        s = 0.0; ss = 0.0;
        for (int i = 0; i < 8; i++) { s += sred[i]; ss += ssred[i]; }
        double mu = s*(1.0/16384.0);
        double var = ss*(1.0/16384.0) - mu*mu;
        g_mu[d] = (float)mu;
        g_rs[d] = rsqrtf((float)var + EPSV);
    }
}

// ---------------- BN+leaky+patch max-pool + cls token ------------------------
__global__ void k_pool(const float* __restrict__ g5, const float* __restrict__ b5,
                       const float* __restrict__ cls) {
    int id = blockIdx.x*256 + threadIdx.x;
    if (id >= BB*DD*PP) return;
    int p = id % PP, d = (id / PP) % DD, b = id / (PP*DD);
    float mu = g_mu[d], r = g_rs[d], gg = g5[d], bv = b5[d];
    const float* yp = g_y + ((size_t)(b*1024 + d))*NN + p*PSZ;
    float mx = -INFINITY;
    #pragma unroll
    for (int s_ = 0; s_ < PSZ; s_++) {
        float v = (yp[s_] - mu)*r*gg + bv;
        v = v >= 0.f ? v : 0.2f*v;
        mx = fmaxf(mx, v);
    }
    g_t[((size_t)(b*TT + 1 + p))*DD + d] = mx;
    if (p == 0) g_t[((size_t)(b*TT))*DD + d] = cls[d];
}

// ---------------- two-pass LN (optional fused +pos residual into t) ----------
__global__ void k_ln(const float* __restrict__ pos, const float* __restrict__ g,
                     const float* __restrict__ b, float* __restrict__ out) {
    int row = blockIdx.x, t = threadIdx.x;
    float* xp = g_t + (size_t)row*DD;
    float v0 = xp[t], v1 = xp[t+256], v2 = xp[t+512], v3 = xp[t+768];
    if (pos) {
        const float* pp = pos + (size_t)row*DD;
        v0 += pp[t]; v1 += pp[t+256]; v2 += pp[t+512]; v3 += pp[t+768];
        xp[t] = v0; xp[t+256] = v1; xp[t+512] = v2; xp[t+768] = v3;
    }
    __shared__ float red[8];
    __shared__ float bc[2];
    float s = v0+v1+v2+v3;
    for (int off = 16; off; off >>= 1) s += __shfl_xor_sync(0xffffffffu, s, off);
    if ((t & 31) == 0) red[t >> 5] = s;
    __syncthreads();
    if (t == 0) {
        s = 0.f;
        for (int i = 0; i < 8; i++) s += red[i];
        bc[0] = s*(1.0f/1024.0f);
    }
    __syncthreads();
    float mu = bc[0];
    float d0 = v0-mu, d1 = v1-mu, d2 = v2-mu, d3 = v3-mu;
    float ss = d0*d0 + d1*d1 + d2*d2 + d3*d3;
    for (int off = 16; off; off >>= 1) ss += __shfl_xor_sync(0xffffffffu, ss, off);
    if ((t & 31) == 0) red[t >> 5] = ss;
    __syncthreads();
    if (t == 0) {
        ss = 0.f;
        for (int i = 0; i < 8; i++) ss += red[i];
        bc[1] = rsqrtf(ss*(1.0f/1024.0f) + EPSV);
    }
    __syncthreads();
    float r = bc[1];
    float* op = out + (size_t)row*DD;
    op[t]     = d0*r*g[t]     + b[t];
    op[t+256] = d1*r*g[t+256] + b[t+256];
    op[t+512] = d2*r*g[t+512] + b[t+512];
    op[t+768] = d3*r*g[t+768] + b[t+768];
}

// block per (b,h); dynamic smem q/k/v[65][64] + probs[65][66]
__global__ void k_attn(const float* __restrict__ qkv, float* __restrict__ z) {
    extern __shared__ float sm[];
    float* q = sm;
    float* k = q + TT*DHEAD;
    float* v = k + TT*DHEAD;
    float* s = v + TT*DHEAD;        // [65][66]
    int b = blockIdx.x >> 3, h = blockIdx.x & 7;
    int t = threadIdx.x;            // 128
    for (int e = t; e < TT*DHEAD; e += 128) {
        int tt = e >> 6, d = e & 63;
        size_t base = ((size_t)(b*TT + tt))*(3*INNER) + h*64 + d;
        q[e] = qkv[base]; k[e] = qkv[base + 512]; v[e] = qkv[base + 1024];
    }
    __syncthreads();
    for (int e = t; e < TT*TT; e += 128) {
        int i = e / TT, j = e - i*TT;
        float acc = 0.f;
        #pragma unroll
        for (int d = 0; d < 64; d++) acc = fmaf(q[i*64+d], k[j*64+d], acc);
        s[i*66 + j] = acc*0.125f;
    }
    __syncthreads();
    int w = t >> 5, lane = t & 31;
    for (int i = w; i < TT; i += 4) {
        float a0 = s[i*66 + lane], a1 = s[i*66 + 32 + lane];
        float a2 = (lane == 0) ? s[i*66 + 64] : -INFINITY;
        float mx = fmaxf(fmaxf(a0, a1), a2);
        for (int off = 16; off; off >>= 1) mx = fmaxf(mx, __shfl_xor_sync(0xffffffffu, mx, off));
        float e0 = expf(a0 - mx), e1 = expf(a1 - mx);
        float e2 = (lane == 0) ? expf(a2 - mx) : 0.f;
        float sum = e0 + e1 + e2;
        for (int off = 16; off; off >>= 1) sum += __shfl_xor_sync(0xffffffffu, sum, off);
        float inv = 1.0f / sum;
        s[i*66 + lane] = e0*inv; s[i*66 + 32 + lane] = e1*inv;
        if (lane == 0) s[i*66 + 64] = e2*inv;
    }
    __syncthreads();
    for (int e = t; e < TT*DHEAD; e += 128) {
        int i = e >> 6, d = e & 63;
        float acc = 0.f;
        for (int j = 0; j < TT; j++) acc = fmaf(s[i*66 + j], v[j*64 + d], acc);
        z[((size_t)(b*TT + i))*INNER + h*64 + d] = acc;
    }
}

__global__ void k_out(float* __restrict__ out) {
    int id = blockIdx.x*256 + threadIdx.x;
    if (id >= BB*PP*DD) return;
    int d = id % DD, p = (id / DD) % PP, b = id / (DD*PP);
    out[id] = g_t[((size_t)(b*TT + 1 + p))*DD + d];
}

// =============================================================================
extern "C" void kernel_launch(void* const* d_in, const int* in_sizes, int n_in,
                              void* d_out, int out_size) {
    const float* x    = (const float*)d_in[0];
    const float* pos  = (const float*)d_in[1];
    const float* w1   = (const float*)d_in[2];
    const float* g1   = (const float*)d_in[3];
    const float* b1   = (const float*)d_in[4];
    const float* w2   = (const float*)d_in[5];
    const float* g2   = (const float*)d_in[6];
    const float* b2   = (const float*)d_in[7];
    const float* w3   = (const float*)d_in[8];
    const float* g3   = (const float*)d_in[9];
    const float* b3   = (const float*)d_in[10];
    const float* w4   = (const float*)d_in[11];
    const float* g4   = (const float*)d_in[12];
    const float* b4   = (const float*)d_in[13];
    const float* w5   = (const float*)d_in[14];
    const float* g5   = (const float*)d_in[15];
    const float* b5   = (const float*)d_in[16];
    const float* cls  = (const float*)d_in[17];
    const float* ln1g = (const float*)d_in[18];
    const float* ln1b = (const float*)d_in[19];
    const float* wqkv = (const float*)d_in[20];
    const float* wout = (const float*)d_in[21];
    const float* bout = (const float*)d_in[22];
    const float* ln2g = (const float*)d_in[23];
    const float* ln2b = (const float*)d_in[24];
    const float* wff1 = (const float*)d_in[25];
    const float* bff1 = (const float*)d_in[26];
    const float* wff2 = (const float*)d_in[27];
    const float* bff2 = (const float*)d_in[28];

    void* p;
    float *h0P, *HP, *xxP, *yP, *ftP, *fbP, *tP, *hnP, *qkvP, *zP, *ffP;
    double *sumdP, *ssqdP;
    cudaGetSymbolAddress(&p, g_h0);    h0P   = (float*)p;
    cudaGetSymbolAddress(&p, g_H);     HP    = (float*)p;
    cudaGetSymbolAddress(&p, g_xx);    xxP   = (float*)p;
    cudaGetSymbolAddress(&p, g_y);     yP    = (float*)p;
    cudaGetSymbolAddress(&p, g_ft);    ftP   = (float*)p;
    cudaGetSymbolAddress(&p, g_fpadB); fbP   = (float*)p;
    cudaGetSymbolAddress(&p, g_sumd);  sumdP = (double*)p;
    cudaGetSymbolAddress(&p, g_ssqd);  ssqdP = (double*)p;
    cudaGetSymbolAddress(&p, g_t);     tP    = (float*)p;
    cudaGetSymbolAddress(&p, g_hn);    hnP   = (float*)p;
    cudaGetSymbolAddress(&p, g_qkv);   qkvP  = (float*)p;
    cudaGetSymbolAddress(&p, g_z);     zP    = (float*)p;
    cudaGetSymbolAddress(&p, g_ff);    ffP   = (float*)p;

    int attn_smem = (3*TT*DHEAD + TT*66) * sizeof(float);
    cudaFuncSetAttribute(k_attn, cudaFuncAttributeMaxDynamicSharedMemorySize, attn_smem);

    k_transpose_x<<<(BB*NN + 255)/256, 256>>>(x);

    dim3 gDist64(NN/64, NN/64, BB);
    dim3 gDist128(NN/128, NN/128, BB);

    // ---- EdgeConv 1: C=3 -> O=64 ----
    k_xx<<<(BB*NN + 255)/256, 256>>>(h0P, 3, 0, 3);
    k_gemm<<<gDist64, 256>>>(ftP, fbP, nullptr, xxP, yP,
        NN, NN, 16, (long)NN*16, (long)16*NN, (long)NN*NN, 4);
    k_topk2<<<BB*NN/4, 128>>>(yP);
    cudaMemsetAsync(sumdP, 0, 256*NBIN*sizeof(double));
    cudaMemsetAsync(ssqdP, 0, 256*NBIN*sizeof(double));
    k_edgeconv<64><<<BB*NN, 64>>>(ftP, 16, 3, w1);
    k_finstats<64><<<1, 64>>>();
    k_bnmax<64><<<(BB*NN*64 + 255)/256, 256>>>(g1, b1, 0);

    // ---- EdgeConv 2: x1 (coff 0, C=64) -> O=64 ----
    k_xx<<<(BB*NN + 255)/256, 256>>>(HP, 512, 0, 64);
    k_featT<<<(BB*NN*64 + 255)/256, 256>>>(HP, 512, 0, 64, 64, ftP);
    k_gemm128<<<gDist128, 256>>>(ftP, HP, xxP, yP,
        NN, NN, 64, (long)NN*64, (long)512*NN, (long)NN*NN, 64, NN, 4, 1);
    k_topk2<<<BB*NN/4, 128>>>(yP);
    cudaMemsetAsync(sumdP, 0, 256*NBIN*sizeof(double));
    cudaMemsetAsync(ssqdP, 0, 256*NBIN*sizeof(double));
    k_edgeconv<64><<<BB*NN, 64>>>(ftP, 64, 64, w2);
    k_finstats<64><<<1, 64>>>();
    k_bnmax<64><<<(BB*NN*64 + 255)/256, 256>>>(g2, b2, 64);

    // ---- EdgeConv 3: x2 (coff 64, C=64) -> O=128 ----
    k_xx<<<(BB*NN + 255)/256, 256>>>(HP, 512, 64, 64);
    k_featT<<<(BB*NN*64 + 255)/256, 256>>>(HP, 512, 64, 64, 64, ftP);
    k_gemm128<<<gDist128, 256>>>(ftP, HP + (size_t)64*NN, xxP, yP,
        NN, NN, 64, (long)NN*64, (long)512*NN, (long)NN*NN, 64, NN, 4, 1);
    k_topk2<<<BB*NN/4, 128>>>(yP);
    cudaMemsetAsync(sumdP, 0, 256*NBIN*sizeof(double));
    cudaMemsetAsync(ssqdP, 0, 256*NBIN*sizeof(double));
    k_edgeconv<128><<<BB*NN, 128>>>(ftP, 64, 64, w3);
    k_finstats<128><<<1, 128>>>();
    k_bnmax<128><<<(BB*NN*128 + 255)/256, 256>>>(g3, b3, 128);

    // ---- EdgeConv 4: x3 (coff 128, C=128) -> O=256 ----
    k_xx<<<(BB*NN + 255)/256, 256>>>(HP, 512, 128, 128);
    k_featT<<<(BB*NN*128 + 255)/256, 256>>>(HP, 512, 128, 128, 128, ftP);
    k_gemm128<<<gDist128, 256>>>(ftP, HP + (size_t)128*NN, xxP, yP,
        NN, NN, 128, (long)NN*128, (long)512*NN, (long)NN*NN, 128, NN, 4, 1);
    k_topk2<<<BB*NN/4, 128>>>(yP);
    cudaMemsetAsync(sumdP, 0, 256*NBIN*sizeof(double));
    cudaMemsetAsync(ssqdP, 0, 256*NBIN*sizeof(double));
    k_edgeconv<256><<<BB*NN, 256>>>(ftP, 128, 128, w4);
    k_finstats<256><<<1, 256>>>();
    k_bnmax<256><<<(BB*NN*256 + 255)/256, 256>>>(g4, b4, 256);

    // ---- conv5: y[b] = w5[1024,512] @ H[b][512,2048] ----
    k_gemm128<<<dim3(NN/128, 1024/128, BB), 256>>>(
        w5, HP, nullptr, yP, 1024, NN, 512,
        0L, (long)512*NN, (long)1024*NN, 512, NN, 0, 0);
    k_stats5<<<1024, 256>>>();
    k_pool<<<(BB*DD*PP + 255)/256, 256>>>(g5, b5, cls);

    // ---- transformer (64x64 k_gemm: max parallelism at M=520) ----
    for (int i = 0; i < DEPTH; i++) {
        k_ln<<<TOK, 256>>>(pos, ln1g + (size_t)i*DD, ln1b + (size_t)i*DD, hnP);
        k_gemm<<<dim3((3*INNER)/64, (TOK + 63)/64, 1), 256>>>(
            hnP, wqkv + (size_t)i*DD*3*INNER, nullptr, nullptr, qkvP,
            TOK, 3*INNER, DD, 0L, 0L, 0L, 0);
        k_attn<<<BB*NHEAD, 128, attn_smem>>>(qkvP, zP);
        k_gemm<<<dim3(DD/64, (TOK + 63)/64, 1), 256>>>(
            zP, wout + (size_t)i*INNER*DD, bout + (size_t)i*DD, nullptr, tP,
            TOK, DD, INNER, 0L, 0L, 0L, 3);
        k_ln<<<TOK, 256>>>(nullptr, ln2g + (size_t)i*DD, ln2b + (size_t)i*DD, hnP);
        k_gemm<<<dim3(MLPD/64, (TOK + 63)/64, 1), 256>>>(
            hnP, wff1 + (size_t)i*DD*MLPD, bff1 + (size_t)i*MLPD, nullptr, ffP,
            TOK, MLPD, DD, 0L, 0L, 0L, 2);
        k_gemm<<<dim3(DD/64, (TOK + 63)/64, 1), 256>>>(
            ffP, wff2 + (size_t)i*MLPD*DD, bff2 + (size_t)i*DD, nullptr, tP,
            TOK, DD, MLPD, 0L, 0L, 0L, 3);
    }

    k_out<<<(BB*PP*DD + 255)/256, 256>>>((float*)d_out);
}

// round 12
// speedup vs baseline: 1.1912x; 1.0008x over previous
#include <cuda_runtime.h>
#include <math.h>

#define BB    8
#define NN    2048
#define KKN   20
#define PP    64
#define PSZ   32
#define DD    1024
#define TT    65
#define TOK   (BB*TT)     // 520
#define INNER 512
#define NHEAD 8
#define DHEAD 64
#define MLPD  2048
#define DEPTH 6
#define EPSV  1e-5f
#define NBIN  64

// ---------------- scratch (static device globals; no runtime allocation) ----
__device__ float  g_h0 [BB*3*NN];                     // transposed xyz [B,3,N]
__device__ float  g_H  [BB*512*NN];                   // concat features [B,512,N]
__device__ float  g_xx[BB*NN];
__device__ int    g_idx[BB*NN*KKN];
__device__ float  g_y [(size_t)BB*NN*KKN*256];        // 335MB scratch: dist matrix, then conv y
__device__ float  g_ft [BB*NN*128];                   // row-major features [B*N][Cld]
__device__ float  g_fpadB[BB*16*NN];                  // zero-padded xyz [B,16,N]
__device__ double g_sumd[256*NBIN];
__device__ double g_ssqd[256*NBIN];
__device__ float  g_mu [1024];
__device__ float  g_rs [1024];
__device__ float  g_t  [TOK*DD];
__device__ float  g_hn [TOK*DD];
__device__ float  g_qkv[TOK*3*INNER];
__device__ float  g_z  [TOK*INNER];
__device__ float  g_ff [TOK*MLPD];

// ------- stage 0: transpose x + build padded B operand + conv1 ft rows -------
__global__ void k_transpose_x(const float* __restrict__ x) {
    int id = blockIdx.x*256 + threadIdx.x;
    if (id >= BB*NN) return;
    int b = id / NN, n = id % NN;
    float v[3];
    #pragma unroll
    for (int c = 0; c < 3; c++) {
        v[c] = x[id*3 + c];
        g_h0[(b*3+c)*NN + n] = v[c];
        g_fpadB[(b*16+c)*NN + n] = v[c];
    }
    #pragma unroll
    for (int c = 3; c < 16; c++) g_fpadB[(b*16+c)*NN + n] = 0.f;
    #pragma unroll
    for (int c = 0; c < 16; c++) g_ft[(size_t)id*16 + c] = (c < 3) ? v[c] : 0.f;
}

// ---------------- xx = sum_c x^2 ---------------------------------------------
__global__ void k_xx(const float* __restrict__ src, int Ctot, int coff, int C) {
    int id = blockIdx.x*256 + threadIdx.x;
    if (id >= BB*NN) return;
    int b = id / NN, m = id % NN;
    float s = 0.f;
    for (int c = 0; c < C; c++) {
        float v = src[((size_t)b*Ctot + coff + c)*NN + m];
        s = fmaf(v, v, s);
    }
    g_xx[id] = s;
}

// ---------------- build row-major feature copy [B*N][Kpad] -------------------
__global__ void k_featT(const float* __restrict__ src, int Ctot, int coff, int C,
                        int Kpad, float* __restrict__ out) {
    int id = blockIdx.x*256 + threadIdx.x;
    if (id >= BB*NN*Kpad) return;
    int c = id % Kpad; int rem = id / Kpad;
    int n = rem % NN, b = rem / NN;
    out[id] = (c < C) ? src[((size_t)b*Ctot + coff + c)*NN + n] : 0.f;
}

// ---------------- generic tiled fp32 GEMM (64x64) ----------------------------
// epi: 0 plain, 1 +bias, 2 gelu(x+bias), 3 x+bias+dst residual, 4 dist
__global__ void k_gemm(const float* __restrict__ A, const float* __restrict__ Bm,
                       const float* __restrict__ bias, const float* __restrict__ xx,
                       float* dst,
                       int M, int Nc, int Kc, long sA, long sB, long sC, int epi) {
    __shared__ __align__(16) float As[16][64];
    __shared__ __align__(16) float Bs[16][64];
    int tid = threadIdx.x;
    int tx = tid & 15, ty = tid >> 4;
    int row0 = blockIdx.y*64, col0 = blockIdx.x*64;
    const float* Ap = A + (size_t)blockIdx.z*sA;
    const float* Bp = Bm + (size_t)blockIdx.z*sB;
    float acc[4][4] = {};
    int r = tid >> 2, kq = tid & 3;
    for (int kt = 0; kt < Kc; kt += 16) {
        float4 a4 = make_float4(0.f, 0.f, 0.f, 0.f);
        int row = row0 + r;
        if (row < M) a4 = *(const float4*)&Ap[(size_t)row*Kc + kt + kq*4];
        As[kq*4+0][r] = a4.x; As[kq*4+1][r] = a4.y;
        As[kq*4+2][r] = a4.z; As[kq*4+3][r] = a4.w;
        #pragma unroll
        for (int i = 0; i < 4; i++) {
            int kr = (tid >> 6) + i*4;
            Bs[kr][tid & 63] = Bp[(size_t)(kt + kr)*Nc + col0 + (tid & 63)];
        }
        __syncthreads();
        #pragma unroll
        for (int kk = 0; kk < 16; kk++) {
            float4 a = *(const float4*)&As[kk][ty*4];
            float4 bq = *(const float4*)&Bs[kk][tx*4];
            acc[0][0] = fmaf(a.x, bq.x, acc[0][0]); acc[0][1] = fmaf(a.x, bq.y, acc[0][1]);
            acc[0][2] = fmaf(a.x, bq.z, acc[0][2]); acc[0][3] = fmaf(a.x, bq.w, acc[0][3]);
            acc[1][0] = fmaf(a.y, bq.x, acc[1][0]); acc[1][1] = fmaf(a.y, bq.y, acc[1][1]);
            acc[1][2] = fmaf(a.y, bq.z, acc[1][2]); acc[1][3] = fmaf(a.y, bq.w, acc[1][3]);
            acc[2][0] = fmaf(a.z, bq.x, acc[2][0]); acc[2][1] = fmaf(a.z, bq.y, acc[2][1]);
            acc[2][2] = fmaf(a.z, bq.z, acc[2][2]); acc[2][3] = fmaf(a.z, bq.w, acc[2][3]);
            acc[3][0] = fmaf(a.w, bq.x, acc[3][0]); acc[3][1] = fmaf(a.w, bq.y, acc[3][1]);
            acc[3][2] = fmaf(a.w, bq.z, acc[3][2]); acc[3][3] = fmaf(a.w, bq.w, acc[3][3]);
        }
        __syncthreads();
    }
    float* Dp = dst + (size_t)blockIdx.z*sC;
    const float* xxz = (epi == 4) ? (xx + (size_t)blockIdx.z*Nc) : nullptr;
    #pragma unroll
    for (int i = 0; i < 4; i++) {
        int row = row0 + ty*4 + i;
        if (row >= M) continue;
        #pragma unroll
        for (int j = 0; j < 4; j++) {
            int col = col0 + tx*4 + j;
            float v = acc[i][j];
            if (epi == 1 || epi == 2 || epi == 3) v += bias[col];
            if (epi == 2) v = 0.5f*v*(1.0f + erff(v*0.70710678118654752f));
            if (epi == 3) v += Dp[(size_t)row*Nc + col];
            if (epi == 4) v = 2.0f*v - xxz[row] - xxz[col];
            Dp[(size_t)row*Nc + col] = v;
        }
    }
}

// ---------------- 128x128-tile fp32 GEMM (8x8/thread), optional symmetry -----
__global__ void __launch_bounds__(256) k_gemm128(
        const float* __restrict__ A, const float* __restrict__ Bm,
        const float* __restrict__ xx, float* __restrict__ dst,
        int M, int Nc, int Kc,
        long sA, long sB, long sC, int lda, int ldb, int epi, int sym) {
    int bx = blockIdx.x, by = blockIdx.y;
    if (sym && bx < by) return;
    __shared__ __align__(16) float As[16][128];
    __shared__ __align__(16) float Bs[16][128];
    int tid = threadIdx.x;
    int tx = tid & 15, ty = tid >> 4;
    int row0 = by*128, col0 = bx*128;
    const float* Ap = A + (size_t)blockIdx.z*sA;
    const float* Bp = Bm + (size_t)blockIdx.z*sB;
    float acc[8][8] = {};
    int ar = tid >> 1, ak = (tid & 1)*8;
    int bkr = tid >> 4, bc4 = (tid & 15)*8;
    for (int kt = 0; kt < Kc; kt += 16) {
        float4 a0 = make_float4(0.f,0.f,0.f,0.f), a1 = a0;
        int arow = row0 + ar;
        if (arow < M) {
            a0 = *(const float4*)&Ap[(size_t)arow*lda + kt + ak];
            a1 = *(const float4*)&Ap[(size_t)arow*lda + kt + ak + 4];
        }
        As[ak+0][ar] = a0.x; As[ak+1][ar] = a0.y; As[ak+2][ar] = a0.z; As[ak+3][ar] = a0.w;
        As[ak+4][ar] = a1.x; As[ak+5][ar] = a1.y; As[ak+6][ar] = a1.z; As[ak+7][ar] = a1.w;
        *(float4*)&Bs[bkr][bc4]   = *(const float4*)&Bp[(size_t)(kt+bkr)*ldb + col0 + bc4];
        *(float4*)&Bs[bkr][bc4+4] = *(const float4*)&Bp[(size_t)(kt+bkr)*ldb + col0 + bc4 + 4];
        __syncthreads();
        #pragma unroll
        for (int kk = 0; kk < 16; kk++) {
            float av[8], bv[8];
            *(float4*)&av[0] = *(const float4*)&As[kk][ty*8];
            *(float4*)&av[4] = *(const float4*)&As[kk][ty*8+4];
            *(float4*)&bv[0] = *(const float4*)&Bs[kk][tx*8];
            *(float4*)&bv[4] = *(const float4*)&Bs[kk][tx*8+4];
            #pragma unroll
            for (int i = 0; i < 8; i++)
                #pragma unroll
                for (int j = 0; j < 8; j++)
                    acc[i][j] = fmaf(av[i], bv[j], acc[i][j]);
        }
        __syncthreads();
    }
    float* Dp = dst + (size_t)blockIdx.z*sC;
    if (epi == 4) {
        const float* xxz = xx + (size_t)blockIdx.z*Nc;
        float xr[8], xc[8];
        #pragma unroll
        for (int i = 0; i < 8; i++) xr[i] = xxz[row0 + ty*8 + i];
        #pragma unroll
        for (int j = 0; j < 8; j++) xc[j] = xxz[col0 + tx*8 + j];
        #pragma unroll
        for (int i = 0; i < 8; i++) {
            int row = row0 + ty*8 + i;
            float v[8];
            #pragma unroll
            for (int j = 0; j < 8; j++) v[j] = 2.0f*acc[i][j] - xr[i] - xc[j];
            *(float4*)&Dp[(size_t)row*Nc + col0 + tx*8]     = *(float4*)&v[0];
            *(float4*)&Dp[(size_t)row*Nc + col0 + tx*8 + 4] = *(float4*)&v[4];
        }
        if (sym && bx != by) {
            #pragma unroll
            for (int j = 0; j < 8; j++) {
                int col = col0 + tx*8 + j;
                float tv[8];
                #pragma unroll
                for (int i = 0; i < 8; i++) tv[i] = 2.0f*acc[i][j] - xr[i] - xc[j];
                *(float4*)&Dp[(size_t)col*Nc + row0 + ty*8]     = *(float4*)&tv[0];
                *(float4*)&Dp[(size_t)col*Nc + row0 + ty*8 + 4] = *(float4*)&tv[4];
            }
        }
    } else {
        #pragma unroll
        for (int i = 0; i < 8; i++) {
            int row = row0 + ty*8 + i;
            if (row >= M) continue;
            *(float4*)&Dp[(size_t)row*Nc + col0 + tx*8]     = *(float4*)&acc[i][0];
            *(float4*)&Dp[(size_t)row*Nc + col0 + tx*8 + 4] = *(float4*)&acc[i][4];
        }
    }
}

// ------------- top-20 v3: block per row, sort-8/lane + 2-level merge ---------
#define CMPSW(i,j) { if (a[i] < a[j]) { unsigned long long tq = a[i]; a[i] = a[j]; a[j] = tq; } }
__global__ void __launch_bounds__(256) k_topk3(const float* __restrict__ dist) {
    __shared__ unsigned long long sml[8*256];     // [pos][tid] sorted lists (16KB)
    __shared__ unsigned long long wtop[8*20];     // per-warp top-20
    int t = threadIdx.x;
    int w = t >> 5, lane = t & 31;
    int bn = blockIdx.x;
    const float* dp = dist + (size_t)bn*NN;
    unsigned long long a[8];
    #pragma unroll
    for (int i = 0; i < 8; i++) {
        int m = w*256 + i*32 + lane;
        unsigned int u = __float_as_uint(dp[m]);
        u ^= ((unsigned int)((int)u >> 31)) | 0x80000000u;   // monotone map
        a[i] = ((unsigned long long)u << 32) | (unsigned int)(2047 - m);
    }
    // optimal 19-comparator descending sort of 8
    CMPSW(0,1) CMPSW(2,3) CMPSW(4,5) CMPSW(6,7)
    CMPSW(0,2) CMPSW(1,3) CMPSW(4,6) CMPSW(5,7)
    CMPSW(1,2) CMPSW(5,6) CMPSW(0,4) CMPSW(3,7)
    CMPSW(1,5) CMPSW(2,6)
    CMPSW(1,4) CMPSW(3,6)
    CMPSW(2,4) CMPSW(3,5)
    CMPSW(3,4)
    #pragma unroll
    for (int i = 0; i < 8; i++) sml[i*256 + t] = a[i];
    __syncwarp();
    // per-warp merge: top-20 of this warp's 256 elements
    {
        int pos = 0;
        unsigned long long cur = a[0];
        #pragma unroll
        for (int j = 0; j < 20; j++) {
            unsigned long long mx = cur;
            #pragma unroll
            for (int off = 16; off; off >>= 1) {
                unsigned long long o = __shfl_xor_sync(0xffffffffu, mx, off);
                if (o > mx) mx = o;
            }
            if (lane == 0) wtop[w*20 + j] = mx;
            if (cur == mx) { pos++; cur = (pos < 8) ? sml[pos*256 + t] : 0ull; }
        }
    }
    __syncthreads();
    // warp 0 merges the 8 sorted 20-lists
    if (w == 0) {
        int pos = 0;
        unsigned long long cur = (lane < 8) ? wtop[lane*20] : 0ull;
        #pragma unroll
        for (int j = 0; j < 20; j++) {
            unsigned long long mx = cur;
            #pragma unroll
            for (int off = 16; off; off >>= 1) {
                unsigned long long o = __shfl_xor_sync(0xffffffffu, mx, off);
                if (o > mx) mx = o;
            }
            if (lane == 0) g_idx[bn*KKN + j] = 2047 - (int)(mx & 0xffffffffu);
            if (cur == mx && lane < 8) { pos++; cur = (pos < 20) ? wtop[lane*20 + pos] : 0ull; }
        }
    }
}

// -------- EdgeConv: coalesced gather from row-major ft + conv + BN sums ------
template<int O>
__global__ void k_edgeconv(const float* __restrict__ ft, int Cld, int C,
                           const float* __restrict__ w) {
    __shared__ __align__(16) float ctr[128];
    __shared__ __align__(16) float nd[KKN*128];
    __shared__ int sidx[KKN];
    int bn = blockIdx.x;
    int b = bn >> 11;
    int t = threadIdx.x;
    if (t < KKN) sidx[t] = g_idx[bn*KKN + t];
    for (int e = t; e < C; e += O)
        ctr[e] = ft[(size_t)bn*Cld + e];
    __syncthreads();
    for (int e = t; e < KKN*C; e += O) {
        int kk = e / C, c = e - kk*C;
        nd[e] = ft[((size_t)(b*NN + sidx[kk]))*Cld + c] - ctr[c];
    }
    __syncthreads();

    int o = t;
    float acc[KKN];
    #pragma unroll
    for (int kk = 0; kk < KKN; kk++) acc[kk] = 0.f;
    float base = 0.f;
    const float* wr = w + (size_t)o*2*C;
    if ((C & 3) == 0) {
        for (int c = 0; c < C; c += 4) {
            float4 w1 = *(const float4*)&wr[c];
            float4 w2 = *(const float4*)&wr[C + c];
            float4 ct = *(const float4*)&ctr[c];
            base = fmaf(w2.x, ct.x, fmaf(w2.y, ct.y, fmaf(w2.z, ct.z, fmaf(w2.w, ct.w, base))));
            #pragma unroll
            for (int kk = 0; kk < KKN; kk++) {
                float4 nv = *(const float4*)&nd[kk*C + c];
                acc[kk] = fmaf(w1.x, nv.x, fmaf(w1.y, nv.y,
                          fmaf(w1.z, nv.z, fmaf(w1.w, nv.w, acc[kk]))));
            }
        }
    } else {
        for (int c = 0; c < C; c++) {
            float w1 = wr[c], w2 = wr[C + c], ct = ctr[c];
            base = fmaf(w2, ct, base);
            #pragma unroll
            for (int kk = 0; kk < KKN; kk++) acc[kk] = fmaf(w1, nd[kk*C + c], acc[kk]);
        }
    }
    double s = 0.0, ss = 0.0;
    float* yp = g_y + ((size_t)bn*KKN)*O + o;
    #pragma unroll
    for (int kk = 0; kk < KKN; kk++) {
        float v = acc[kk] + base;
        yp[(size_t)kk*O] = v;
        double vd = (double)v;
        s += vd; ss += vd*vd;
    }
    int bin = bn & (NBIN-1);
    atomicAdd(&g_sumd[o*NBIN + bin], s);
    atomicAdd(&g_ssqd[o*NBIN + bin], ss);
}

// ------------- finalize BN stats (and re-zero bins for the next stage) -------
template<int O>
__global__ void k_finstats() {
    int o = threadIdx.x;
    if (o >= O) return;
    double s = 0.0, ss = 0.0;
    #pragma unroll 8
    for (int i = 0; i < NBIN; i++) {
        s += g_sumd[o*NBIN + i]; ss += g_ssqd[o*NBIN + i];
        g_sumd[o*NBIN + i] = 0.0; g_ssqd[o*NBIN + i] = 0.0;
    }
    const double cnt = (double)BB*NN*KKN;
    double mu = s / cnt;
    double var = ss / cnt - mu*mu;
    g_mu[o] = (float)mu;
    g_rs[o] = rsqrtf((float)var + EPSV);
}

// ---------------- BN normalize + leaky + max over k --------------------------
template<int O>
__global__ void k_bnmax(const float* __restrict__ g, const float* __restrict__ bb, int coff) {
    int id = blockIdx.x*256 + threadIdx.x;
    if (id >= BB*NN*O) return;
    int o = id % O, bn = id / O;
    float mu = g_mu[o], rs = g_rs[o];
    float gg = g[o], bv = bb[o];
    const float* yp = g_y + ((size_t)bn*KKN)*O + o;
    float mx = -INFINITY;
    #pragma unroll
    for (int kk = 0; kk < KKN; kk++) {
        float v = (yp[(size_t)kk*O] - mu)*rs*gg + bv;
        v = v >= 0.f ? v : 0.2f*v;
        mx = fmaxf(mx, v);
    }
    int b = bn >> 11, n = bn & 2047;
    g_H[((size_t)b*512 + coff + o)*NN + n] = mx;
}

// ---------------- conv5 BN stats (block per channel, double accum) -----------
__global__ void k_stats5() {
    int d = blockIdx.x, t = threadIdx.x;
    double s = 0.0, ss = 0.0;
    for (int b = 0; b < BB; b++) {
        const float* yp = g_y + ((size_t)(b*1024 + d))*NN;
        for (int n = t; n < NN; n += 256) {
            double v = (double)yp[n];
            s += v; ss += v*v;
        }
    }
    __shared__ double sred[8], ssred[8];
    for (int off = 16; off; off >>= 1) {
        s  += __shfl_xor_sync(0xffffffffu, s, off);
        ss += __shfl_xor_sync(0xffffffffu, ss, off);
    }
    if ((t & 31) == 0) { sred[t >> 5] = s; ssred[t >> 5] = ss; }
    __syncthreads();
    if (t == 0) {
        s = 0.0; ss = 0.0;
        for (int i = 0; i < 8; i++) { s += sred[i]; ss += ssred[i]; }
        double mu = s*(1.0/16384.0);
        double var = ss*(1.0/16384.0) - mu*mu;
        g_mu[d] = (float)mu;
        g_rs[d] = rsqrtf((float)var + EPSV);
    }
}

// ---------------- BN+leaky+patch max-pool + cls token ------------------------
__global__ void k_pool(const float* __restrict__ g5, const float* __restrict__ b5,
                       const float* __restrict__ cls) {
    int id = blockIdx.x*256 + threadIdx.x;
    if (id >= BB*DD*PP) return;
    int p = id % PP, d = (id / PP) % DD, b = id / (PP*DD);
    float mu = g_mu[d], r = g_rs[d], gg = g5[d], bv = b5[d];
    const float* yp = g_y + ((size_t)(b*1024 + d))*NN + p*PSZ;
    float mx = -INFINITY;
    #pragma unroll
    for (int s_ = 0; s_ < PSZ; s_++) {
        float v = (yp[s_] - mu)*r*gg + bv;
        v = v >= 0.f ? v : 0.2f*v;
        mx = fmaxf(mx, v);
    }
    g_t[((size_t)(b*TT + 1 + p))*DD + d] = mx;
    if (p == 0) g_t[((size_t)(b*TT))*DD + d] = cls[d];
}

// ---------------- two-pass LN (optional fused +pos residual into t) ----------
__global__ void k_ln(const float* __restrict__ pos, const float* __restrict__ g,
                     const float* __restrict__ b, float* __restrict__ out) {
    int row = blockIdx.x, t = threadIdx.x;
    float* xp = g_t + (size_t)row*DD;
    float v0 = xp[t], v1 = xp[t+256], v2 = xp[t+512], v3 = xp[t+768];
    if (pos) {
        const float* pp = pos + (size_t)row*DD;
        v0 += pp[t]; v1 += pp[t+256]; v2 += pp[t+512]; v3 += pp[t+768];
        xp[t] = v0; xp[t+256] = v1; xp[t+512] = v2; xp[t+768] = v3;
    }
    __shared__ float red[8];
    __shared__ float bc[2];
    float s = v0+v1+v2+v3;
    for (int off = 16; off; off >>= 1) s += __shfl_xor_sync(0xffffffffu, s, off);
    if ((t & 31) == 0) red[t >> 5] = s;
    __syncthreads();
    if (t == 0) {
        s = 0.f;
        for (int i = 0; i < 8; i++) s += red[i];
        bc[0] = s*(1.0f/1024.0f);
    }
    __syncthreads();
    float mu = bc[0];
    float d0 = v0-mu, d1 = v1-mu, d2 = v2-mu, d3 = v3-mu;
    float ss = d0*d0 + d1*d1 + d2*d2 + d3*d3;
    for (int off = 16; off; off >>= 1) ss += __shfl_xor_sync(0xffffffffu, ss, off);
    if ((t & 31) == 0) red[t >> 5] = ss;
    __syncthreads();
    if (t == 0) {
        ss = 0.f;
        for (int i = 0; i < 8; i++) ss += red[i];
        bc[1] = rsqrtf(ss*(1.0f/1024.0f) + EPSV);
    }
    __syncthreads();
    float r = bc[1];
    float* op = out + (size_t)row*DD;
    op[t]     = d0*r*g[t]     + b[t];
    op[t+256] = d1*r*g[t+256] + b[t+256];
    op[t+512] = d2*r*g[t+512] + b[t+512];
    op[t+768] = d3*r*g[t+768] + b[t+768];
}

// block per (b,h); dynamic smem q/k/v[65][64] + probs[65][66]
__global__ void k_attn(const float* __restrict__ qkv, float* __restrict__ z) {
    extern __shared__ float sm[];
    float* q = sm;
    float* k = q + TT*DHEAD;
    float* v = k + TT*DHEAD;
    float* s = v + TT*DHEAD;        // [65][66]
    int b = blockIdx.x >> 3, h = blockIdx.x & 7;
    int t = threadIdx.x;            // 128
    for (int e = t; e < TT*DHEAD; e += 128) {
        int tt = e >> 6, d = e & 63;
        size_t base = ((size_t)(b*TT + tt))*(3*INNER) + h*64 + d;
        q[e] = qkv[base]; k[e] = qkv[base + 512]; v[e] = qkv[base + 1024];
    }
    __syncthreads();
    for (int e = t; e < TT*TT; e += 128) {
        int i = e / TT, j = e - i*TT;
        float acc = 0.f;
        #pragma unroll
        for (int d = 0; d < 64; d++) acc = fmaf(q[i*64+d], k[j*64+d], acc);
        s[i*66 + j] = acc*0.125f;
    }
    __syncthreads();
    int w = t >> 5, lane = t & 31;
    for (int i = w; i < TT; i += 4) {
        float a0 = s[i*66 + lane], a1 = s[i*66 + 32 + lane];
        float a2 = (lane == 0) ? s[i*66 + 64] : -INFINITY;
        float mx = fmaxf(fmaxf(a0, a1), a2);
        for (int off = 16; off; off >>= 1) mx = fmaxf(mx, __shfl_xor_sync(0xffffffffu, mx, off));
        float e0 = expf(a0 - mx), e1 = expf(a1 - mx);
        float e2 = (lane == 0) ? expf(a2 - mx) : 0.f;
        float sum = e0 + e1 + e2;
        for (int off = 16; off; off >>= 1) sum += __shfl_xor_sync(0xffffffffu, sum, off);
        float inv = 1.0f / sum;
        s[i*66 + lane] = e0*inv; s[i*66 + 32 + lane] = e1*inv;
        if (lane == 0) s[i*66 + 64] = e2*inv;
    }
    __syncthreads();
    for (int e = t; e < TT*DHEAD; e += 128) {
        int i = e >> 6, d = e & 63;
        float acc = 0.f;
        for (int j = 0; j < TT; j++) acc = fmaf(s[i*66 + j], v[j*64 + d], acc);
        z[((size_t)(b*TT + i))*INNER + h*64 + d] = acc;
    }
}

__global__ void k_out(float* __restrict__ out) {
    int id = blockIdx.x*256 + threadIdx.x;
    if (id >= BB*PP*DD) return;
    int d = id % DD, p = (id / DD) % PP, b = id / (DD*PP);
    out[id] = g_t[((size_t)(b*TT + 1 + p))*DD + d];
}

// =============================================================================
extern "C" void kernel_launch(void* const* d_in, const int* in_sizes, int n_in,
                              void* d_out, int out_size) {
    const float* x    = (const float*)d_in[0];
    const float* pos  = (const float*)d_in[1];
    const float* w1   = (const float*)d_in[2];
    const float* g1   = (const float*)d_in[3];
    const float* b1   = (const float*)d_in[4];
    const float* w2   = (const float*)d_in[5];
    const float* g2   = (const float*)d_in[6];
    const float* b2   = (const float*)d_in[7];
    const float* w3   = (const float*)d_in[8];
    const float* g3   = (const float*)d_in[9];
    const float* b3   = (const float*)d_in[10];
    const float* w4   = (const float*)d_in[11];
    const float* g4   = (const float*)d_in[12];
    const float* b4   = (const float*)d_in[13];
    const float* w5   = (const float*)d_in[14];
    const float* g5   = (const float*)d_in[15];
    const float* b5   = (const float*)d_in[16];
    const float* cls  = (const float*)d_in[17];
    const float* ln1g = (const float*)d_in[18];
    const float* ln1b = (const float*)d_in[19];
    const float* wqkv = (const float*)d_in[20];
    const float* wout = (const float*)d_in[21];
    const float* bout = (const float*)d_in[22];
    const float* ln2g = (const float*)d_in[23];
    const float* ln2b = (const float*)d_in[24];
    const float* wff1 = (const float*)d_in[25];
    const float* bff1 = (const float*)d_in[26];
    const float* wff2 = (const float*)d_in[27];
    const float* bff2 = (const float*)d_in[28];

    void* p;
    float *h0P, *HP, *xxP, *yP, *ftP, *fbP, *tP, *hnP, *qkvP, *zP, *ffP;
    double *sumdP, *ssqdP;
    cudaGetSymbolAddress(&p, g_h0);    h0P   = (float*)p;
    cudaGetSymbolAddress(&p, g_H);     HP    = (float*)p;
    cudaGetSymbolAddress(&p, g_xx);    xxP   = (float*)p;
    cudaGetSymbolAddress(&p, g_y);     yP    = (float*)p;
    cudaGetSymbolAddress(&p, g_ft);    ftP   = (float*)p;
    cudaGetSymbolAddress(&p, g_fpadB); fbP   = (float*)p;
    cudaGetSymbolAddress(&p, g_sumd);  sumdP = (double*)p;
    cudaGetSymbolAddress(&p, g_ssqd);  ssqdP = (double*)p;
    cudaGetSymbolAddress(&p, g_t);     tP    = (float*)p;
    cudaGetSymbolAddress(&p, g_hn);    hnP   = (float*)p;
    cudaGetSymbolAddress(&p, g_qkv);   qkvP  = (float*)p;
    cudaGetSymbolAddress(&p, g_z);     zP    = (float*)p;
    cudaGetSymbolAddress(&p, g_ff);    ffP   = (float*)p;

    int attn_smem = (3*TT*DHEAD + TT*66) * sizeof(float);
    cudaFuncSetAttribute(k_attn, cudaFuncAttributeMaxDynamicSharedMemorySize, attn_smem);

    k_transpose_x<<<(BB*NN + 255)/256, 256>>>(x);
    cudaMemsetAsync(sumdP, 0, 256*NBIN*sizeof(double));
    cudaMemsetAsync(ssqdP, 0, 256*NBIN*sizeof(double));

    dim3 gDist64(NN/64, NN/64, BB);
    dim3 gDist128(NN/128, NN/128, BB);

    // ---- EdgeConv 1: C=3 -> O=64 ----
    k_xx<<<(BB*NN + 255)/256, 256>>>(h0P, 3, 0, 3);
    k_gemm<<<gDist64, 256>>>(ftP, fbP, nullptr, xxP, yP,
        NN, NN, 16, (long)NN*16, (long)16*NN, (long)NN*NN, 4);
    k_topk3<<<BB*NN, 256>>>(yP);
    k_edgeconv<64><<<BB*NN, 64>>>(ftP, 16, 3, w1);
    k_finstats<64><<<1, 64>>>();
    k_bnmax<64><<<(BB*NN*64 + 255)/256, 256>>>(g1, b1, 0);

    // ---- EdgeConv 2: x1 (coff 0, C=64) -> O=64 ----
    k_xx<<<(BB*NN + 255)/256, 256>>>(HP, 512, 0, 64);
    k_featT<<<(BB*NN*64 + 255)/256, 256>>>(HP, 512, 0, 64, 64, ftP);
    k_gemm128<<<gDist128, 256>>>(ftP, HP, xxP, yP,
        NN, NN, 64, (long)NN*64, (long)512*NN, (long)NN*NN, 64, NN, 4, 1);
    k_topk3<<<BB*NN, 256>>>(yP);
    k_edgeconv<64><<<BB*NN, 64>>>(ftP, 64, 64, w2);
    k_finstats<64><<<1, 64>>>();
    k_bnmax<64><<<(BB*NN*64 + 255)/256, 256>>>(g2, b2, 64);

    // ---- EdgeConv 3: x2 (coff 64, C=64) -> O=128 ----
    k_xx<<<(BB*NN + 255)/256, 256>>>(HP, 512, 64, 64);
    k_featT<<<(BB*NN*64 + 255)/256, 256>>>(HP, 512, 64, 64, 64, ftP);
    k_gemm128<<<gDist128, 256>>>(ftP, HP + (size_t)64*NN, xxP, yP,
        NN, NN, 64, (long)NN*64, (long)512*NN, (long)NN*NN, 64, NN, 4, 1);
    k_topk3<<<BB*NN, 256>>>(yP);
    k_edgeconv<128><<<BB*NN, 128>>>(ftP, 64, 64, w3);
    k_finstats<128><<<1, 128>>>();
    k_bnmax<128><<<(BB*NN*128 + 255)/256, 256>>>(g3, b3, 128);

    // ---- EdgeConv 4: x3 (coff 128, C=128) -> O=256 ----
    k_xx<<<(BB*NN + 255)/256, 256>>>(HP, 512, 128, 128);
    k_featT<<<(BB*NN*128 + 255)/256, 256>>>(HP, 512, 128, 128, 128, ftP);
    k_gemm128<<<gDist128, 256>>>(ftP, HP + (size_t)128*NN, xxP, yP,
        NN, NN, 128, (long)NN*128, (long)512*NN, (long)NN*NN, 128, NN, 4, 1);
    k_topk3<<<BB*NN, 256>>>(yP);
    k_edgeconv<256><<<BB*NN, 256>>>(ftP, 128, 128, w4);
    k_finstats<256><<<1, 256>>>();
    k_bnmax<256><<<(BB*NN*256 + 255)/256, 256>>>(g4, b4, 256);

    // ---- conv5: y[b] = w5[1024,512] @ H[b][512,2048] ----
    k_gemm128<<<dim3(NN/128, 1024/128, BB), 256>>>(
        w5, HP, nullptr, yP, 1024, NN, 512,
        0L, (long)512*NN, (long)1024*NN, 512, NN, 0, 0);
    k_stats5<<<1024, 256>>>();
    k_pool<<<(BB*DD*PP + 255)/256, 256>>>(g5, b5, cls);

    // ---- transformer (64x64 k_gemm: max parallelism at M=520) ----
    for (int i = 0; i < DEPTH; i++) {
        k_ln<<<TOK, 256>>>(pos, ln1g + (size_t)i*DD, ln1b + (size_t)i*DD, hnP);
        k_gemm<<<dim3((3*INNER)/64, (TOK + 63)/64, 1), 256>>>(
            hnP, wqkv + (size_t)i*DD*3*INNER, nullptr, nullptr, qkvP,
            TOK, 3*INNER, DD, 0L, 0L, 0L, 0);
        k_attn<<<BB*NHEAD, 128, attn_smem>>>(qkvP, zP);
        k_gemm<<<dim3(DD/64, (TOK + 63)/64, 1), 256>>>(
            zP, wout + (size_t)i*INNER*DD, bout + (size_t)i*DD, nullptr, tP,
            TOK, DD, INNER, 0L, 0L, 0L, 3);
        k_ln<<<TOK, 256>>>(nullptr, ln2g + (size_t)i*DD, ln2b + (size_t)i*DD, hnP);
        k_gemm<<<dim3(MLPD/64, (TOK + 63)/64, 1), 256>>>(
            hnP, wff1 + (size_t)i*DD*MLPD, bff1 + (size_t)i*MLPD, nullptr, ffP,
            TOK, MLPD, DD, 0L, 0L, 0L, 2);
        k_gemm<<<dim3(DD/64, (TOK + 63)/64, 1), 256>>>(
            ffP, wff2 + (size_t)i*MLPD*DD, bff2 + (size_t)i*DD, nullptr, tP,
            TOK, DD, MLPD, 0L, 0L, 0L, 3);
    }

    k_out<<<(BB*PP*DD + 255)/256, 256>>>((float*)d_out);
}

// round 13
// speedup vs baseline: 1.2064x; 1.0127x over previous
#include <cuda_runtime.h>
#include <math.h>

#define BB    8
#define NN    2048
#define KKN   20
#define PP    64
#define PSZ   32
#define DD    1024
#define TT    65
#define TOK   (BB*TT)     // 520
#define INNER 512
#define NHEAD 8
#define DHEAD 64
#define MLPD  2048
#define DEPTH 6
#define EPSV  1e-5f
#define NBIN  64

// ---------------- scratch (static device globals; no runtime allocation) ----
__device__ float  g_h0 [BB*3*NN];                     // transposed xyz [B,3,N]
__device__ float  g_H  [BB*512*NN];                   // concat features [B,512,N]
__device__ float  g_xx[BB*NN];
__device__ int    g_idx[BB*NN*KKN];
__device__ float  g_y [(size_t)BB*NN*KKN*256];        // scratch: dist matrix / conv5 y
__device__ float  g_mn [BB*NN*256*2];                 // per-(bn,o) max/min over k
__device__ float  g_ft [BB*NN*128];                   // row-major features [B*N][Cld]
__device__ float  g_fpadB[BB*16*NN];                  // zero-padded xyz [B,16,N]
__device__ double g_sumd[256*NBIN];
__device__ double g_ssqd[256*NBIN];
__device__ float  g_mu [1024];
__device__ float  g_rs [1024];
__device__ float  g_t  [TOK*DD];
__device__ float  g_hn [TOK*DD];
__device__ float  g_qkv[TOK*3*INNER];
__device__ float  g_z  [TOK*INNER];
__device__ float  g_ff [TOK*MLPD];

// ------- stage 0: transpose x + build padded B operand + conv1 ft rows -------
__global__ void k_transpose_x(const float* __restrict__ x) {
    int id = blockIdx.x*256 + threadIdx.x;
    if (id >= BB*NN) return;
    int b = id / NN, n = id % NN;
    float v[3];
    #pragma unroll
    for (int c = 0; c < 3; c++) {
        v[c] = x[id*3 + c];
        g_h0[(b*3+c)*NN + n] = v[c];
        g_fpadB[(b*16+c)*NN + n] = v[c];
    }
    #pragma unroll
    for (int c = 3; c < 16; c++) g_fpadB[(b*16+c)*NN + n] = 0.f;
    #pragma unroll
    for (int c = 0; c < 16; c++) g_ft[(size_t)id*16 + c] = (c < 3) ? v[c] : 0.f;
}

// ---------------- xx = sum_c x^2 ---------------------------------------------
__global__ void k_xx(const float* __restrict__ src, int Ctot, int coff, int C) {
    int id = blockIdx.x*256 + threadIdx.x;
    if (id >= BB*NN) return;
    int b = id / NN, m = id % NN;
    float s = 0.f;
    for (int c = 0; c < C; c++) {
        float v = src[((size_t)b*Ctot + coff + c)*NN + m];
        s = fmaf(v, v, s);
    }
    g_xx[id] = s;
}

// ---------------- generic tiled fp32 GEMM (64x64) ----------------------------
// epi: 0 plain, 1 +bias, 2 gelu(x+bias), 3 x+bias+dst residual, 4 dist
__global__ void k_gemm(const float* __restrict__ A, const float* __restrict__ Bm,
                       const float* __restrict__ bias, const float* __restrict__ xx,
                       float* dst,
                       int M, int Nc, int Kc, long sA, long sB, long sC, int epi) {
    __shared__ __align__(16) float As[16][64];
    __shared__ __align__(16) float Bs[16][64];
    int tid = threadIdx.x;
    int tx = tid & 15, ty = tid >> 4;
    int row0 = blockIdx.y*64, col0 = blockIdx.x*64;
    const float* Ap = A + (size_t)blockIdx.z*sA;
    const float* Bp = Bm + (size_t)blockIdx.z*sB;
    float acc[4][4] = {};
    int r = tid >> 2, kq = tid & 3;
    for (int kt = 0; kt < Kc; kt += 16) {
        float4 a4 = make_float4(0.f, 0.f, 0.f, 0.f);
        int row = row0 + r;
        if (row < M) a4 = *(const float4*)&Ap[(size_t)row*Kc + kt + kq*4];
        As[kq*4+0][r] = a4.x; As[kq*4+1][r] = a4.y;
        As[kq*4+2][r] = a4.z; As[kq*4+3][r] = a4.w;
        #pragma unroll
        for (int i = 0; i < 4; i++) {
            int kr = (tid >> 6) + i*4;
            Bs[kr][tid & 63] = Bp[(size_t)(kt + kr)*Nc + col0 + (tid & 63)];
        }
        __syncthreads();
        #pragma unroll
        for (int kk = 0; kk < 16; kk++) {
            float4 a = *(const float4*)&As[kk][ty*4];
            float4 bq = *(const float4*)&Bs[kk][tx*4];
            acc[0][0] = fmaf(a.x, bq.x, acc[0][0]); acc[0][1] = fmaf(a.x, bq.y, acc[0][1]);
            acc[0][2] = fmaf(a.x, bq.z, acc[0][2]); acc[0][3] = fmaf(a.x, bq.w, acc[0][3]);
            acc[1][0] = fmaf(a.y, bq.x, acc[1][0]); acc[1][1] = fmaf(a.y, bq.y, acc[1][1]);
            acc[1][2] = fmaf(a.y, bq.z, acc[1][2]); acc[1][3] = fmaf(a.y, bq.w, acc[1][3]);
            acc[2][0] = fmaf(a.z, bq.x, acc[2][0]); acc[2][1] = fmaf(a.z, bq.y, acc[2][1]);
            acc[2][2] = fmaf(a.z, bq.z, acc[2][2]); acc[2][3] = fmaf(a.z, bq.w, acc[2][3]);
            acc[3][0] = fmaf(a.w, bq.x, acc[3][0]); acc[3][1] = fmaf(a.w, bq.y, acc[3][1]);
            acc[3][2] = fmaf(a.w, bq.z, acc[3][2]); acc[3][3] = fmaf(a.w, bq.w, acc[3][3]);
        }
        __syncthreads();
    }
    float* Dp = dst + (size_t)blockIdx.z*sC;
    const float* xxz = (epi == 4) ? (xx + (size_t)blockIdx.z*Nc) : nullptr;
    #pragma unroll
    for (int i = 0; i < 4; i++) {
        int row = row0 + ty*4 + i;
        if (row >= M) continue;
        #pragma unroll
        for (int j = 0; j < 4; j++) {
            int col = col0 + tx*4 + j;
            float v = acc[i][j];
            if (epi == 1 || epi == 2 || epi == 3) v += bias[col];
            if (epi == 2) v = 0.5f*v*(1.0f + erff(v*0.70710678118654752f));
            if (epi == 3) v += Dp[(size_t)row*Nc + col];
            if (epi == 4) v = 2.0f*v - xxz[row] - xxz[col];
            Dp[(size_t)row*Nc + col] = v;
        }
    }
}

// ---------------- 128x128-tile fp32 GEMM (8x8/thread), optional symmetry -----
__global__ void __launch_bounds__(256) k_gemm128(
        const float* __restrict__ A, const float* __restrict__ Bm,
        const float* __restrict__ xx, float* __restrict__ dst,
        int M, int Nc, int Kc,
        long sA, long sB, long sC, int lda, int ldb, int epi, int sym) {
    int bx = blockIdx.x, by = blockIdx.y;
    if (sym && bx < by) return;
    __shared__ __align__(16) float As[16][128];
    __shared__ __align__(16) float Bs[16][128];
    int tid = threadIdx.x;
    int tx = tid & 15, ty = tid >> 4;
    int row0 = by*128, col0 = bx*128;
    const float* Ap = A + (size_t)blockIdx.z*sA;
    const float* Bp = Bm + (size_t)blockIdx.z*sB;
    float acc[8][8] = {};
    int ar = tid >> 1, ak = (tid & 1)*8;
    int bkr = tid >> 4, bc4 = (tid & 15)*8;
    for (int kt = 0; kt < Kc; kt += 16) {
        float4 a0 = make_float4(0.f,0.f,0.f,0.f), a1 = a0;
        int arow = row0 + ar;
        if (arow < M) {
            a0 = *(const float4*)&Ap[(size_t)arow*lda + kt + ak];
            a1 = *(const float4*)&Ap[(size_t)arow*lda + kt + ak + 4];
        }
        As[ak+0][ar] = a0.x; As[ak+1][ar] = a0.y; As[ak+2][ar] = a0.z; As[ak+3][ar] = a0.w;
        As[ak+4][ar] = a1.x; As[ak+5][ar] = a1.y; As[ak+6][ar] = a1.z; As[ak+7][ar] = a1.w;
        *(float4*)&Bs[bkr][bc4]   = *(const float4*)&Bp[(size_t)(kt+bkr)*ldb + col0 + bc4];
        *(float4*)&Bs[bkr][bc4+4] = *(const float4*)&Bp[(size_t)(kt+bkr)*ldb + col0 + bc4 + 4];
        __syncthreads();
        #pragma unroll
        for (int kk = 0; kk < 16; kk++) {
            float av[8], bv[8];
            *(float4*)&av[0] = *(const float4*)&As[kk][ty*8];
            *(float4*)&av[4] = *(const float4*)&As[kk][ty*8+4];
            *(float4*)&bv[0] = *(const float4*)&Bs[kk][tx*8];
            *(float4*)&bv[4] = *(const float4*)&Bs[kk][tx*8+4];
            #pragma unroll
            for (int i = 0; i < 8; i++)
                #pragma unroll
                for (int j = 0; j < 8; j++)
                    acc[i][j] = fmaf(av[i], bv[j], acc[i][j]);
        }
        __syncthreads();
    }
    float* Dp = dst + (size_t)blockIdx.z*sC;
    if (epi == 4) {
        const float* xxz = xx + (size_t)blockIdx.z*Nc;
        float xr[8], xc[8];
        #pragma unroll
        for (int i = 0; i < 8; i++) xr[i] = xxz[row0 + ty*8 + i];
        #pragma unroll
        for (int j = 0; j < 8; j++) xc[j] = xxz[col0 + tx*8 + j];
        #pragma unroll
        for (int i = 0; i < 8; i++) {
            int row = row0 + ty*8 + i;
            float v[8];
            #pragma unroll
            for (int j = 0; j < 8; j++) v[j] = 2.0f*acc[i][j] - xr[i] - xc[j];
            *(float4*)&Dp[(size_t)row*Nc + col0 + tx*8]     = *(float4*)&v[0];
            *(float4*)&Dp[(size_t)row*Nc + col0 + tx*8 + 4] = *(float4*)&v[4];
        }
        if (sym && bx != by) {
            #pragma unroll
            for (int j = 0; j < 8; j++) {
                int col = col0 + tx*8 + j;
                float tv[8];
                #pragma unroll
                for (int i = 0; i < 8; i++) tv[i] = 2.0f*acc[i][j] - xr[i] - xc[j];
                *(float4*)&Dp[(size_t)col*Nc + row0 + ty*8]     = *(float4*)&tv[0];
                *(float4*)&Dp[(size_t)col*Nc + row0 + ty*8 + 4] = *(float4*)&tv[4];
            }
        }
    } else {
        #pragma unroll
        for (int i = 0; i < 8; i++) {
            int row = row0 + ty*8 + i;
            if (row >= M) continue;
            *(float4*)&Dp[(size_t)row*Nc + col0 + tx*8]     = *(float4*)&acc[i][0];
            *(float4*)&Dp[(size_t)row*Nc + col0 + tx*8 + 4] = *(float4*)&acc[i][4];
        }
    }
}

// ------------- top-20 v3: block per row, sort-8/lane + 2-level merge ---------
#define CMPSW(i,j) { if (a[i] < a[j]) { unsigned long long tq = a[i]; a[i] = a[j]; a[j] = tq; } }
__global__ void __launch_bounds__(256) k_topk3(const float* __restrict__ dist) {
    __shared__ unsigned long long sml[8*256];
    __shared__ unsigned long long wtop[8*20];
    int t = threadIdx.x;
    int w = t >> 5, lane = t & 31;
    int bn = blockIdx.x;
    const float* dp = dist + (size_t)bn*NN;
    unsigned long long a[8];
    #pragma unroll
    for (int i = 0; i < 8; i++) {
        int m = w*256 + i*32 + lane;
        unsigned int u = __float_as_uint(dp[m]);
        u ^= ((unsigned int)((int)u >> 31)) | 0x80000000u;   // monotone map
        a[i] = ((unsigned long long)u << 32) | (unsigned int)(2047 - m);
    }
    CMPSW(0,1) CMPSW(2,3) CMPSW(4,5) CMPSW(6,7)
    CMPSW(0,2) CMPSW(1,3) CMPSW(4,6) CMPSW(5,7)
    CMPSW(1,2) CMPSW(5,6) CMPSW(0,4) CMPSW(3,7)
    CMPSW(1,5) CMPSW(2,6)
    CMPSW(1,4) CMPSW(3,6)
    CMPSW(2,4) CMPSW(3,5)
    CMPSW(3,4)
    #pragma unroll
    for (int i = 0; i < 8; i++) sml[i*256 + t] = a[i];
    __syncwarp();
    {
        int pos = 0;
        unsigned long long cur = a[0];
        #pragma unroll
        for (int j = 0; j < 20; j++) {
            unsigned long long mx = cur;
            #pragma unroll
            for (int off = 16; off; off >>= 1) {
                unsigned long long o = __shfl_xor_sync(0xffffffffu, mx, off);
                if (o > mx) mx = o;
            }
            if (lane == 0) wtop[w*20 + j] = mx;
            if (cur == mx) { pos++; cur = (pos < 8) ? sml[pos*256 + t] : 0ull; }
        }
    }
    __syncthreads();
    if (w == 0) {
        int pos = 0;
        unsigned long long cur = (lane < 8) ? wtop[lane*20] : 0ull;
        #pragma unroll
        for (int j = 0; j < 20; j++) {
            unsigned long long mx = cur;
            #pragma unroll
            for (int off = 16; off; off >>= 1) {
                unsigned long long o = __shfl_xor_sync(0xffffffffu, mx, off);
                if (o > mx) mx = o;
            }
            if (lane == 0) g_idx[bn*KKN + j] = 2047 - (int)(mx & 0xffffffffu);
            if (cur == mx && lane < 8) { pos++; cur = (pos < 20) ? wtop[lane*20 + pos] : 0ull; }
        }
    }
}

// -- EdgeConv: coalesced gather + conv + BN sums + fused max/min over k -------
template<int O>
__global__ void k_edgeconv(const float* __restrict__ ft, int Cld, int C,
                           const float* __restrict__ w) {
    __shared__ __align__(16) float ctr[128];
    __shared__ __align__(16) float nd[KKN*128];
    __shared__ int sidx[KKN];
    int bn = blockIdx.x;
    int b = bn >> 11;
    int t = threadIdx.x;
    if (t < KKN) sidx[t] = g_idx[bn*KKN + t];
    for (int e = t; e < C; e += O)
        ctr[e] = ft[(size_t)bn*Cld + e];
    __syncthreads();
    for (int e = t; e < KKN*C; e += O) {
        int kk = e / C, c = e - kk*C;
        nd[e] = ft[((size_t)(b*NN + sidx[kk]))*Cld + c] - ctr[c];
    }
    __syncthreads();

    int o = t;
    float acc[KKN];
    #pragma unroll
    for (int kk = 0; kk < KKN; kk++) acc[kk] = 0.f;
    float base = 0.f;
    const float* wr = w + (size_t)o*2*C;
    if ((C & 3) == 0) {
        for (int c = 0; c < C; c += 4) {
            float4 w1 = *(const float4*)&wr[c];
            float4 w2 = *(const float4*)&wr[C + c];
            float4 ct = *(const float4*)&ctr[c];
            base = fmaf(w2.x, ct.x, fmaf(w2.y, ct.y, fmaf(w2.z, ct.z, fmaf(w2.w, ct.w, base))));
            #pragma unroll
            for (int kk = 0; kk < KKN; kk++) {
                float4 nv = *(const float4*)&nd[kk*C + c];
                acc[kk] = fmaf(w1.x, nv.x, fmaf(w1.y, nv.y,
                          fmaf(w1.z, nv.z, fmaf(w1.w, nv.w, acc[kk]))));
            }
        }
    } else {
        for (int c = 0; c < C; c++) {
            float w1 = wr[c], w2 = wr[C + c], ct = ctr[c];
            base = fmaf(w2, ct, base);
            #pragma unroll
            for (int kk = 0; kk < KKN; kk++) acc[kk] = fmaf(w1, nd[kk*C + c], acc[kk]);
        }
    }
    double s = 0.0, ss = 0.0;
    float mx = -INFINITY, mn = INFINITY;
    #pragma unroll
    for (int kk = 0; kk < KKN; kk++) {
        float v = acc[kk] + base;
        mx = fmaxf(mx, v); mn = fminf(mn, v);
        double vd = (double)v;
        s += vd; ss += vd*vd;
    }
    g_mn[((size_t)bn*O + o)*2]     = mx;
    g_mn[((size_t)bn*O + o)*2 + 1] = mn;
    int bin = bn & (NBIN-1);
    atomicAdd(&g_sumd[o*NBIN + bin], s);
    atomicAdd(&g_ssqd[o*NBIN + bin], ss);
}

// ------------- finalize BN stats (and re-zero bins for the next stage) -------
template<int O>
__global__ void k_finstats() {
    int o = threadIdx.x;
    if (o >= O) return;
    double s = 0.0, ss = 0.0;
    #pragma unroll 8
    for (int i = 0; i < NBIN; i++) {
        s += g_sumd[o*NBIN + i]; ss += g_ssqd[o*NBIN + i];
        g_sumd[o*NBIN + i] = 0.0; g_ssqd[o*NBIN + i] = 0.0;
    }
    const double cnt = (double)BB*NN*KKN;
    double mu = s / cnt;
    double var = ss / cnt - mu*mu;
    g_mu[o] = (float)mu;
    g_rs[o] = rsqrtf((float)var + EPSV);
}

// -- BN normalize + leaky on pre-reduced max/min; writes g_H and next ft ------
// ftNext: row-major [B*N][ldNext] buffer for next stage input (or null)
template<int O>
__global__ void k_bnmax(const float* __restrict__ g, const float* __restrict__ bb,
                        int coff, float* __restrict__ ftNext, int ldNext, int foff) {
    int id = blockIdx.x*256 + threadIdx.x;
    if (id >= BB*NN*O) return;
    int o = id % O, bn = id / O;
    float mu = g_mu[o], rs = g_rs[o];
    float gg = g[o], bv = bb[o];
    float a = rs*gg;
    float y = (a >= 0.f) ? g_mn[(size_t)id*2] : g_mn[(size_t)id*2 + 1];
    float v = (y - mu)*a + bv;
    v = v >= 0.f ? v : 0.2f*v;
    int b = bn >> 11, n = bn & 2047;
    g_H[((size_t)b*512 + coff + o)*NN + n] = v;
    if (ftNext) ftNext[(size_t)bn*ldNext + foff + o] = v;
}

// ---------------- conv5 BN stats (block per channel, double accum) -----------
__global__ void k_stats5() {
    int d = blockIdx.x, t = threadIdx.x;
    double s = 0.0, ss = 0.0;
    for (int b = 0; b < BB; b++) {
        const float* yp = g_y + ((size_t)(b*1024 + d))*NN;
        for (int n = t; n < NN; n += 256) {
            double v = (double)yp[n];
            s += v; ss += v*v;
        }
    }
    __shared__ double sred[8], ssred[8];
    for (int off = 16; off; off >>= 1) {
        s  += __shfl_xor_sync(0xffffffffu, s, off);
        ss += __shfl_xor_sync(0xffffffffu, ss, off);
    }
    if ((t & 31) == 0) { sred[t >> 5] = s; ssred[t >> 5] = ss; }
    __syncthreads();
    if (t == 0) {
        s = 0.0; ss = 0.0;
        for (int i = 0; i < 8; i++) { s += sred[i]; ss += ssred[i]; }
        double mu = s*(1.0/16384.0);
        double var = ss*(1.0/16384.0) - mu*mu;
        g_mu[d] = (float)mu;
        g_rs[d] = rsqrtf((float)var + EPSV);
    }
}

// ---------------- BN+leaky+patch max-pool + cls token ------------------------
__global__ void k_pool(const float* __restrict__ g5, const float* __restrict__ b5,
                       const float* __restrict__ cls) {
    int id = blockIdx.x*256 + threadIdx.x;
    if (id >= BB*DD*PP) return;
    int p = id % PP, d = (id / PP) % DD, b = id / (PP*DD);
    float mu = g_mu[d], r = g_rs[d], gg = g5[d], bv = b5[d];
    const float* yp = g_y + ((size_t)(b*1024 + d))*NN + p*PSZ;
    float mx = -INFINITY;
    #pragma unroll
    for (int s_ = 0; s_ < PSZ; s_++) {
        float v = (yp[s_] - mu)*r*gg + bv;
        v = v >= 0.f ? v : 0.2f*v;
        mx = fmaxf(mx, v);
    }
    g_t[((size_t)(b*TT + 1 + p))*DD + d] = mx;
    if (p == 0) g_t[((size_t)(b*TT))*DD + d] = cls[d];
}

// ---------------- two-pass LN (optional fused +pos residual into t) ----------
__global__ void k_ln(const float* __restrict__ pos, const float* __restrict__ g,
                     const float* __restrict__ b, float* __restrict__ out) {
    int row = blockIdx.x, t = threadIdx.x;
    float* xp = g_t + (size_t)row*DD;
    float v0 = xp[t], v1 = xp[t+256], v2 = xp[t+512], v3 = xp[t+768];
    if (pos) {
        const float* pp = pos + (size_t)row*DD;
        v0 += pp[t]; v1 += pp[t+256]; v2 += pp[t+512]; v3 += pp[t+768];
        xp[t] = v0; xp[t+256] = v1; xp[t+512] = v2; xp[t+768] = v3;
    }
    __shared__ float red[8];
    __shared__ float bc[2];
    float s = v0+v1+v2+v3;
    for (int off = 16; off; off >>= 1) s += __shfl_xor_sync(0xffffffffu, s, off);
    if ((t & 31) == 0) red[t >> 5] = s;
    __syncthreads();
    if (t == 0) {
        s = 0.f;
        for (int i = 0; i < 8; i++) s += red[i];
        bc[0] = s*(1.0f/1024.0f);
    }
    __syncthreads();
    float mu = bc[0];
    float d0 = v0-mu, d1 = v1-mu, d2 = v2-mu, d3 = v3-mu;
    float ss = d0*d0 + d1*d1 + d2*d2 + d3*d3;
    for (int off = 16; off; off >>= 1) ss += __shfl_xor_sync(0xffffffffu, ss, off);
    if ((t & 31) == 0) red[t >> 5] = ss;
    __syncthreads();
    if (t == 0) {
        ss = 0.f;
        for (int i = 0; i < 8; i++) ss += red[i];
        bc[1] = rsqrtf(ss*(1.0f/1024.0f) + EPSV);
    }
    __syncthreads();
    float r = bc[1];
    float* op = out + (size_t)row*DD;
    op[t]     = d0*r*g[t]     + b[t];
    op[t+256] = d1*r*g[t+256] + b[t+256];
    op[t+512] = d2*r*g[t+512] + b[t+512];
    op[t+768] = d3*r*g[t+768] + b[t+768];
}

// block per (b,h); dynamic smem q/k/v[65][64] + probs[65][66]
__global__ void k_attn(const float* __restrict__ qkv, float* __restrict__ z) {
    extern __shared__ float sm[];
    float* q = sm;
    float* k = q + TT*DHEAD;
    float* v = k + TT*DHEAD;
    float* s = v + TT*DHEAD;        // [65][66]
    int b = blockIdx.x >> 3, h = blockIdx.x & 7;
    int t = threadIdx.x;            // 128
    for (int e = t; e < TT*DHEAD; e += 128) {
        int tt = e >> 6, d = e & 63;
        size_t base = ((size_t)(b*TT + tt))*(3*INNER) + h*64 + d;
        q[e] = qkv[base]; k[e] = qkv[base + 512]; v[e] = qkv[base + 1024];
    }
    __syncthreads();
    for (int e = t; e < TT*TT; e += 128) {
        int i = e / TT, j = e - i*TT;
        float acc = 0.f;
        #pragma unroll
        for (int d = 0; d < 64; d++) acc = fmaf(q[i*64+d], k[j*64+d], acc);
        s[i*66 + j] = acc*0.125f;
    }
    __syncthreads();
    int w = t >> 5, lane = t & 31;
    for (int i = w; i < TT; i += 4) {
        float a0 = s[i*66 + lane], a1 = s[i*66 + 32 + lane];
        float a2 = (lane == 0) ? s[i*66 + 64] : -INFINITY;
        float mx = fmaxf(fmaxf(a0, a1), a2);
        for (int off = 16; off; off >>= 1) mx = fmaxf(mx, __shfl_xor_sync(0xffffffffu, mx, off));
        float e0 = expf(a0 - mx), e1 = expf(a1 - mx);
        float e2 = (lane == 0) ? expf(a2 - mx) : 0.f;
        float sum = e0 + e1 + e2;
        for (int off = 16; off; off >>= 1) sum += __shfl_xor_sync(0xffffffffu, sum, off);
        float inv = 1.0f / sum;
        s[i*66 + lane] = e0*inv; s[i*66 + 32 + lane] = e1*inv;
        if (lane == 0) s[i*66 + 64] = e2*inv;
    }
    __syncthreads();
    for (int e = t; e < TT*DHEAD; e += 128) {
        int i = e >> 6, d = e & 63;
        float acc = 0.f;
        for (int j = 0; j < TT; j++) acc = fmaf(s[i*66 + j], v[j*64 + d], acc);
        z[((size_t)(b*TT + i))*INNER + h*64 + d] = acc;
    }
}

__global__ void k_out(float* __restrict__ out) {
    int id = blockIdx.x*256 + threadIdx.x;
    if (id >= BB*PP*DD) return;
    int d = id % DD, p = (id / DD) % PP, b = id / (DD*PP);
    out[id] = g_t[((size_t)(b*TT + 1 + p))*DD + d];
}

// =============================================================================
extern "C" void kernel_launch(void* const* d_in, const int* in_sizes, int n_in,
                              void* d_out, int out_size) {
    const float* x    = (const float*)d_in[0];
    const float* pos  = (const float*)d_in[1];
    const float* w1   = (const float*)d_in[2];
    const float* g1   = (const float*)d_in[3];
    const float* b1   = (const float*)d_in[4];
    const float* w2   = (const float*)d_in[5];
    const float* g2   = (const float*)d_in[6];
    const float* b2   = (const float*)d_in[7];
    const float* w3   = (const float*)d_in[8];
    const float* g3   = (const float*)d_in[9];
    const float* b3   = (const float*)d_in[10];
    const float* w4   = (const float*)d_in[11];
    const float* g4   = (const float*)d_in[12];
    const float* b4   = (const float*)d_in[13];
    const float* w5   = (const float*)d_in[14];
    const float* g5   = (const float*)d_in[15];
    const float* b5   = (const float*)d_in[16];
    const float* cls  = (const float*)d_in[17];
    const float* ln1g = (const float*)d_in[18];
    const float* ln1b = (const float*)d_in[19];
    const float* wqkv = (const float*)d_in[20];
    const float* wout = (const float*)d_in[21];
    const float* bout = (const float*)d_in[22];
    const float* ln2g = (const float*)d_in[23];
    const float* ln2b = (const float*)d_in[24];
    const float* wff1 = (const float*)d_in[25];
    const float* bff1 = (const float*)d_in[26];
    const float* wff2 = (const float*)d_in[27];
    const float* bff2 = (const float*)d_in[28];

    void* p;
    float *h0P, *HP, *xxP, *yP, *ftP, *fbP, *tP, *hnP, *qkvP, *zP, *ffP;
    double *sumdP, *ssqdP;
    cudaGetSymbolAddress(&p, g_h0);    h0P   = (float*)p;
    cudaGetSymbolAddress(&p, g_H);     HP    = (float*)p;
    cudaGetSymbolAddress(&p, g_xx);    xxP   = (float*)p;
    cudaGetSymbolAddress(&p, g_y);     yP    = (float*)p;
    cudaGetSymbolAddress(&p, g_ft);    ftP   = (float*)p;
    cudaGetSymbolAddress(&p, g_fpadB); fbP   = (float*)p;
    cudaGetSymbolAddress(&p, g_sumd);  sumdP = (double*)p;
    cudaGetSymbolAddress(&p, g_ssqd);  ssqdP = (double*)p;
    cudaGetSymbolAddress(&p, g_t);     tP    = (float*)p;
    cudaGetSymbolAddress(&p, g_hn);    hnP   = (float*)p;
    cudaGetSymbolAddress(&p, g_qkv);   qkvP  = (float*)p;
    cudaGetSymbolAddress(&p, g_z);     zP    = (float*)p;
    cudaGetSymbolAddress(&p, g_ff);    ffP   = (float*)p;

    int attn_smem = (3*TT*DHEAD + TT*66) * sizeof(float);
    cudaFuncSetAttribute(k_attn, cudaFuncAttributeMaxDynamicSharedMemorySize, attn_smem);

    k_transpose_x<<<(BB*NN + 255)/256, 256>>>(x);
    cudaMemsetAsync(sumdP, 0, 256*NBIN*sizeof(double));
    cudaMemsetAsync(ssqdP, 0, 256*NBIN*sizeof(double));

    dim3 gDist64(NN/64, NN/64, BB);
    dim3 gDist128(NN/128, NN/128, BB);

    // ---- EdgeConv 1: C=3 -> O=64 ----
    k_xx<<<(BB*NN + 255)/256, 256>>>(h0P, 3, 0, 3);
    k_gemm<<<gDist64, 256>>>(ftP, fbP, nullptr, xxP, yP,
        NN, NN, 16, (long)NN*16, (long)16*NN, (long)NN*NN, 4);
    k_topk3<<<BB*NN, 256>>>(yP);
    k_edgeconv<64><<<BB*NN, 64>>>(ftP, 16, 3, w1);
    k_finstats<64><<<1, 64>>>();
    // x1 -> g_H channels [0,64) and ft rows for stage 2 (ld 64)
    k_bnmax<64><<<(BB*NN*64 + 255)/256, 256>>>(g1, b1, 0, ftP, 64, 0);

    // ---- EdgeConv 2: x1 (C=64) -> O=64 ----
    k_xx<<<(BB*NN + 255)/256, 256>>>(HP, 512, 0, 64);
    k_gemm128<<<gDist128, 256>>>(ftP, HP, xxP, yP,
        NN, NN, 64, (long)NN*64, (long)512*NN, (long)NN*NN, 64, NN, 4, 1);
    k_topk3<<<BB*NN, 256>>>(yP);
    k_edgeconv<64><<<BB*NN, 64>>>(ftP, 64, 64, w2);
    k_finstats<64><<<1, 64>>>();
    // x2 -> g_H channels [64,128) and ft rows for stage 3 (ld 64)
    k_bnmax<64><<<(BB*NN*64 + 255)/256, 256>>>(g2, b2, 64, ftP, 64, 0);

    // ---- EdgeConv 3: x2 (C=64) -> O=128 ----
    k_xx<<<(BB*NN + 255)/256, 256>>>(HP, 512, 64, 64);
    k_gemm128<<<gDist128, 256>>>(ftP, HP + (size_t)64*NN, xxP, yP,
        NN, NN, 64, (long)NN*64, (long)512*NN, (long)NN*NN, 64, NN, 4, 1);
    k_topk3<<<BB*NN, 256>>>(yP);
    k_edgeconv<128><<<BB*NN, 128>>>(ftP, 64, 64, w3);
    k_finstats<128><<<1, 128>>>();
    // x3 -> g_H channels [128,256) and ft rows for stage 4 (ld 128)
    k_bnmax<128><<<(BB*NN*128 + 255)/256, 256>>>(g3, b3, 128, ftP, 128, 0);

    // ---- EdgeConv 4: x3 (C=128) -> O=256 ----
    k_xx<<<(BB*NN + 255)/256, 256>>>(HP, 512, 128, 128);
    k_gemm128<<<gDist128, 256>>>(ftP, HP + (size_t)128*NN, xxP, yP,
        NN, NN, 128, (long)NN*128, (long)512*NN, (long)NN*NN, 128, NN, 4, 1);
    k_topk3<<<BB*NN, 256>>>(yP);
    k_edgeconv<256><<<BB*NN, 256>>>(ftP, 128, 128, w4);
    k_finstats<256><<<1, 256>>>();
    k_bnmax<256><<<(BB*NN*256 + 255)/256, 256>>>(g4, b4, 256, nullptr, 0, 0);

    // ---- conv5: y[b] = w5[1024,512] @ H[b][512,2048] ----
    k_gemm128<<<dim3(NN/128, 1024/128, BB), 256>>>(
        w5, HP, nullptr, yP, 1024, NN, 512,
        0L, (long)512*NN, (long)1024*NN, 512, NN, 0, 0);
    k_stats5<<<1024, 256>>>();
    k_pool<<<(BB*DD*PP + 255)/256, 256>>>(g5, b5, cls);

    // ---- transformer (64x64 k_gemm: max parallelism at M=520) ----
    for (int i = 0; i < DEPTH; i++) {
        k_ln<<<TOK, 256>>>(pos, ln1g + (size_t)i*DD, ln1b + (size_t)i*DD, hnP);
        k_gemm<<<dim3((3*INNER)/64, (TOK + 63)/64, 1), 256>>>(
            hnP, wqkv + (size_t)i*DD*3*INNER, nullptr, nullptr, qkvP,
            TOK, 3*INNER, DD, 0L, 0L, 0L, 0);
        k_attn<<<BB*NHEAD, 128, attn_smem>>>(qkvP, zP);
        k_gemm<<<dim3(DD/64, (TOK + 63)/64, 1), 256>>>(
            zP, wout + (size_t)i*INNER*DD, bout + (size_t)i*DD, nullptr, tP,
            TOK, DD, INNER, 0L, 0L, 0L, 3);
        k_ln<<<TOK, 256>>>(nullptr, ln2g + (size_t)i*DD, ln2b + (size_t)i*DD, hnP);
        k_gemm<<<dim3(MLPD/64, (TOK + 63)/64, 1), 256>>>(
            hnP, wff1 + (size_t)i*DD*MLPD, bff1 + (size_t)i*MLPD, nullptr, ffP,
            TOK, MLPD, DD, 0L, 0L, 0L, 2);
        k_gemm<<<dim3(DD/64, (TOK + 63)/64, 1), 256>>>(
            ffP, wff2 + (size_t)i*MLPD*DD, bff2 + (size_t)i*DD, nullptr, tP,
            TOK, DD, MLPD, 0L, 0L, 0L, 3);
    }

    k_out<<<(BB*PP*DD + 255)/256, 256>>>((float*)d_out);
}

// round 14
// speedup vs baseline: 1.3192x; 1.0935x over previous
#include <cuda_runtime.h>
#include <math.h>

#define BB    8
#define NN    2048
#define KKN   20
#define PP    64
#define PSZ   32
#define DD    1024
#define TT    65
#define TOK   (BB*TT)     // 520
#define INNER 512
#define NHEAD 8
#define DHEAD 64
#define MLPD  2048
#define DEPTH 6
#define EPSV  1e-5f
#define NBIN  64

// ---------------- scratch (static device globals; no runtime allocation) ----
__device__ float  g_h0 [BB*3*NN];                     // transposed xyz [B,3,N]
__device__ float  g_H  [BB*512*NN];                   // concat features [B,512,N]
__device__ float  g_xx[BB*NN];
__device__ int    g_idx[BB*NN*KKN];
__device__ float  g_y [(size_t)BB*NN*KKN*256];        // scratch: dist / conv5 y / split-K partials
__device__ float  g_mn [BB*NN*256*2];                 // per-(bn,o) max/min over k
__device__ float  g_ft [BB*NN*128];                   // row-major features [B*N][Cld]
__device__ float  g_fpadB[BB*16*NN];                  // zero-padded xyz [B,16,N]
__device__ double g_sumd[256*NBIN];
__device__ double g_ssqd[256*NBIN];
__device__ float  g_mu [1024];
__device__ float  g_rs [1024];
__device__ float  g_t  [TOK*DD];
__device__ float  g_hn [TOK*DD];
__device__ float  g_qkv[TOK*3*INNER];
__device__ float  g_z  [TOK*INNER];
__device__ float  g_ff [TOK*MLPD];

// ------- stage 0: transpose x + build padded B operand + conv1 ft rows -------
__global__ void k_transpose_x(const float* __restrict__ x) {
    int id = blockIdx.x*256 + threadIdx.x;
    if (id >= BB*NN) return;
    int b = id / NN, n = id % NN;
    float v[3];
    #pragma unroll
    for (int c = 0; c < 3; c++) {
        v[c] = x[id*3 + c];
        g_h0[(b*3+c)*NN + n] = v[c];
        g_fpadB[(b*16+c)*NN + n] = v[c];
    }
    #pragma unroll
    for (int c = 3; c < 16; c++) g_fpadB[(b*16+c)*NN + n] = 0.f;
    #pragma unroll
    for (int c = 0; c < 16; c++) g_ft[(size_t)id*16 + c] = (c < 3) ? v[c] : 0.f;
}

// ---------------- xx = sum_c x^2 ---------------------------------------------
__global__ void k_xx(const float* __restrict__ src, int Ctot, int coff, int C) {
    int id = blockIdx.x*256 + threadIdx.x;
    if (id >= BB*NN) return;
    int b = id / NN, m = id % NN;
    float s = 0.f;
    for (int c = 0; c < C; c++) {
        float v = src[((size_t)b*Ctot + coff + c)*NN + m];
        s = fmaf(v, v, s);
    }
    g_xx[id] = s;
}

// ---------------- generic tiled fp32 GEMM (64x64), lda-aware -----------------
// epi: 0 plain, 4 dist
__global__ void k_gemm(const float* __restrict__ A, const float* __restrict__ Bm,
                       const float* __restrict__ xx,
                       float* dst,
                       int M, int Nc, int Kc, int lda,
                       long sA, long sB, long sC, int epi) {
    __shared__ __align__(16) float As[16][64];
    __shared__ __align__(16) float Bs[16][64];
    int tid = threadIdx.x;
    int tx = tid & 15, ty = tid >> 4;
    int row0 = blockIdx.y*64, col0 = blockIdx.x*64;
    const float* Ap = A + (size_t)blockIdx.z*sA;
    const float* Bp = Bm + (size_t)blockIdx.z*sB;
    float acc[4][4] = {};
    int r = tid >> 2, kq = tid & 3;
    for (int kt = 0; kt < Kc; kt += 16) {
        float4 a4 = make_float4(0.f, 0.f, 0.f, 0.f);
        int row = row0 + r;
        if (row < M) a4 = *(const float4*)&Ap[(size_t)row*lda + kt + kq*4];
        As[kq*4+0][r] = a4.x; As[kq*4+1][r] = a4.y;
        As[kq*4+2][r] = a4.z; As[kq*4+3][r] = a4.w;
        #pragma unroll
        for (int i = 0; i < 4; i++) {
            int kr = (tid >> 6) + i*4;
            Bs[kr][tid & 63] = Bp[(size_t)(kt + kr)*Nc + col0 + (tid & 63)];
        }
        __syncthreads();
        #pragma unroll
        for (int kk = 0; kk < 16; kk++) {
            float4 a = *(const float4*)&As[kk][ty*4];
            float4 bq = *(const float4*)&Bs[kk][tx*4];
            acc[0][0] = fmaf(a.x, bq.x, acc[0][0]); acc[0][1] = fmaf(a.x, bq.y, acc[0][1]);
            acc[0][2] = fmaf(a.x, bq.z, acc[0][2]); acc[0][3] = fmaf(a.x, bq.w, acc[0][3]);
            acc[1][0] = fmaf(a.y, bq.x, acc[1][0]); acc[1][1] = fmaf(a.y, bq.y, acc[1][1]);
            acc[1][2] = fmaf(a.y, bq.z, acc[1][2]); acc[1][3] = fmaf(a.y, bq.w, acc[1][3]);
            acc[2][0] = fmaf(a.z, bq.x, acc[2][0]); acc[2][1] = fmaf(a.z, bq.y, acc[2][1]);
            acc[2][2] = fmaf(a.z, bq.z, acc[2][2]); acc[2][3] = fmaf(a.z, bq.w, acc[2][3]);
            acc[3][0] = fmaf(a.w, bq.x, acc[3][0]); acc[3][1] = fmaf(a.w, bq.y, acc[3][1]);
            acc[3][2] = fmaf(a.w, bq.z, acc[3][2]); acc[3][3] = fmaf(a.w, bq.w, acc[3][3]);
        }
        __syncthreads();
    }
    float* Dp = dst + (size_t)blockIdx.z*sC;
    const float* xxz = (epi == 4) ? (xx + (size_t)blockIdx.z*Nc) : nullptr;
    #pragma unroll
    for (int i = 0; i < 4; i++) {
        int row = row0 + ty*4 + i;
        if (row >= M) continue;
        #pragma unroll
        for (int j = 0; j < 4; j++) {
            int col = col0 + tx*4 + j;
            float v = acc[i][j];
            if (epi == 4) v = 2.0f*v - xxz[row] - xxz[col];
            Dp[(size_t)row*Nc + col] = v;
        }
    }
}

// ---------------- split-K reduce: sum partials + epilogue --------------------
// mode: 0 plain, 2 gelu(v+bias), 3 v+bias+dst residual
__global__ void k_reduce(const float* __restrict__ part, long sC, int P,
                         const float* __restrict__ bias, float* __restrict__ dst,
                         int Nc, int total, int mode) {
    int id = blockIdx.x*256 + threadIdx.x;
    if (id >= total) return;
    float v = 0.f;
    for (int p = 0; p < P; p++) v += part[(size_t)p*sC + id];
    if (mode >= 2) v += bias[id % Nc];
    if (mode == 2) v = 0.5f*v*(1.0f + erff(v*0.70710678118654752f));
    if (mode == 3) v += dst[id];
    dst[id] = v;
}

// ---------------- 128x128-tile fp32 GEMM (8x8/thread), optional symmetry -----
__global__ void __launch_bounds__(256) k_gemm128(
        const float* __restrict__ A, const float* __restrict__ Bm,
        const float* __restrict__ xx, float* __restrict__ dst,
        int M, int Nc, int Kc,
        long sA, long sB, long sC, int lda, int ldb, int epi, int sym) {
    int bx = blockIdx.x, by = blockIdx.y;
    if (sym && bx < by) return;
    __shared__ __align__(16) float As[16][128];
    __shared__ __align__(16) float Bs[16][128];
    int tid = threadIdx.x;
    int tx = tid & 15, ty = tid >> 4;
    int row0 = by*128, col0 = bx*128;
    const float* Ap = A + (size_t)blockIdx.z*sA;
    const float* Bp = Bm + (size_t)blockIdx.z*sB;
    float acc[8][8] = {};
    int ar = tid >> 1, ak = (tid & 1)*8;
    int bkr = tid >> 4, bc4 = (tid & 15)*8;
    for (int kt = 0; kt < Kc; kt += 16) {
        float4 a0 = make_float4(0.f,0.f,0.f,0.f), a1 = a0;
        int arow = row0 + ar;
        if (arow < M) {
            a0 = *(const float4*)&Ap[(size_t)arow*lda + kt + ak];
            a1 = *(const float4*)&Ap[(size_t)arow*lda + kt + ak + 4];
        }
        As[ak+0][ar] = a0.x; As[ak+1][ar] = a0.y; As[ak+2][ar] = a0.z; As[ak+3][ar] = a0.w;
        As[ak+4][ar] = a1.x; As[ak+5][ar] = a1.y; As[ak+6][ar] = a1.z; As[ak+7][ar] = a1.w;
        *(float4*)&Bs[bkr][bc4]   = *(const float4*)&Bp[(size_t)(kt+bkr)*ldb + col0 + bc4];
        *(float4*)&Bs[bkr][bc4+4] = *(const float4*)&Bp[(size_t)(kt+bkr)*ldb + col0 + bc4 + 4];
        __syncthreads();
        #pragma unroll
        for (int kk = 0; kk < 16; kk++) {
            float av[8], bv[8];
            *(float4*)&av[0] = *(const float4*)&As[kk][ty*8];
            *(float4*)&av[4] = *(const float4*)&As[kk][ty*8+4];
            *(float4*)&bv[0] = *(const float4*)&Bs[kk][tx*8];
            *(float4*)&bv[4] = *(const float4*)&Bs[kk][tx*8+4];
            #pragma unroll
            for (int i = 0; i < 8; i++)
                #pragma unroll
                for (int j = 0; j < 8; j++)
                    acc[i][j] = fmaf(av[i], bv[j], acc[i][j]);
        }
        __syncthreads();
    }
    float* Dp = dst + (size_t)blockIdx.z*sC;
    if (epi == 4) {
        const float* xxz = xx + (size_t)blockIdx.z*Nc;
        float xr[8], xc[8];
        #pragma unroll
        for (int i = 0; i < 8; i++) xr[i] = xxz[row0 + ty*8 + i];
        #pragma unroll
        for (int j = 0; j < 8; j++) xc[j] = xxz[col0 + tx*8 + j];
        #pragma unroll
        for (int i = 0; i < 8; i++) {
            int row = row0 + ty*8 + i;
            float v[8];
            #pragma unroll
            for (int j = 0; j < 8; j++) v[j] = 2.0f*acc[i][j] - xr[i] - xc[j];
            *(float4*)&Dp[(size_t)row*Nc + col0 + tx*8]     = *(float4*)&v[0];
            *(float4*)&Dp[(size_t)row*Nc + col0 + tx*8 + 4] = *(float4*)&v[4];
        }
        if (sym && bx != by) {
            #pragma unroll
            for (int j = 0; j < 8; j++) {
                int col = col0 + tx*8 + j;
                float tv[8];
                #pragma unroll
                for (int i = 0; i < 8; i++) tv[i] = 2.0f*acc[i][j] - xr[i] - xc[j];
                *(float4*)&Dp[(size_t)col*Nc + row0 + ty*8]     = *(float4*)&tv[0];
                *(float4*)&Dp[(size_t)col*Nc + row0 + ty*8 + 4] = *(float4*)&tv[4];
            }
        }
    } else {
        #pragma unroll
        for (int i = 0; i < 8; i++) {
            int row = row0 + ty*8 + i;
            if (row >= M) continue;
            *(float4*)&Dp[(size_t)row*Nc + col0 + tx*8]     = *(float4*)&acc[i][0];
            *(float4*)&Dp[(size_t)row*Nc + col0 + tx*8 + 4] = *(float4*)&acc[i][4];
        }
    }
}

// ------------- top-20 v3: block per row, sort-8/lane + 2-level merge ---------
#define CMPSW(i,j) { if (a[i] < a[j]) { unsigned long long tq = a[i]; a[i] = a[j]; a[j] = tq; } }
__global__ void __launch_bounds__(256) k_topk3(const float* __restrict__ dist) {
    __shared__ unsigned long long sml[8*256];
    __shared__ unsigned long long wtop[8*20];
    int t = threadIdx.x;
    int w = t >> 5, lane = t & 31;
    int bn = blockIdx.x;
    const float* dp = dist + (size_t)bn*NN;
    unsigned long long a[8];
    #pragma unroll
    for (int i = 0; i < 8; i++) {
        int m = w*256 + i*32 + lane;
        unsigned int u = __float_as_uint(dp[m]);
        u ^= ((unsigned int)((int)u >> 31)) | 0x80000000u;   // monotone map
        a[i] = ((unsigned long long)u << 32) | (unsigned int)(2047 - m);
    }
    CMPSW(0,1) CMPSW(2,3) CMPSW(4,5) CMPSW(6,7)
    CMPSW(0,2) CMPSW(1,3) CMPSW(4,6) CMPSW(5,7)
    CMPSW(1,2) CMPSW(5,6) CMPSW(0,4) CMPSW(3,7)
    CMPSW(1,5) CMPSW(2,6)
    CMPSW(1,4) CMPSW(3,6)
    CMPSW(2,4) CMPSW(3,5)
    CMPSW(3,4)
    #pragma unroll
    for (int i = 0; i < 8; i++) sml[i*256 + t] = a[i];
    __syncwarp();
    {
        int pos = 0;
        unsigned long long cur = a[0];
        #pragma unroll
        for (int j = 0; j < 20; j++) {
            unsigned long long mx = cur;
            #pragma unroll
            for (int off = 16; off; off >>= 1) {
                unsigned long long o = __shfl_xor_sync(0xffffffffu, mx, off);
                if (o > mx) mx = o;
            }
            if (lane == 0) wtop[w*20 + j] = mx;
            if (cur == mx) { pos++; cur = (pos < 8) ? sml[pos*256 + t] : 0ull; }
        }
    }
    __syncthreads();
    if (w == 0) {
        int pos = 0;
        unsigned long long cur = (lane < 8) ? wtop[lane*20] : 0ull;
        #pragma unroll
        for (int j = 0; j < 20; j++) {
            unsigned long long mx = cur;
            #pragma unroll
            for (int off = 16; off; off >>= 1) {
                unsigned long long o = __shfl_xor_sync(0xffffffffu, mx, off);
                if (o > mx) mx = o;
            }
            if (lane == 0) g_idx[bn*KKN + j] = 2047 - (int)(mx & 0xffffffffu);
            if (cur == mx && lane < 8) { pos++; cur = (pos < 20) ? wtop[lane*20 + pos] : 0ull; }
        }
    }
}

// -- EdgeConv: coalesced gather + conv + BN sums + fused max/min over k -------
template<int O>
__global__ void k_edgeconv(const float* __restrict__ ft, int Cld, int C,
                           const float* __restrict__ w) {
    __shared__ __align__(16) float ctr[128];
    __shared__ __align__(16) float nd[KKN*128];
    __shared__ int sidx[KKN];
    int bn = blockIdx.x;
    int b = bn >> 11;
    int t = threadIdx.x;
    if (t < KKN) sidx[t] = g_idx[bn*KKN + t];
    for (int e = t; e < C; e += O)
        ctr[e] = ft[(size_t)bn*Cld + e];
    __syncthreads();
    for (int e = t; e < KKN*C; e += O) {
        int kk = e / C, c = e - kk*C;
        nd[e] = ft[((size_t)(b*NN + sidx[kk]))*Cld + c] - ctr[c];
    }
    __syncthreads();

    int o = t;
    float acc[KKN];
    #pragma unroll
    for (int kk = 0; kk < KKN; kk++) acc[kk] = 0.f;
    float base = 0.f;
    const float* wr = w + (size_t)o*2*C;
    if ((C & 3) == 0) {
        for (int c = 0; c < C; c += 4) {
            float4 w1 = *(const float4*)&wr[c];
            float4 w2 = *(const float4*)&wr[C + c];
            float4 ct = *(const float4*)&ctr[c];
            base = fmaf(w2.x, ct.x, fmaf(w2.y, ct.y, fmaf(w2.z, ct.z, fmaf(w2.w, ct.w, base))));
            #pragma unroll
            for (int kk = 0; kk < KKN; kk++) {
                float4 nv = *(const float4*)&nd[kk*C + c];
                acc[kk] = fmaf(w1.x, nv.x, fmaf(w1.y, nv.y,
                          fmaf(w1.z, nv.z, fmaf(w1.w, nv.w, acc[kk]))));
            }
        }
    } else {
        for (int c = 0; c < C; c++) {
            float w1 = wr[c], w2 = wr[C + c], ct = ctr[c];
            base = fmaf(w2, ct, base);
            #pragma unroll
            for (int kk = 0; kk < KKN; kk++) acc[kk] = fmaf(w1, nd[kk*C + c], acc[kk]);
        }
    }
    double s = 0.0, ss = 0.0;
    float mx = -INFINITY, mn = INFINITY;
    #pragma unroll
    for (int kk = 0; kk < KKN; kk++) {
        float v = acc[kk] + base;
        mx = fmaxf(mx, v); mn = fminf(mn, v);
        double vd = (double)v;
        s += vd; ss += vd*vd;
    }
    g_mn[((size_t)bn*O + o)*2]     = mx;
    g_mn[((size_t)bn*O + o)*2 + 1] = mn;
    int bin = bn & (NBIN-1);
    atomicAdd(&g_sumd[o*NBIN + bin], s);
    atomicAdd(&g_ssqd[o*NBIN + bin], ss);
}

// ------------- finalize BN stats (and re-zero bins for the next stage) -------
template<int O>
__global__ void k_finstats() {
    int o = threadIdx.x;
    if (o >= O) return;
    double s = 0.0, ss = 0.0;
    #pragma unroll 8
    for (int i = 0; i < NBIN; i++) {
        s += g_sumd[o*NBIN + i]; ss += g_ssqd[o*NBIN + i];
        g_sumd[o*NBIN + i] = 0.0; g_ssqd[o*NBIN + i] = 0.0;
    }
    const double cnt = (double)BB*NN*KKN;
    double mu = s / cnt;
    double var = ss / cnt - mu*mu;
    g_mu[o] = (float)mu;
    g_rs[o] = rsqrtf((float)var + EPSV);
}

// -- BN normalize + leaky on pre-reduced max/min; writes g_H and next ft ------
template<int O>
__global__ void k_bnmax(const float* __restrict__ g, const float* __restrict__ bb,
                        int coff, float* __restrict__ ftNext, int ldNext, int foff) {
    int id = blockIdx.x*256 + threadIdx.x;
    if (id >= BB*NN*O) return;
    int o = id % O, bn = id / O;
    float mu = g_mu[o], rs = g_rs[o];
    float gg = g[o], bv = bb[o];
    float a = rs*gg;
    float y = (a >= 0.f) ? g_mn[(size_t)id*2] : g_mn[(size_t)id*2 + 1];
    float v = (y - mu)*a + bv;
    v = v >= 0.f ? v : 0.2f*v;
    int b = bn >> 11, n = bn & 2047;
    g_H[((size_t)b*512 + coff + o)*NN + n] = v;
    if (ftNext) ftNext[(size_t)bn*ldNext + foff + o] = v;
}

// ---------------- conv5 BN stats (block per channel, double accum) -----------
__global__ void k_stats5() {
    int d = blockIdx.x, t = threadIdx.x;
    double s = 0.0, ss = 0.0;
    for (int b = 0; b < BB; b++) {
        const float* yp = g_y + ((size_t)(b*1024 + d))*NN;
        for (int n = t; n < NN; n += 256) {
            double v = (double)yp[n];
            s += v; ss += v*v;
        }
    }
    __shared__ double sred[8], ssred[8];
    for (int off = 16; off; off >>= 1) {
        s  += __shfl_xor_sync(0xffffffffu, s, off);
        ss += __shfl_xor_sync(0xffffffffu, ss, off);
    }
    if ((t & 31) == 0) { sred[t >> 5] = s; ssred[t >> 5] = ss; }
    __syncthreads();
    if (t == 0) {
        s = 0.0; ss = 0.0;
        for (int i = 0; i < 8; i++) { s += sred[i]; ss += ssred[i]; }
        double mu = s*(1.0/16384.0);
        double var = ss*(1.0/16384.0) - mu*mu;
        g_mu[d] = (float)mu;
        g_rs[d] = rsqrtf((float)var + EPSV);
    }
}

// ---------------- BN+leaky+patch max-pool + cls token ------------------------
__global__ void k_pool(const float* __restrict__ g5, const float* __restrict__ b5,
                       const float* __restrict__ cls) {
    int id = blockIdx.x*256 + threadIdx.x;
    if (id >= BB*DD*PP) return;
    int p = id % PP, d = (id / PP) % DD, b = id / (PP*DD);
    float mu = g_mu[d], r = g_rs[d], gg = g5[d], bv = b5[d];
    const float* yp = g_y + ((size_t)(b*1024 + d))*NN + p*PSZ;
    float mx = -INFINITY;
    #pragma unroll
    for (int s_ = 0; s_ < PSZ; s_++) {
        float v = (yp[s_] - mu)*r*gg + bv;
        v = v >= 0.f ? v : 0.2f*v;
        mx = fmaxf(mx, v);
    }
    g_t[((size_t)(b*TT + 1 + p))*DD + d] = mx;
    if (p == 0) g_t[((size_t)(b*TT))*DD + d] = cls[d];
}

// ---------------- two-pass LN (optional fused +pos residual into t) ----------
__global__ void k_ln(const float* __restrict__ pos, const float* __restrict__ g,
                     const float* __restrict__ b, float* __restrict__ out) {
    int row = blockIdx.x, t = threadIdx.x;
    float* xp = g_t + (size_t)row*DD;
    float v0 = xp[t], v1 = xp[t+256], v2 = xp[t+512], v3 = xp[t+768];
    if (pos) {
        const float* pp = pos + (size_t)row*DD;
        v0 += pp[t]; v1 += pp[t+256]; v2 += pp[t+512]; v3 += pp[t+768];
        xp[t] = v0; xp[t+256] = v1; xp[t+512] = v2; xp[t+768] = v3;
    }
    __shared__ float red[8];
    __shared__ float bc[2];
    float s = v0+v1+v2+v3;
    for (int off = 16; off; off >>= 1) s += __shfl_xor_sync(0xffffffffu, s, off);
    if ((t & 31) == 0) red[t >> 5] = s;
    __syncthreads();
    if (t == 0) {
        s = 0.f;
        for (int i = 0; i < 8; i++) s += red[i];
        bc[0] = s*(1.0f/1024.0f);
    }
    __syncthreads();
    float mu = bc[0];
    float d0 = v0-mu, d1 = v1-mu, d2 = v2-mu, d3 = v3-mu;
    float ss = d0*d0 + d1*d1 + d2*d2 + d3*d3;
    for (int off = 16; off; off >>= 1) ss += __shfl_xor_sync(0xffffffffu, ss, off);
    if ((t & 31) == 0) red[t >> 5] = ss;
    __syncthreads();
    if (t == 0) {
        ss = 0.f;
        for (int i = 0; i < 8; i++) ss += red[i];
        bc[1] = rsqrtf(ss*(1.0f/1024.0f) + EPSV);
    }
    __syncthreads();
    float r = bc[1];
    float* op = out + (size_t)row*DD;
    op[t]     = d0*r*g[t]     + b[t];
    op[t+256] = d1*r*g[t+256] + b[t+256];
    op[t+512] = d2*r*g[t+512] + b[t+512];
    op[t+768] = d3*r*g[t+768] + b[t+768];
}

// block per (b,h); dynamic smem q/k/v[65][64] + probs[65][66]
__global__ void k_attn(const float* __restrict__ qkv, float* __restrict__ z) {
    extern __shared__ float sm[];
    float* q = sm;
    float* k = q + TT*DHEAD;
    float* v = k + TT*DHEAD;
    float* s = v + TT*DHEAD;        // [65][66]
    int b = blockIdx.x >> 3, h = blockIdx.x & 7;
    int t = threadIdx.x;            // 128
    for (int e = t; e < TT*DHEAD; e += 128) {
        int tt = e >> 6, d = e & 63;
        size_t base = ((size_t)(b*TT + tt))*(3*INNER) + h*64 + d;
        q[e] = qkv[base]; k[e] = qkv[base + 512]; v[e] = qkv[base + 1024];
    }
    __syncthreads();
    for (int e = t; e < TT*TT; e += 128) {
        int i = e / TT, j = e - i*TT;
        float acc = 0.f;
        #pragma unroll
        for (int d = 0; d < 64; d++) acc = fmaf(q[i*64+d], k[j*64+d], acc);
        s[i*66 + j] = acc*0.125f;
    }
    __syncthreads();
    int w = t >> 5, lane = t & 31;
    for (int i = w; i < TT; i += 4) {
        float a0 = s[i*66 + lane], a1 = s[i*66 + 32 + lane];
        float a2 = (lane == 0) ? s[i*66 + 64] : -INFINITY;
        float mx = fmaxf(fmaxf(a0, a1), a2);
        for (int off = 16; off; off >>= 1) mx = fmaxf(mx, __shfl_xor_sync(0xffffffffu, mx, off));
        float e0 = expf(a0 - mx), e1 = expf(a1 - mx);
        float e2 = (lane == 0) ? expf(a2 - mx) : 0.f;
        float sum = e0 + e1 + e2;
        for (int off = 16; off; off >>= 1) sum += __shfl_xor_sync(0xffffffffu, sum, off);
        float inv = 1.0f / sum;
        s[i*66 + lane] = e0*inv; s[i*66 + 32 + lane] = e1*inv;
        if (lane == 0) s[i*66 + 64] = e2*inv;
    }
    __syncthreads();
    for (int e = t; e < TT*DHEAD; e += 128) {
        int i = e >> 6, d = e & 63;
        float acc = 0.f;
        for (int j = 0; j < TT; j++) acc = fmaf(s[i*66 + j], v[j*64 + d], acc);
        z[((size_t)(b*TT + i))*INNER + h*64 + d] = acc;
    }
}

__global__ void k_out(float* __restrict__ out) {
    int id = blockIdx.x*256 + threadIdx.x;
    if (id >= BB*PP*DD) return;
    int d = id % DD, p = (id / DD) % PP, b = id / (DD*PP);
    out[id] = g_t[((size_t)(b*TT + 1 + p))*DD + d];
}

// =============================================================================
extern "C" void kernel_launch(void* const* d_in, const int* in_sizes, int n_in,
                              void* d_out, int out_size) {
    const float* x    = (const float*)d_in[0];
    const float* pos  = (const float*)d_in[1];
    const float* w1   = (const float*)d_in[2];
    const float* g1   = (const float*)d_in[3];
    const float* b1   = (const float*)d_in[4];
    const float* w2   = (const float*)d_in[5];
    const float* g2   = (const float*)d_in[6];
    const float* b2   = (const float*)d_in[7];
    const float* w3   = (const float*)d_in[8];
    const float* g3   = (const float*)d_in[9];
    const float* b3   = (const float*)d_in[10];
    const float* w4   = (const float*)d_in[11];
    const float* g4   = (const float*)d_in[12];
    const float* b4   = (const float*)d_in[13];
    const float* w5   = (const float*)d_in[14];
    const float* g5   = (const float*)d_in[15];
    const float* b5   = (const float*)d_in[16];
    const float* cls  = (const float*)d_in[17];
    const float* ln1g = (const float*)d_in[18];
    const float* ln1b = (const float*)d_in[19];
    const float* wqkv = (const float*)d_in[20];
    const float* wout = (const float*)d_in[21];
    const float* bout = (const float*)d_in[22];
    const float* ln2g = (const float*)d_in[23];
    const float* ln2b = (const float*)d_in[24];
    const float* wff1 = (const float*)d_in[25];
    const float* bff1 = (const float*)d_in[26];
    const float* wff2 = (const float*)d_in[27];
    const float* bff2 = (const float*)d_in[28];

    void* p;
    float *h0P, *HP, *xxP, *yP, *ftP, *fbP, *tP, *hnP, *qkvP, *zP, *ffP;
    double *sumdP, *ssqdP;
    cudaGetSymbolAddress(&p, g_h0);    h0P   = (float*)p;
    cudaGetSymbolAddress(&p, g_H);     HP    = (float*)p;
    cudaGetSymbolAddress(&p, g_xx);    xxP   = (float*)p;
    cudaGetSymbolAddress(&p, g_y);     yP    = (float*)p;
    cudaGetSymbolAddress(&p, g_ft);    ftP   = (float*)p;
    cudaGetSymbolAddress(&p, g_fpadB); fbP   = (float*)p;
    cudaGetSymbolAddress(&p, g_sumd);  sumdP = (double*)p;
    cudaGetSymbolAddress(&p, g_ssqd);  ssqdP = (double*)p;
    cudaGetSymbolAddress(&p, g_t);     tP    = (float*)p;
    cudaGetSymbolAddress(&p, g_hn);    hnP   = (float*)p;
    cudaGetSymbolAddress(&p, g_qkv);   qkvP  = (float*)p;
    cudaGetSymbolAddress(&p, g_z);     zP    = (float*)p;
    cudaGetSymbolAddress(&p, g_ff);    ffP   = (float*)p;

    int attn_smem = (3*TT*DHEAD + TT*66) * sizeof(float);
    cudaFuncSetAttribute(k_attn, cudaFuncAttributeMaxDynamicSharedMemorySize, attn_smem);

    k_transpose_x<<<(BB*NN + 255)/256, 256>>>(x);
    cudaMemsetAsync(sumdP, 0, 256*NBIN*sizeof(double));
    cudaMemsetAsync(ssqdP, 0, 256*NBIN*sizeof(double));

    dim3 gDist64(NN/64, NN/64, BB);
    dim3 gDist128(NN/128, NN/128, BB);

    // ---- EdgeConv 1: C=3 -> O=64 ----
    k_xx<<<(BB*NN + 255)/256, 256>>>(h0P, 3, 0, 3);
    k_gemm<<<gDist64, 256>>>(ftP, fbP, xxP, yP,
        NN, NN, 16, 16, (long)NN*16, (long)16*NN, (long)NN*NN, 4);
    k_topk3<<<BB*NN, 256>>>(yP);
    k_edgeconv<64><<<BB*NN, 64>>>(ftP, 16, 3, w1);
    k_finstats<64><<<1, 64>>>();
    k_bnmax<64><<<(BB*NN*64 + 255)/256, 256>>>(g1, b1, 0, ftP, 64, 0);

    // ---- EdgeConv 2: x1 (C=64) -> O=64 ----
    k_xx<<<(BB*NN + 255)/256, 256>>>(HP, 512, 0, 64);
    k_gemm128<<<gDist128, 256>>>(ftP, HP, xxP, yP,
        NN, NN, 64, (long)NN*64, (long)512*NN, (long)NN*NN, 64, NN, 4, 1);
    k_topk3<<<BB*NN, 256>>>(yP);
    k_edgeconv<64><<<BB*NN, 64>>>(ftP, 64, 64, w2);
    k_finstats<64><<<1, 64>>>();
    k_bnmax<64><<<(BB*NN*64 + 255)/256, 256>>>(g2, b2, 64, ftP, 64, 0);

    // ---- EdgeConv 3: x2 (C=64) -> O=128 ----
    k_xx<<<(BB*NN + 255)/256, 256>>>(HP, 512, 64, 64);
    k_gemm128<<<gDist128, 256>>>(ftP, HP + (size_t)64*NN, xxP, yP,
        NN, NN, 64, (long)NN*64, (long)512*NN, (long)NN*NN, 64, NN, 4, 1);
    k_topk3<<<BB*NN, 256>>>(yP);
    k_edgeconv<128><<<BB*NN, 128>>>(ftP, 64, 64, w3);
    k_finstats<128><<<1, 128>>>();
    k_bnmax<128><<<(BB*NN*128 + 255)/256, 256>>>(g3, b3, 128, ftP, 128, 0);

    // ---- EdgeConv 4: x3 (C=128) -> O=256 ----
    k_xx<<<(BB*NN + 255)/256, 256>>>(HP, 512, 128, 128);
    k_gemm128<<<gDist128, 256>>>(ftP, HP + (size_t)128*NN, xxP, yP,
        NN, NN, 128, (long)NN*128, (long)512*NN, (long)NN*NN, 128, NN, 4, 1);
    k_topk3<<<BB*NN, 256>>>(yP);
    k_edgeconv<256><<<BB*NN, 256>>>(ftP, 128, 128, w4);
    k_finstats<256><<<1, 256>>>();
    k_bnmax<256><<<(BB*NN*256 + 255)/256, 256>>>(g4, b4, 256, nullptr, 0, 0);

    // ---- conv5: y[b] = w5[1024,512] @ H[b][512,2048] ----
    k_gemm128<<<dim3(NN/128, 1024/128, BB), 256>>>(
        w5, HP, nullptr, yP, 1024, NN, 512,
        0L, (long)512*NN, (long)1024*NN, 512, NN, 0, 0);
    k_stats5<<<1024, 256>>>();
    k_pool<<<(BB*DD*PP + 255)/256, 256>>>(g5, b5, cls);

    // ---- transformer: split-K partial GEMMs + reduce epilogues ----
    int mrows = (TOK + 63)/64;   // 9
    for (int i = 0; i < DEPTH; i++) {
        k_ln<<<TOK, 256>>>(pos, ln1g + (size_t)i*DD, ln1b + (size_t)i*DD, hnP);
        // qkv: 520x1536, K=1024 split 2
        k_gemm<<<dim3((3*INNER)/64, mrows, 2), 256>>>(
            hnP, wqkv + (size_t)i*DD*3*INNER, nullptr, yP,
            TOK, 3*INNER, 512, DD, 512L, (long)512*3*INNER, (long)TOK*3*INNER, 0);
        k_reduce<<<(TOK*3*INNER + 255)/256, 256>>>(
            yP, (long)TOK*3*INNER, 2, nullptr, qkvP, 3*INNER, TOK*3*INNER, 0);
        k_attn<<<BB*NHEAD, 128, attn_smem>>>(qkvP, zP);
        // out: 520x1024, K=512 split 2
        k_gemm<<<dim3(DD/64, mrows, 2), 256>>>(
            zP, wout + (size_t)i*INNER*DD, nullptr, yP,
            TOK, DD, 256, INNER, 256L, (long)256*DD, (long)TOK*DD, 0);
        k_reduce<<<(TOK*DD + 255)/256, 256>>>(
            yP, (long)TOK*DD, 2, bout + (size_t)i*DD, tP, DD, TOK*DD, 3);
        k_ln<<<TOK, 256>>>(nullptr, ln2g + (size_t)i*DD, ln2b + (size_t)i*DD, hnP);
        // ff1: 520x2048, K=1024 split 2, gelu
        k_gemm<<<dim3(MLPD/64, mrows, 2), 256>>>(
            hnP, wff1 + (size_t)i*DD*MLPD, nullptr, yP,
            TOK, MLPD, 512, DD, 512L, (long)512*MLPD, (long)TOK*MLPD, 0);
        k_reduce<<<(TOK*MLPD + 255)/256, 256>>>(
            yP, (long)TOK*MLPD, 2, bff1 + (size_t)i*MLPD, ffP, MLPD, TOK*MLPD, 2);
        // ff2: 520x1024, K=2048 split 4, residual
        k_gemm<<<dim3(DD/64, mrows, 4), 256>>>(
            ffP, wff2 + (size_t)i*MLPD*DD, nullptr, yP,
            TOK, DD, 512, MLPD, 512L, (long)512*DD, (long)TOK*DD, 0);
        k_reduce<<<(TOK*DD + 255)/256, 256>>>(
            yP, (long)TOK*DD, 4, bff2 + (size_t)i*DD, tP, DD, TOK*DD, 3);
    }

    k_out<<<(BB*PP*DD + 255)/256, 256>>>((float*)d_out);
}

// round 16
// speedup vs baseline: 1.6581x; 1.2569x over previous
#include <cuda_runtime.h>
#include <math.h>

#define BB    8
#define NN    2048
#define KKN   20
#define PP    64
#define PSZ   32
#define DD    1024
#define TT    65
#define TOK   (BB*TT)     // 520
#define INNER 512
#define NHEAD 8
#define DHEAD 64
#define MLPD  2048
#define DEPTH 6
#define EPSV  1e-5f
#define NBIN  64

// ---------------- scratch (static device globals; no runtime allocation) ----
__device__ float  g_h0 [BB*3*NN];                     // transposed xyz [B,3,N]
__device__ float  g_H  [BB*512*NN];                   // concat features [B,512,N]
__device__ float  g_xx[BB*NN];
__device__ int    g_idx[BB*NN*KKN];
__device__ float  g_y [(size_t)BB*NN*KKN*256];        // scratch: dist / conv5 y / split-K partials / vu
__device__ float  g_mn [BB*NN*256*2];                 // per-(bn,o) max/min over k
__device__ float  g_ft [BB*NN*128];                   // row-major features [B*N][Cld]
__device__ float  g_fpadB[BB*16*NN];                  // zero-padded xyz [B,16,N]
__device__ float  g_wc [128*512];                     // concatenated transposed weights
__device__ double g_sumd[256*NBIN];
__device__ double g_ssqd[256*NBIN];
__device__ float  g_mu [1024];
__device__ float  g_rs [1024];
__device__ float  g_t  [TOK*DD];
__device__ float  g_hn [TOK*DD];
__device__ float  g_qkv[TOK*3*INNER];
__device__ float  g_z  [TOK*INNER];
__device__ float  g_ff [TOK*MLPD];

// ------- stage 0: transpose x + build padded B operand + conv1 ft rows -------
__global__ void k_transpose_x(const float* __restrict__ x) {
    int id = blockIdx.x*256 + threadIdx.x;
    if (id >= BB*NN) return;
    int b = id / NN, n = id % NN;
    float v[3];
    #pragma unroll
    for (int c = 0; c < 3; c++) {
        v[c] = x[id*3 + c];
        g_h0[(b*3+c)*NN + n] = v[c];
        g_fpadB[(b*16+c)*NN + n] = v[c];
    }
    #pragma unroll
    for (int c = 3; c < 16; c++) g_fpadB[(b*16+c)*NN + n] = 0.f;
    #pragma unroll
    for (int c = 0; c < 16; c++) g_ft[(size_t)id*16 + c] = (c < 3) ? v[c] : 0.f;
}

// ---------------- xx = sum_c x^2 ---------------------------------------------
__global__ void k_xx(const float* __restrict__ src, int Ctot, int coff, int C) {
    int id = blockIdx.x*256 + threadIdx.x;
    if (id >= BB*NN) return;
    int b = id / NN, m = id % NN;
    float s = 0.f;
    for (int c = 0; c < C; c++) {
        float v = src[((size_t)b*Ctot + coff + c)*NN + m];
        s = fmaf(v, v, s);
    }
    g_xx[id] = s;
}

// --------- build wcat[Kpad][2O]: cols [0,O)=w1^T, [O,2O)=(w2-w1)^T ----------
__global__ void k_wcat(const float* __restrict__ w, int C, int Kpad, int O,
                       float* __restrict__ wc) {
    int id = blockIdx.x*256 + threadIdx.x;
    if (id >= Kpad*2*O) return;
    int col = id % (2*O), c = id / (2*O);
    float val = 0.f;
    if (c < C) {
        int o = (col < O) ? col : col - O;
        float a = w[(size_t)o*2*C + c];
        val = (col < O) ? a : (w[(size_t)o*2*C + C + c] - a);
    }
    wc[id] = val;
}

// ---------------- generic tiled fp32 GEMM (64x64), lda-aware -----------------
// epi: 0 plain, 4 dist
__global__ void k_gemm(const float* __restrict__ A, const float* __restrict__ Bm,
                       const float* __restrict__ xx,
                       float* dst,
                       int M, int Nc, int Kc, int lda,
                       long sA, long sB, long sC, int epi) {
    __shared__ __align__(16) float As[16][64];
    __shared__ __align__(16) float Bs[16][64];
    int tid = threadIdx.x;
    int tx = tid & 15, ty = tid >> 4;
    int row0 = blockIdx.y*64, col0 = blockIdx.x*64;
    const float* Ap = A + (size_t)blockIdx.z*sA;
    const float* Bp = Bm + (size_t)blockIdx.z*sB;
    float acc[4][4] = {};
    int r = tid >> 2, kq = tid & 3;
    for (int kt = 0; kt < Kc; kt += 16) {
        float4 a4 = make_float4(0.f, 0.f, 0.f, 0.f);
        int row = row0 + r;
        if (row < M) a4 = *(const float4*)&Ap[(size_t)row*lda + kt + kq*4];
        As[kq*4+0][r] = a4.x; As[kq*4+1][r] = a4.y;
        As[kq*4+2][r] = a4.z; As[kq*4+3][r] = a4.w;
        #pragma unroll
        for (int i = 0; i < 4; i++) {
            int kr = (tid >> 6) + i*4;
            Bs[kr][tid & 63] = Bp[(size_t)(kt + kr)*Nc + col0 + (tid & 63)];
        }
        __syncthreads();
        #pragma unroll
        for (int kk = 0; kk < 16; kk++) {
            float4 a = *(const float4*)&As[kk][ty*4];
            float4 bq = *(const float4*)&Bs[kk][tx*4];
            acc[0][0] = fmaf(a.x, bq.x, acc[0][0]); acc[0][1] = fmaf(a.x, bq.y, acc[0][1]);
            acc[0][2] = fmaf(a.x, bq.z, acc[0][2]); acc[0][3] = fmaf(a.x, bq.w, acc[0][3]);
            acc[1][0] = fmaf(a.y, bq.x, acc[1][0]); acc[1][1] = fmaf(a.y, bq.y, acc[1][1]);
            acc[1][2] = fmaf(a.y, bq.z, acc[1][2]); acc[1][3] = fmaf(a.y, bq.w, acc[1][3]);
            acc[2][0] = fmaf(a.z, bq.x, acc[2][0]); acc[2][1] = fmaf(a.z, bq.y, acc[2][1]);
            acc[2][2] = fmaf(a.z, bq.z, acc[2][2]); acc[2][3] = fmaf(a.z, bq.w, acc[2][3]);
            acc[3][0] = fmaf(a.w, bq.x, acc[3][0]); acc[3][1] = fmaf(a.w, bq.y, acc[3][1]);
            acc[3][2] = fmaf(a.w, bq.z, acc[3][2]); acc[3][3] = fmaf(a.w, bq.w, acc[3][3]);
        }
        __syncthreads();
    }
    float* Dp = dst + (size_t)blockIdx.z*sC;
    const float* xxz = (epi == 4) ? (xx + (size_t)blockIdx.z*Nc) : nullptr;
    #pragma unroll
    for (int i = 0; i < 4; i++) {
        int row = row0 + ty*4 + i;
        if (row >= M) continue;
        #pragma unroll
        for (int j = 0; j < 4; j++) {
            int col = col0 + tx*4 + j;
            float v = acc[i][j];
            if (epi == 4) v = 2.0f*v - xxz[row] - xxz[col];
            Dp[(size_t)row*Nc + col] = v;
        }
    }
}

// ---------------- split-K reduce: sum partials + epilogue --------------------
// mode: 0 plain, 2 gelu(v+bias), 3 v+bias+dst residual
__global__ void k_reduce(const float* __restrict__ part, long sC, int P,
                         const float* __restrict__ bias, float* __restrict__ dst,
                         int Nc, int total, int mode) {
    int id = blockIdx.x*256 + threadIdx.x;
    if (id >= total) return;
    float v = 0.f;
    for (int p = 0; p < P; p++) v += part[(size_t)p*sC + id];
    if (mode >= 2) v += bias[id % Nc];
    if (mode == 2) v = 0.5f*v*(1.0f + erff(v*0.70710678118654752f));
    if (mode == 3) v += dst[id];
    dst[id] = v;
}

// ---------------- 128x128-tile fp32 GEMM (8x8/thread), optional symmetry -----
__global__ void __launch_bounds__(256) k_gemm128(
        const float* __restrict__ A, const float* __restrict__ Bm,
        const float* __restrict__ xx, float* __restrict__ dst,
        int M, int Nc, int Kc,
        long sA, long sB, long sC, int lda, int ldb, int epi, int sym) {
    int bx = blockIdx.x, by = blockIdx.y;
    if (sym && bx < by) return;
    __shared__ __align__(16) float As[16][128];
    __shared__ __align__(16) float Bs[16][128];
    int tid = threadIdx.x;
    int tx = tid & 15, ty = tid >> 4;
    int row0 = by*128, col0 = bx*128;
    const float* Ap = A + (size_t)blockIdx.z*sA;
    const float* Bp = Bm + (size_t)blockIdx.z*sB;
    float acc[8][8] = {};
    int ar = tid >> 1, ak = (tid & 1)*8;
    int bkr = tid >> 4, bc4 = (tid & 15)*8;
    for (int kt = 0; kt < Kc; kt += 16) {
        float4 a0 = make_float4(0.f,0.f,0.f,0.f), a1 = a0;
        int arow = row0 + ar;
        if (arow < M) {
            a0 = *(const float4*)&Ap[(size_t)arow*lda + kt + ak];
            a1 = *(const float4*)&Ap[(size_t)arow*lda + kt + ak + 4];
        }
        As[ak+0][ar] = a0.x; As[ak+1][ar] = a0.y; As[ak+2][ar] = a0.z; As[ak+3][ar] = a0.w;
        As[ak+4][ar] = a1.x; As[ak+5][ar] = a1.y; As[ak+6][ar] = a1.z; As[ak+7][ar] = a1.w;
        *(float4*)&Bs[bkr][bc4]   = *(const float4*)&Bp[(size_t)(kt+bkr)*ldb + col0 + bc4];
        *(float4*)&Bs[bkr][bc4+4] = *(const float4*)&Bp[(size_t)(kt+bkr)*ldb + col0 + bc4 + 4];
        __syncthreads();
        #pragma unroll
        for (int kk = 0; kk < 16; kk++) {
            float av[8], bv[8];
            *(float4*)&av[0] = *(const float4*)&As[kk][ty*8];
            *(float4*)&av[4] = *(const float4*)&As[kk][ty*8+4];
            *(float4*)&bv[0] = *(const float4*)&Bs[kk][tx*8];
            *(float4*)&bv[4] = *(const float4*)&Bs[kk][tx*8+4];
            #pragma unroll
            for (int i = 0; i < 8; i++)
                #pragma unroll
                for (int j = 0; j < 8; j++)
                    acc[i][j] = fmaf(av[i], bv[j], acc[i][j]);
        }
        __syncthreads();
    }
    float* Dp = dst + (size_t)blockIdx.z*sC;
    if (epi == 4) {
        const float* xxz = xx + (size_t)blockIdx.z*Nc;
        float xr[8], xc[8];
        #pragma unroll
        for (int i = 0; i < 8; i++) xr[i] = xxz[row0 + ty*8 + i];
        #pragma unroll
        for (int j = 0; j < 8; j++) xc[j] = xxz[col0 + tx*8 + j];
        #pragma unroll
        for (int i = 0; i < 8; i++) {
            int row = row0 + ty*8 + i;
            float v[8];
            #pragma unroll
            for (int j = 0; j < 8; j++) v[j] = 2.0f*acc[i][j] - xr[i] - xc[j];
            *(float4*)&Dp[(size_t)row*Nc + col0 + tx*8]     = *(float4*)&v[0];
            *(float4*)&Dp[(size_t)row*Nc + col0 + tx*8 + 4] = *(float4*)&v[4];
        }
        if (sym && bx != by) {
            #pragma unroll
            for (int j = 0; j < 8; j++) {
                int col = col0 + tx*8 + j;
                float tv[8];
                #pragma unroll
                for (int i = 0; i < 8; i++) tv[i] = 2.0f*acc[i][j] - xr[i] - xc[j];
                *(float4*)&Dp[(size_t)col*Nc + row0 + ty*8]     = *(float4*)&tv[0];
                *(float4*)&Dp[(size_t)col*Nc + row0 + ty*8 + 4] = *(float4*)&tv[4];
            }
        }
    } else {
        #pragma unroll
        for (int i = 0; i < 8; i++) {
            int row = row0 + ty*8 + i;
            if (row >= M) continue;
            *(float4*)&Dp[(size_t)row*Nc + col0 + tx*8]     = *(float4*)&acc[i][0];
            *(float4*)&Dp[(size_t)row*Nc + col0 + tx*8 + 4] = *(float4*)&acc[i][4];
        }
    }
}

// ------------- top-20 v3: block per row, sort-8/lane + 2-level merge ---------
#define CMPSW(i,j) { if (a[i] < a[j]) { unsigned long long tq = a[i]; a[i] = a[j]; a[j] = tq; } }
__global__ void __launch_bounds__(256) k_topk3(const float* __restrict__ dist) {
    __shared__ unsigned long long sml[8*256];
    __shared__ unsigned long long wtop[8*20];
    int t = threadIdx.x;
    int w = t >> 5, lane = t & 31;
    int bn = blockIdx.x;
    const float* dp = dist + (size_t)bn*NN;
    unsigned long long a[8];
    #pragma unroll
    for (int i = 0; i < 8; i++) {
        int m = w*256 + i*32 + lane;
        unsigned int u = __float_as_uint(dp[m]);
        u ^= ((unsigned int)((int)u >> 31)) | 0x80000000u;   // monotone map
        a[i] = ((unsigned long long)u << 32) | (unsigned int)(2047 - m);
    }
    CMPSW(0,1) CMPSW(2,3) CMPSW(4,5) CMPSW(6,7)
    CMPSW(0,2) CMPSW(1,3) CMPSW(4,6) CMPSW(5,7)
    CMPSW(1,2) CMPSW(5,6) CMPSW(0,4) CMPSW(3,7)
    CMPSW(1,5) CMPSW(2,6)
    CMPSW(1,4) CMPSW(3,6)
    CMPSW(2,4) CMPSW(3,5)
    CMPSW(3,4)
    #pragma unroll
    for (int i = 0; i < 8; i++) sml[i*256 + t] = a[i];
    __syncwarp();
    {
        int pos = 0;
        unsigned long long cur = a[0];
        #pragma unroll
        for (int j = 0; j < 20; j++) {
            unsigned long long mx = cur;
            #pragma unroll
            for (int off = 16; off; off >>= 1) {
                unsigned long long o = __shfl_xor_sync(0xffffffffu, mx, off);
                if (o > mx) mx = o;
            }
            if (lane == 0) wtop[w*20 + j] = mx;
            if (cur == mx) { pos++; cur = (pos < 8) ? sml[pos*256 + t] : 0ull; }
        }
    }
    __syncthreads();
    if (w == 0) {
        int pos = 0;
        unsigned long long cur = (lane < 8) ? wtop[lane*20] : 0ull;
        #pragma unroll
        for (int j = 0; j < 20; j++) {
            unsigned long long mx = cur;
            #pragma unroll
            for (int off = 16; off; off >>= 1) {
                unsigned long long o = __shfl_xor_sync(0xffffffffu, mx, off);
                if (o > mx) mx = o;
            }
            if (lane == 0) g_idx[bn*KKN + j] = 2047 - (int)(mx & 0xffffffffu);
            if (cur == mx && lane < 8) { pos++; cur = (pos < 20) ? wtop[lane*20 + pos] : 0ull; }
        }
    }
}

// -- EdgeConv v2: gather precomputed per-point projections, max/min + stats ---
// vu: [B*N][2O]  cols [0,O)=v=w1·ft,  [O,2O)=u=(w2-w1)·ft
template<int O>
__global__ void __launch_bounds__(256) k_edgemax(const float* __restrict__ vu) {
    constexpr int G = 256/O;
    __shared__ int sidx[G][KKN];
    int bn0 = blockIdx.x*G;
    int t = threadIdx.x;
    for (int e = t; e < G*KKN; e += 256) {
        int g = e / KKN, kk = e % KKN;
        sidx[g][kk] = g_idx[(bn0+g)*KKN + kk];
    }
    __syncthreads();
    int g = t / O, o = t % O;
    int bn = bn0 + g, b = bn >> 11;
    float u = vu[(size_t)bn*(2*O) + O + o];
    double s = 0.0, ss = 0.0;
    float mx = -INFINITY, mn = INFINITY;
    #pragma unroll
    for (int kk = 0; kk < KKN; kk++) {
        float v = vu[((size_t)(b*NN + sidx[g][kk]))*(2*O) + o] + u;
        mx = fmaxf(mx, v); mn = fminf(mn, v);
        double vd = (double)v; s += vd; ss += vd*vd;
    }
    g_mn[((size_t)bn*O + o)*2]     = mx;
    g_mn[((size_t)bn*O + o)*2 + 1] = mn;
    int bin = bn & (NBIN-1);
    atomicAdd(&g_sumd[o*NBIN + bin], s);
    atomicAdd(&g_ssqd[o*NBIN + bin], ss);
}

// ------------- finalize BN stats (and re-zero bins for the next stage) -------
template<int O>
__global__ void k_finstats() {
    int o = threadIdx.x;
    if (o >= O) return;
    double s = 0.0, ss = 0.0;
    #pragma unroll 8
    for (int i = 0; i < NBIN; i++) {
        s += g_sumd[o*NBIN + i]; ss += g_ssqd[o*NBIN + i];
        g_sumd[o*NBIN + i] = 0.0; g_ssqd[o*NBIN + i] = 0.0;
    }
    const double cnt = (double)BB*NN*KKN;
    double mu = s / cnt;
    double var = ss / cnt - mu*mu;
    g_mu[o] = (float)mu;
    g_rs[o] = rsqrtf((float)var + EPSV);
}

// -- BN normalize + leaky on pre-reduced max/min; writes g_H and next ft ------
template<int O>
__global__ void k_bnmax(const float* __restrict__ g, const float* __restrict__ bb,
                        int coff, float* __restrict__ ftNext, int ldNext, int foff) {
    int id = blockIdx.x*256 + threadIdx.x;
    if (id >= BB*NN*O) return;
    int o = id % O, bn = id / O;
    float mu = g_mu[o], rs = g_rs[o];
    float gg = g[o], bv = bb[o];
    float a = rs*gg;
    float y = (a >= 0.f) ? g_mn[(size_t)id*2] : g_mn[(size_t)id*2 + 1];
    float v = (y - mu)*a + bv;
    v = v >= 0.f ? v : 0.2f*v;
    int b = bn >> 11, n = bn & 2047;
    g_H[((size_t)b*512 + coff + o)*NN + n] = v;
    if (ftNext) ftNext[(size_t)bn*ldNext + foff + o] = v;
}

// ---------------- conv5 BN stats (block per channel, double accum) -----------
__global__ void k_stats5() {
    int d = blockIdx.x, t = threadIdx.x;
    double s = 0.0, ss = 0.0;
    for (int b = 0; b < BB; b++) {
        const float* yp = g_y + ((size_t)(b*1024 + d))*NN;
        for (int n = t; n < NN; n += 256) {
            double v = (double)yp[n];
            s += v; ss += v*v;
        }
    }
    __shared__ double sred[8], ssred[8];
    for (int off = 16; off; off >>= 1) {
        s  += __shfl_xor_sync(0xffffffffu, s, off);
        ss += __shfl_xor_sync(0xffffffffu, ss, off);
    }
    if ((t & 31) == 0) { sred[t >> 5] = s; ssred[t >> 5] = ss; }
    __syncthreads();
    if (t == 0) {
        s = 0.0; ss = 0.0;
        for (int i = 0; i < 8; i++) { s += sred[i]; ss += ssred[i]; }
        double mu = s*(1.0/16384.0);
        double var = ss*(1.0/16384.0) - mu*mu;
        g_mu[d] = (float)mu;
        g_rs[d] = rsqrtf((float)var + EPSV);
    }
}

// ---------------- BN+leaky+patch max-pool + cls token ------------------------
__global__ void k_pool(const float* __restrict__ g5, const float* __restrict__ b5,
                       const float* __restrict__ cls) {
    int id = blockIdx.x*256 + threadIdx.x;
    if (id >= BB*DD*PP) return;
    int p = id % PP, d = (id / PP) % DD, b = id / (PP*DD);
    float mu = g_mu[d], r = g_rs[d], gg = g5[d], bv = b5[d];
    const float* yp = g_y + ((size_t)(b*1024 + d))*NN + p*PSZ;
    float mx = -INFINITY;
    #pragma unroll
    for (int s_ = 0; s_ < PSZ; s_++) {
        float v = (yp[s_] - mu)*r*gg + bv;
        v = v >= 0.f ? v : 0.2f*v;
        mx = fmaxf(mx, v);
    }
    g_t[((size_t)(b*TT + 1 + p))*DD + d] = mx;
    if (p == 0) g_t[((size_t)(b*TT))*DD + d] = cls[d];
}

// ---------------- two-pass LN (optional fused +pos residual into t) ----------
__global__ void k_ln(const float* __restrict__ pos, const float* __restrict__ g,
                     const float* __restrict__ b, float* __restrict__ out) {
    int row = blockIdx.x, t = threadIdx.x;
    float* xp = g_t + (size_t)row*DD;
    float v0 = xp[t], v1 = xp[t+256], v2 = xp[t+512], v3 = xp[t+768];
    if (pos) {
        const float* pp = pos + (size_t)row*DD;
        v0 += pp[t]; v1 += pp[t+256]; v2 += pp[t+512]; v3 += pp[t+768];
        xp[t] = v0; xp[t+256] = v1; xp[t+512] = v2; xp[t+768] = v3;
    }
    __shared__ float red[8];
    __shared__ float bc[2];
    float s = v0+v1+v2+v3;
    for (int off = 16; off; off >>= 1) s += __shfl_xor_sync(0xffffffffu, s, off);
    if ((t & 31) == 0) red[t >> 5] = s;
    __syncthreads();
    if (t == 0) {
        s = 0.f;
        for (int i = 0; i < 8; i++) s += red[i];
        bc[0] = s*(1.0f/1024.0f);
    }
    __syncthreads();
    float mu = bc[0];
    float d0 = v0-mu, d1 = v1-mu, d2 = v2-mu, d3 = v3-mu;
    float ss = d0*d0 + d1*d1 + d2*d2 + d3*d3;
    for (int off = 16; off; off >>= 1) ss += __shfl_xor_sync(0xffffffffu, ss, off);
    if ((t & 31) == 0) red[t >> 5] = ss;
    __syncthreads();
    if (t == 0) {
        ss = 0.f;
        for (int i = 0; i < 8; i++) ss += red[i];
        bc[1] = rsqrtf(ss*(1.0f/1024.0f) + EPSV);
    }
    __syncthreads();
    float r = bc[1];
    float* op = out + (size_t)row*DD;
    op[t]     = d0*r*g[t]     + b[t];
    op[t+256] = d1*r*g[t+256] + b[t+256];
    op[t+512] = d2*r*g[t+512] + b[t+512];
    op[t+768] = d3*r*g[t+768] + b[t+768];
}

// block per (b,h); dynamic smem q/k/v[65][64] + probs[65][66]
__global__ void k_attn(const float* __restrict__ qkv, float* __restrict__ z) {
    extern __shared__ float sm[];
    float* q = sm;
    float* k = q + TT*DHEAD;
    float* v = k + TT*DHEAD;
    float* s = v + TT*DHEAD;        // [65][66]
    int b = blockIdx.x >> 3, h = blockIdx.x & 7;
    int t = threadIdx.x;            // 128
    for (int e = t; e < TT*DHEAD; e += 128) {
        int tt = e >> 6, d = e & 63;
        size_t base = ((size_t)(b*TT + tt))*(3*INNER) + h*64 + d;
        q[e] = qkv[base]; k[e] = qkv[base + 512]; v[e] = qkv[base + 1024];
    }
    __syncthreads();
    for (int e = t; e < TT*TT; e += 128) {
        int i = e / TT, j = e - i*TT;
        float acc = 0.f;
        #pragma unroll
        for (int d = 0; d < 64; d++) acc = fmaf(q[i*64+d], k[j*64+d], acc);
        s[i*66 + j] = acc*0.125f;
    }
    __syncthreads();
    int w = t >> 5, lane = t & 31;
    for (int i = w; i < TT; i += 4) {
        float a0 = s[i*66 + lane], a1 = s[i*66 + 32 + lane];
        float a2 = (lane == 0) ? s[i*66 + 64] : -INFINITY;
        float mx = fmaxf(fmaxf(a0, a1), a2);
        for (int off = 16; off; off >>= 1) mx = fmaxf(mx, __shfl_xor_sync(0xffffffffu, mx, off));
        float e0 = expf(a0 - mx), e1 = expf(a1 - mx);
        float e2 = (lane == 0) ? expf(a2 - mx) : 0.f;
        float sum = e0 + e1 + e2;
        for (int off = 16; off; off >>= 1) sum += __shfl_xor_sync(0xffffffffu, sum, off);
        float inv = 1.0f / sum;
        s[i*66 + lane] = e0*inv; s[i*66 + 32 + lane] = e1*inv;
        if (lane == 0) s[i*66 + 64] = e2*inv;
    }
    __syncthreads();
    for (int e = t; e < TT*DHEAD; e += 128) {
        int i = e >> 6, d = e & 63;
        float acc = 0.f;
        for (int j = 0; j < TT; j++) acc = fmaf(s[i*66 + j], v[j*64 + d], acc);
        z[((size_t)(b*TT + i))*INNER + h*64 + d] = acc;
    }
}

__global__ void k_out(float* __restrict__ out) {
    int id = blockIdx.x*256 + threadIdx.x;
    if (id >= BB*PP*DD) return;
    int d = id % DD, p = (id / DD) % PP, b = id / (DD*PP);
    out[id] = g_t[((size_t)(b*TT + 1 + p))*DD + d];
}

// =============================================================================
extern "C" void kernel_launch(void* const* d_in, const int* in_sizes, int n_in,
                              void* d_out, int out_size) {
    const float* x    = (const float*)d_in[0];
    const float* pos  = (const float*)d_in[1];
    const float* w1   = (const float*)d_in[2];
    const float* g1   = (const float*)d_in[3];
    const float* b1   = (const float*)d_in[4];
    const float* w2   = (const float*)d_in[5];
    const float* g2   = (const float*)d_in[6];
    const float* b2   = (const float*)d_in[7];
    const float* w3   = (const float*)d_in[8];
    const float* g3   = (const float*)d_in[9];
    const float* b3   = (const float*)d_in[10];
    const float* w4   = (const float*)d_in[11];
    const float* g4   = (const float*)d_in[12];
    const float* b4   = (const float*)d_in[13];
    const float* w5   = (const float*)d_in[14];
    const float* g5   = (const float*)d_in[15];
    const float* b5   = (const float*)d_in[16];
    const float* cls  = (const float*)d_in[17];
    const float* ln1g = (const float*)d_in[18];
    const float* ln1b = (const float*)d_in[19];
    const float* wqkv = (const float*)d_in[20];
    const float* wout = (const float*)d_in[21];
    const float* bout = (const float*)d_in[22];
    const float* ln2g = (const float*)d_in[23];
    const float* ln2b = (const float*)d_in[24];
    const float* wff1 = (const float*)d_in[25];
    const float* bff1 = (const float*)d_in[26];
    const float* wff2 = (const float*)d_in[27];
    const float* bff2 = (const float*)d_in[28];

    void* p;
    float *h0P, *HP, *xxP, *yP, *ftP, *fbP, *wcP, *tP, *hnP, *qkvP, *zP, *ffP;
    double *sumdP, *ssqdP;
    cudaGetSymbolAddress(&p, g_h0);    h0P   = (float*)p;
    cudaGetSymbolAddress(&p, g_H);     HP    = (float*)p;
    cudaGetSymbolAddress(&p, g_xx);    xxP   = (float*)p;
    cudaGetSymbolAddress(&p, g_y);     yP    = (float*)p;
    cudaGetSymbolAddress(&p, g_ft);    ftP   = (float*)p;
    cudaGetSymbolAddress(&p, g_fpadB); fbP   = (float*)p;
    cudaGetSymbolAddress(&p, g_wc);    wcP   = (float*)p;
    cudaGetSymbolAddress(&p, g_sumd);  sumdP = (double*)p;
    cudaGetSymbolAddress(&p, g_ssqd);  ssqdP = (double*)p;
    cudaGetSymbolAddress(&p, g_t);     tP    = (float*)p;
    cudaGetSymbolAddress(&p, g_hn);    hnP   = (float*)p;
    cudaGetSymbolAddress(&p, g_qkv);   qkvP  = (float*)p;
    cudaGetSymbolAddress(&p, g_z);     zP    = (float*)p;
    cudaGetSymbolAddress(&p, g_ff);    ffP   = (float*)p;
    float* vuP = yP + (size_t)BB*NN*NN;   // vu scratch beyond dist matrix

    int attn_smem = (3*TT*DHEAD + TT*66) * sizeof(float);
    cudaFuncSetAttribute(k_attn, cudaFuncAttributeMaxDynamicSharedMemorySize, attn_smem);

    k_transpose_x<<<(BB*NN + 255)/256, 256>>>(x);
    cudaMemsetAsync(sumdP, 0, 256*NBIN*sizeof(double));
    cudaMemsetAsync(ssqdP, 0, 256*NBIN*sizeof(double));

    dim3 gDist64(NN/64, NN/64, BB);
    dim3 gDist128(NN/128, NN/128, BB);

    // ---- EdgeConv 1: C=3 (Kpad 16) -> O=64 ----
    k_xx<<<(BB*NN + 255)/256, 256>>>(h0P, 3, 0, 3);
    k_gemm<<<gDist64, 256>>>(ftP, fbP, xxP, yP,
        NN, NN, 16, 16, (long)NN*16, (long)16*NN, (long)NN*NN, 4);
    k_topk3<<<BB*NN, 256>>>(yP);
    k_wcat<<<(16*128 + 255)/256, 256>>>(w1, 3, 16, 64, wcP);
    k_gemm128<<<dim3(1, BB*NN/128, 1), 256>>>(ftP, wcP, nullptr, vuP,
        BB*NN, 128, 16, 0L, 0L, 0L, 16, 128, 0, 0);
    k_edgemax<64><<<BB*NN/4, 256>>>(vuP);
    k_finstats<64><<<1, 64>>>();
    k_bnmax<64><<<(BB*NN*64 + 255)/256, 256>>>(g1, b1, 0, ftP, 64, 0);

    // ---- EdgeConv 2: x1 (C=64) -> O=64 ----
    k_xx<<<(BB*NN + 255)/256, 256>>>(HP, 512, 0, 64);
    k_gemm128<<<gDist128, 256>>>(ftP, HP, xxP, yP,
        NN, NN, 64, (long)NN*64, (long)512*NN, (long)NN*NN, 64, NN, 4, 1);
    k_topk3<<<BB*NN, 256>>>(yP);
    k_wcat<<<(64*128 + 255)/256, 256>>>(w2, 64, 64, 64, wcP);
    k_gemm128<<<dim3(1, BB*NN/128, 1), 256>>>(ftP, wcP, nullptr, vuP,
        BB*NN, 128, 64, 0L, 0L, 0L, 64, 128, 0, 0);
    k_edgemax<64><<<BB*NN/4, 256>>>(vuP);
    k_finstats<64><<<1, 64>>>();
    k_bnmax<64><<<(BB*NN*64 + 255)/256, 256>>>(g2, b2, 64, ftP, 64, 0);

    // ---- EdgeConv 3: x2 (C=64) -> O=128 ----
    k_xx<<<(BB*NN + 255)/256, 256>>>(HP, 512, 64, 64);
    k_gemm128<<<gDist128, 256>>>(ftP, HP + (size_t)64*NN, xxP, yP,
        NN, NN, 64, (long)NN*64, (long)512*NN, (long)NN*NN, 64, NN, 4, 1);
    k_topk3<<<BB*NN, 256>>>(yP);
    k_wcat<<<(64*256 + 255)/256, 256>>>(w3, 64, 64, 128, wcP);
    k_gemm128<<<dim3(2, BB*NN/128, 1), 256>>>(ftP, wcP, nullptr, vuP,
        BB*NN, 256, 64, 0L, 0L, 0L, 64, 256, 0, 0);
    k_edgemax<128><<<BB*NN/2, 256>>>(vuP);
    k_finstats<128><<<1, 128>>>();
    k_bnmax<128><<<(BB*NN*128 + 255)/256, 256>>>(g3, b3, 128, ftP, 128, 0);

    // ---- EdgeConv 4: x3 (C=128) -> O=256 ----
    k_xx<<<(BB*NN + 255)/256, 256>>>(HP, 512, 128, 128);
    k_gemm128<<<gDist128, 256>>>(ftP, HP + (size_t)128*NN, xxP, yP,
        NN, NN, 128, (long)NN*128, (long)512*NN, (long)NN*NN, 128, NN, 4, 1);
    k_topk3<<<BB*NN, 256>>>(yP);
    k_wcat<<<(128*512 + 255)/256, 256>>>(w4, 128, 128, 256, wcP);
    k_gemm128<<<dim3(4, BB*NN/128, 1), 256>>>(ftP, wcP, nullptr, vuP,
        BB*NN, 512, 128, 0L, 0L, 0L, 128, 512, 0, 0);
    k_edgemax<256><<<BB*NN, 256>>>(vuP);
    k_finstats<256><<<1, 256>>>();
    k_bnmax<256><<<(BB*NN*256 + 255)/256, 256>>>(g4, b4, 256, nullptr, 0, 0);

    // ---- conv5: y[b] = w5[1024,512] @ H[b][512,2048] ----
    k_gemm128<<<dim3(NN/128, 1024/128, BB), 256>>>(
        w5, HP, nullptr, yP, 1024, NN, 512,
        0L, (long)512*NN, (long)1024*NN, 512, NN, 0, 0);
    k_stats5<<<1024, 256>>>();
    k_pool<<<(BB*DD*PP + 255)/256, 256>>>(g5, b5, cls);

    // ---- transformer: split-K partial GEMMs + reduce epilogues ----
    int mrows = (TOK + 63)/64;   // 9
    for (int i = 0; i < DEPTH; i++) {
        k_ln<<<TOK, 256>>>(pos, ln1g + (size_t)i*DD, ln1b + (size_t)i*DD, hnP);
        k_gemm<<<dim3((3*INNER)/64, mrows, 2), 256>>>(
            hnP, wqkv + (size_t)i*DD*3*INNER, nullptr, yP,
            TOK, 3*INNER, 512, DD, 512L, (long)512*3*INNER, (long)TOK*3*INNER, 0);
        k_reduce<<<(TOK*3*INNER + 255)/256, 256>>>(
            yP, (long)TOK*3*INNER, 2, nullptr, qkvP, 3*INNER, TOK*3*INNER, 0);
        k_attn<<<BB*NHEAD, 128, attn_smem>>>(qkvP, zP);
        k_gemm<<<dim3(DD/64, mrows, 2), 256>>>(
            zP, wout + (size_t)i*INNER*DD, nullptr, yP,
            TOK, DD, 256, INNER, 256L, (long)256*DD, (long)TOK*DD, 0);
        k_reduce<<<(TOK*DD + 255)/256, 256>>>(
            yP, (long)TOK*DD, 2, bout + (size_t)i*DD, tP, DD, TOK*DD, 3);
        k_ln<<<TOK, 256>>>(nullptr, ln2g + (size_t)i*DD, ln2b + (size_t)i*DD, hnP);
        k_gemm<<<dim3(MLPD/64, mrows, 2), 256>>>(
            hnP, wff1 + (size_t)i*DD*MLPD, nullptr, yP,
            TOK, MLPD, 512, DD, 512L, (long)512*MLPD, (long)TOK*MLPD, 0);
        k_reduce<<<(TOK*MLPD + 255)/256, 256>>>(
            yP, (long)TOK*MLPD, 2, bff1 + (size_t)i*MLPD, ffP, MLPD, TOK*MLPD, 2);
        k_gemm<<<dim3(DD/64, mrows, 4), 256>>>(
            ffP, wff2 + (size_t)i*MLPD*DD, nullptr, yP,
            TOK, DD, 512, MLPD, 512L, (long)512*DD, (long)TOK*DD, 0);
        k_reduce<<<(TOK*DD + 255)/256, 256>>>(
            yP, (long)TOK*DD, 4, bff2 + (size_t)i*DD, tP, DD, TOK*DD, 3);
    }

    k_out<<<(BB*PP*DD + 255)/256, 256>>>((float*)d_out);
}

// round 17
// speedup vs baseline: 1.6656x; 1.0045x over previous
#include <cuda_runtime.h>
#include <math.h>

#define BB    8
#define NN    2048
#define KKN   20
#define PP    64
#define PSZ   32
#define DD    1024
#define TT    65
#define TOK   (BB*TT)     // 520
#define INNER 512
#define NHEAD 8
#define DHEAD 64
#define MLPD  2048
#define DEPTH 6
#define EPSV  1e-5f
#define NBIN  64

// ---------------- scratch (static device globals; no runtime allocation) ----
__device__ float  g_h0 [BB*3*NN];                     // transposed xyz [B,3,N]
__device__ float  g_H  [BB*512*NN];                   // concat features [B,512,N]
__device__ float  g_xx[BB*NN];
__device__ int    g_idx[BB*NN*KKN];
__device__ float  g_y [(size_t)BB*NN*KKN*256];        // scratch: dist / conv5 y / split-K partials / vu
__device__ float  g_mn [BB*NN*256*2];                 // per-(bn,o) max/min over k
__device__ float  g_ft [BB*NN*128];                   // row-major features [B*N][Cld]
__device__ float  g_fpadB[BB*16*NN];                  // zero-padded xyz [B,16,N]
__device__ float  g_wc [128*512];                     // concatenated transposed weights
__device__ double g_sumd[256*NBIN];
__device__ double g_ssqd[256*NBIN];
__device__ float  g_mu [1024];
__device__ float  g_rs [1024];
__device__ float  g_t  [TOK*DD];
__device__ float  g_hn [TOK*DD];
__device__ float  g_qkv[TOK*3*INNER];
__device__ float  g_z  [TOK*INNER];
__device__ float  g_ff [TOK*MLPD];

// ------- stage 0: transpose x + build padded B operand + conv1 ft rows -------
__global__ void k_transpose_x(const float* __restrict__ x) {
    int id = blockIdx.x*256 + threadIdx.x;
    if (id >= BB*NN) return;
    int b = id / NN, n = id % NN;
    float v[3];
    #pragma unroll
    for (int c = 0; c < 3; c++) {
        v[c] = x[id*3 + c];
        g_h0[(b*3+c)*NN + n] = v[c];
        g_fpadB[(b*16+c)*NN + n] = v[c];
    }
    #pragma unroll
    for (int c = 3; c < 16; c++) g_fpadB[(b*16+c)*NN + n] = 0.f;
    #pragma unroll
    for (int c = 0; c < 16; c++) g_ft[(size_t)id*16 + c] = (c < 3) ? v[c] : 0.f;
}

// ---------------- xx = sum_c x^2 ---------------------------------------------
__global__ void k_xx(const float* __restrict__ src, int Ctot, int coff, int C) {
    int id = blockIdx.x*256 + threadIdx.x;
    if (id >= BB*NN) return;
    int b = id / NN, m = id % NN;
    float s = 0.f;
    for (int c = 0; c < C; c++) {
        float v = src[((size_t)b*Ctot + coff + c)*NN + m];
        s = fmaf(v, v, s);
    }
    g_xx[id] = s;
}

// --------- build wcat[Kpad][2O]: cols [0,O)=w1^T, [O,2O)=(w2-w1)^T ----------
__global__ void k_wcat(const float* __restrict__ w, int C, int Kpad, int O,
                       float* __restrict__ wc) {
    int id = blockIdx.x*256 + threadIdx.x;
    if (id >= Kpad*2*O) return;
    int col = id % (2*O), c = id / (2*O);
    float val = 0.f;
    if (c < C) {
        int o = (col < O) ? col : col - O;
        float a = w[(size_t)o*2*C + c];
        val = (col < O) ? a : (w[(size_t)o*2*C + C + c] - a);
    }
    wc[id] = val;
}

// ---------------- generic tiled fp32 GEMM (64x64), lda-aware -----------------
// epi: 0 plain, 4 dist
__global__ void k_gemm(const float* __restrict__ A, const float* __restrict__ Bm,
                       const float* __restrict__ xx,
                       float* dst,
                       int M, int Nc, int Kc, int lda,
                       long sA, long sB, long sC, int epi) {
    __shared__ __align__(16) float As[16][64];
    __shared__ __align__(16) float Bs[16][64];
    int tid = threadIdx.x;
    int tx = tid & 15, ty = tid >> 4;
    int row0 = blockIdx.y*64, col0 = blockIdx.x*64;
    const float* Ap = A + (size_t)blockIdx.z*sA;
    const float* Bp = Bm + (size_t)blockIdx.z*sB;
    float acc[4][4] = {};
    int r = tid >> 2, kq = tid & 3;
    for (int kt = 0; kt < Kc; kt += 16) {
        float4 a4 = make_float4(0.f, 0.f, 0.f, 0.f);
        int row = row0 + r;
        if (row < M) a4 = *(const float4*)&Ap[(size_t)row*lda + kt + kq*4];
        As[kq*4+0][r] = a4.x; As[kq*4+1][r] = a4.y;
        As[kq*4+2][r] = a4.z; As[kq*4+3][r] = a4.w;
        #pragma unroll
        for (int i = 0; i < 4; i++) {
            int kr = (tid >> 6) + i*4;
            Bs[kr][tid & 63] = Bp[(size_t)(kt + kr)*Nc + col0 + (tid & 63)];
        }
        __syncthreads();
        #pragma unroll
        for (int kk = 0; kk < 16; kk++) {
            float4 a = *(const float4*)&As[kk][ty*4];
            float4 bq = *(const float4*)&Bs[kk][tx*4];
            acc[0][0] = fmaf(a.x, bq.x, acc[0][0]); acc[0][1] = fmaf(a.x, bq.y, acc[0][1]);
            acc[0][2] = fmaf(a.x, bq.z, acc[0][2]); acc[0][3] = fmaf(a.x, bq.w, acc[0][3]);
            acc[1][0] = fmaf(a.y, bq.x, acc[1][0]); acc[1][1] = fmaf(a.y, bq.y, acc[1][1]);
            acc[1][2] = fmaf(a.y, bq.z, acc[1][2]); acc[1][3] = fmaf(a.y, bq.w, acc[1][3]);
            acc[2][0] = fmaf(a.z, bq.x, acc[2][0]); acc[2][1] = fmaf(a.z, bq.y, acc[2][1]);
            acc[2][2] = fmaf(a.z, bq.z, acc[2][2]); acc[2][3] = fmaf(a.z, bq.w, acc[2][3]);
            acc[3][0] = fmaf(a.w, bq.x, acc[3][0]); acc[3][1] = fmaf(a.w, bq.y, acc[3][1]);
            acc[3][2] = fmaf(a.w, bq.z, acc[3][2]); acc[3][3] = fmaf(a.w, bq.w, acc[3][3]);
        }
        __syncthreads();
    }
    float* Dp = dst + (size_t)blockIdx.z*sC;
    const float* xxz = (epi == 4) ? (xx + (size_t)blockIdx.z*Nc) : nullptr;
    #pragma unroll
    for (int i = 0; i < 4; i++) {
        int row = row0 + ty*4 + i;
        if (row >= M) continue;
        #pragma unroll
        for (int j = 0; j < 4; j++) {
            int col = col0 + tx*4 + j;
            float v = acc[i][j];
            if (epi == 4) v = 2.0f*v - xxz[row] - xxz[col];
            Dp[(size_t)row*Nc + col] = v;
        }
    }
}

// ------- double-buffered 64x64 GEMM for transformer (bit-identical math) -----
__global__ void __launch_bounds__(256) k_gemmDB(
        const float* __restrict__ A, const float* __restrict__ Bm,
        float* __restrict__ dst,
        int M, int Nc, int Kc, int lda,
        long sA, long sB, long sC) {
    __shared__ __align__(16) float As[2][16][64];
    __shared__ __align__(16) float Bs[2][16][64];
    int tid = threadIdx.x;
    int tx = tid & 15, ty = tid >> 4;
    int row0 = blockIdx.y*64, col0 = blockIdx.x*64;
    const float* Ap = A + (size_t)blockIdx.z*sA;
    const float* Bp = Bm + (size_t)blockIdx.z*sB;
    float acc[4][4] = {};
    int r = tid >> 2, kq = (tid & 3)*4;
    int bc = tid & 63, bk0 = tid >> 6;
    float4 ra; float rb[4];

    auto ld = [&](int kt) {
        ra = make_float4(0.f, 0.f, 0.f, 0.f);
        int row = row0 + r;
        if (row < M) ra = *(const float4*)&Ap[(size_t)row*lda + kt + kq];
        #pragma unroll
        for (int i = 0; i < 4; i++)
            rb[i] = Bp[(size_t)(kt + bk0 + i*4)*Nc + col0 + bc];
    };
    auto st = [&](int bf) {
        As[bf][kq+0][r] = ra.x; As[bf][kq+1][r] = ra.y;
        As[bf][kq+2][r] = ra.z; As[bf][kq+3][r] = ra.w;
        #pragma unroll
        for (int i = 0; i < 4; i++) Bs[bf][bk0 + i*4][bc] = rb[i];
    };

    int nk = Kc >> 4;
    ld(0); st(0);
    __syncthreads();
    int cur = 0;
    for (int it = 0; it < nk; it++) {
        if (it + 1 < nk) ld((it+1)*16);
        #pragma unroll
        for (int kk = 0; kk < 16; kk++) {
            float4 a = *(const float4*)&As[cur][kk][ty*4];
            float4 bq = *(const float4*)&Bs[cur][kk][tx*4];
            acc[0][0] = fmaf(a.x, bq.x, acc[0][0]); acc[0][1] = fmaf(a.x, bq.y, acc[0][1]);
            acc[0][2] = fmaf(a.x, bq.z, acc[0][2]); acc[0][3] = fmaf(a.x, bq.w, acc[0][3]);
            acc[1][0] = fmaf(a.y, bq.x, acc[1][0]); acc[1][1] = fmaf(a.y, bq.y, acc[1][1]);
            acc[1][2] = fmaf(a.y, bq.z, acc[1][2]); acc[1][3] = fmaf(a.y, bq.w, acc[1][3]);
            acc[2][0] = fmaf(a.z, bq.x, acc[2][0]); acc[2][1] = fmaf(a.z, bq.y, acc[2][1]);
            acc[2][2] = fmaf(a.z, bq.z, acc[2][2]); acc[2][3] = fmaf(a.z, bq.w, acc[2][3]);
            acc[3][0] = fmaf(a.w, bq.x, acc[3][0]); acc[3][1] = fmaf(a.w, bq.y, acc[3][1]);
            acc[3][2] = fmaf(a.w, bq.z, acc[3][2]); acc[3][3] = fmaf(a.w, bq.w, acc[3][3]);
        }
        if (it + 1 < nk) {
            st(cur ^ 1);
            __syncthreads();
            cur ^= 1;
        }
    }
    float* Dp = dst + (size_t)blockIdx.z*sC;
    #pragma unroll
    for (int i = 0; i < 4; i++) {
        int row = row0 + ty*4 + i;
        if (row >= M) continue;
        #pragma unroll
        for (int j = 0; j < 4; j++)
            Dp[(size_t)row*Nc + col0 + tx*4 + j] = acc[i][j];
    }
}

// ---------------- split-K reduce: sum partials + epilogue --------------------
// mode: 0 plain, 2 gelu(v+bias), 3 v+bias+dst residual
__global__ void k_reduce(const float* __restrict__ part, long sC, int P,
                         const float* __restrict__ bias, float* __restrict__ dst,
                         int Nc, int total, int mode) {
    int id = blockIdx.x*256 + threadIdx.x;
    if (id >= total) return;
    float v = 0.f;
    for (int p = 0; p < P; p++) v += part[(size_t)p*sC + id];
    if (mode >= 2) v += bias[id % Nc];
    if (mode == 2) v = 0.5f*v*(1.0f + erff(v*0.70710678118654752f));
    if (mode == 3) v += dst[id];
    dst[id] = v;
}

// ---------------- 128x128-tile fp32 GEMM (8x8/thread), optional symmetry -----
__global__ void __launch_bounds__(256) k_gemm128(
        const float* __restrict__ A, const float* __restrict__ Bm,
        const float* __restrict__ xx, float* __restrict__ dst,
        int M, int Nc, int Kc,
        long sA, long sB, long sC, int lda, int ldb, int epi, int sym) {
    int bx = blockIdx.x, by = blockIdx.y;
    if (sym && bx < by) return;
    __shared__ __align__(16) float As[16][128];
    __shared__ __align__(16) float Bs[16][128];
    int tid = threadIdx.x;
    int tx = tid & 15, ty = tid >> 4;
    int row0 = by*128, col0 = bx*128;
    const float* Ap = A + (size_t)blockIdx.z*sA;
    const float* Bp = Bm + (size_t)blockIdx.z*sB;
    float acc[8][8] = {};
    int ar = tid >> 1, ak = (tid & 1)*8;
    int bkr = tid >> 4, bc4 = (tid & 15)*8;
    for (int kt = 0; kt < Kc; kt += 16) {
        float4 a0 = make_float4(0.f,0.f,0.f,0.f), a1 = a0;
        int arow = row0 + ar;
        if (arow < M) {
            a0 = *(const float4*)&Ap[(size_t)arow*lda + kt + ak];
            a1 = *(const float4*)&Ap[(size_t)arow*lda + kt + ak + 4];
        }
        As[ak+0][ar] = a0.x; As[ak+1][ar] = a0.y; As[ak+2][ar] = a0.z; As[ak+3][ar] = a0.w;
        As[ak+4][ar] = a1.x; As[ak+5][ar] = a1.y; As[ak+6][ar] = a1.z; As[ak+7][ar] = a1.w;
        *(float4*)&Bs[bkr][bc4]   = *(const float4*)&Bp[(size_t)(kt+bkr)*ldb + col0 + bc4];
        *(float4*)&Bs[bkr][bc4+4] = *(const float4*)&Bp[(size_t)(kt+bkr)*ldb + col0 + bc4 + 4];
        __syncthreads();
        #pragma unroll
        for (int kk = 0; kk < 16; kk++) {
            float av[8], bv[8];
            *(float4*)&av[0] = *(const float4*)&As[kk][ty*8];
            *(float4*)&av[4] = *(const float4*)&As[kk][ty*8+4];
            *(float4*)&bv[0] = *(const float4*)&Bs[kk][tx*8];
            *(float4*)&bv[4] = *(const float4*)&Bs[kk][tx*8+4];
            #pragma unroll
            for (int i = 0; i < 8; i++)
                #pragma unroll
                for (int j = 0; j < 8; j++)
                    acc[i][j] = fmaf(av[i], bv[j], acc[i][j]);
        }
        __syncthreads();
    }
    float* Dp = dst + (size_t)blockIdx.z*sC;
    if (epi == 4) {
        const float* xxz = xx + (size_t)blockIdx.z*Nc;
        float xr[8], xc[8];
        #pragma unroll
        for (int i = 0; i < 8; i++) xr[i] = xxz[row0 + ty*8 + i];
        #pragma unroll
        for (int j = 0; j < 8; j++) xc[j] = xxz[col0 + tx*8 + j];
        #pragma unroll
        for (int i = 0; i < 8; i++) {
            int row = row0 + ty*8 + i;
            float v[8];
            #pragma unroll
            for (int j = 0; j < 8; j++) v[j] = 2.0f*acc[i][j] - xr[i] - xc[j];
            *(float4*)&Dp[(size_t)row*Nc + col0 + tx*8]     = *(float4*)&v[0];
            *(float4*)&Dp[(size_t)row*Nc + col0 + tx*8 + 4] = *(float4*)&v[4];
        }
        if (sym && bx != by) {
            #pragma unroll
            for (int j = 0; j < 8; j++) {
                int col = col0 + tx*8 + j;
                float tv[8];
                #pragma unroll
                for (int i = 0; i < 8; i++) tv[i] = 2.0f*acc[i][j] - xr[i] - xc[j];
                *(float4*)&Dp[(size_t)col*Nc + row0 + ty*8]     = *(float4*)&tv[0];
                *(float4*)&Dp[(size_t)col*Nc + row0 + ty*8 + 4] = *(float4*)&tv[4];
            }
        }
    } else {
        #pragma unroll
        for (int i = 0; i < 8; i++) {
            int row = row0 + ty*8 + i;
            if (row >= M) continue;
            *(float4*)&Dp[(size_t)row*Nc + col0 + tx*8]     = *(float4*)&acc[i][0];
            *(float4*)&Dp[(size_t)row*Nc + col0 + tx*8 + 4] = *(float4*)&acc[i][4];
        }
    }
}

// ------------- top-20 v3: block per row, sort-8/lane + 2-level merge ---------
#define CMPSW(i,j) { if (a[i] < a[j]) { unsigned long long tq = a[i]; a[i] = a[j]; a[j] = tq; } }
__global__ void __launch_bounds__(256) k_topk3(const float* __restrict__ dist) {
    __shared__ unsigned long long sml[8*256];
    __shared__ unsigned long long wtop[8*20];
    int t = threadIdx.x;
    int w = t >> 5, lane = t & 31;
    int bn = blockIdx.x;
    const float* dp = dist + (size_t)bn*NN;
    unsigned long long a[8];
    #pragma unroll
    for (int i = 0; i < 8; i++) {
        int m = w*256 + i*32 + lane;
        unsigned int u = __float_as_uint(dp[m]);
        u ^= ((unsigned int)((int)u >> 31)) | 0x80000000u;   // monotone map
        a[i] = ((unsigned long long)u << 32) | (unsigned int)(2047 - m);
    }
    CMPSW(0,1) CMPSW(2,3) CMPSW(4,5) CMPSW(6,7)
    CMPSW(0,2) CMPSW(1,3) CMPSW(4,6) CMPSW(5,7)
    CMPSW(1,2) CMPSW(5,6) CMPSW(0,4) CMPSW(3,7)
    CMPSW(1,5) CMPSW(2,6)
    CMPSW(1,4) CMPSW(3,6)
    CMPSW(2,4) CMPSW(3,5)
    CMPSW(3,4)
    #pragma unroll
    for (int i = 0; i < 8; i++) sml[i*256 + t] = a[i];
    __syncwarp();
    {
        int pos = 0;
        unsigned long long cur = a[0];
        #pragma unroll
        for (int j = 0; j < 20; j++) {
            unsigned long long mx = cur;
            #pragma unroll
            for (int off = 16; off; off >>= 1) {
                unsigned long long o = __shfl_xor_sync(0xffffffffu, mx, off);
                if (o > mx) mx = o;
            }
            if (lane == 0) wtop[w*20 + j] = mx;
            if (cur == mx) { pos++; cur = (pos < 8) ? sml[pos*256 + t] : 0ull; }
        }
    }
    __syncthreads();
    if (w == 0) {
        int pos = 0;
        unsigned long long cur = (lane < 8) ? wtop[lane*20] : 0ull;
        #pragma unroll
        for (int j = 0; j < 20; j++) {
            unsigned long long mx = cur;
            #pragma unroll
            for (int off = 16; off; off >>= 1) {
                unsigned long long o = __shfl_xor_sync(0xffffffffu, mx, off);
                if (o > mx) mx = o;
            }
            if (lane == 0) g_idx[bn*KKN + j] = 2047 - (int)(mx & 0xffffffffu);
            if (cur == mx && lane < 8) { pos++; cur = (pos < 20) ? wtop[lane*20 + pos] : 0ull; }
        }
    }
}

// -- EdgeConv v2: gather precomputed per-point projections, max/min + stats ---
// vu: [B*N][2O]  cols [0,O)=v=w1·ft,  [O,2O)=u=(w2-w1)·ft
template<int O>
__global__ void __launch_bounds__(256) k_edgemax(const float* __restrict__ vu) {
    constexpr int G = 256/O;
    __shared__ int sidx[G][KKN];
    int bn0 = blockIdx.x*G;
    int t = threadIdx.x;
    for (int e = t; e < G*KKN; e += 256) {
        int g = e / KKN, kk = e % KKN;
        sidx[g][kk] = g_idx[(bn0+g)*KKN + kk];
    }
    __syncthreads();
    int g = t / O, o = t % O;
    int bn = bn0 + g, b = bn >> 11;
    float u = vu[(size_t)bn*(2*O) + O + o];
    double s = 0.0, ss = 0.0;
    float mx = -INFINITY, mn = INFINITY;
    #pragma unroll
    for (int kk = 0; kk < KKN; kk++) {
        float v = vu[((size_t)(b*NN + sidx[g][kk]))*(2*O) + o] + u;
        mx = fmaxf(mx, v); mn = fminf(mn, v);
        double vd = (double)v; s += vd; ss += vd*vd;
    }
    g_mn[((size_t)bn*O + o)*2]     = mx;
    g_mn[((size_t)bn*O + o)*2 + 1] = mn;
    int bin = bn & (NBIN-1);
    atomicAdd(&g_sumd[o*NBIN + bin], s);
    atomicAdd(&g_ssqd[o*NBIN + bin], ss);
}

// ------------- finalize BN stats (and re-zero bins for the next stage) -------
template<int O>
__global__ void k_finstats() {
    int o = threadIdx.x;
    if (o >= O) return;
    double s = 0.0, ss = 0.0;
    #pragma unroll 8
    for (int i = 0; i < NBIN; i++) {
        s += g_sumd[o*NBIN + i]; ss += g_ssqd[o*NBIN + i];
        g_sumd[o*NBIN + i] = 0.0; g_ssqd[o*NBIN + i] = 0.0;
    }
    const double cnt = (double)BB*NN*KKN;
    double mu = s / cnt;
    double var = ss / cnt - mu*mu;
    g_mu[o] = (float)mu;
    g_rs[o] = rsqrtf((float)var + EPSV);
}

// -- BN normalize + leaky on pre-reduced max/min; writes g_H and next ft ------
template<int O>
__global__ void k_bnmax(const float* __restrict__ g, const float* __restrict__ bb,
                        int coff, float* __restrict__ ftNext, int ldNext, int foff) {
    int id = blockIdx.x*256 + threadIdx.x;
    if (id >= BB*NN*O) return;
    int o = id % O, bn = id / O;
    float mu = g_mu[o], rs = g_rs[o];
    float gg = g[o], bv = bb[o];
    float a = rs*gg;
    float y = (a >= 0.f) ? g_mn[(size_t)id*2] : g_mn[(size_t)id*2 + 1];
    float v = (y - mu)*a + bv;
    v = v >= 0.f ? v : 0.2f*v;
    int b = bn >> 11, n = bn & 2047;
    g_H[((size_t)b*512 + coff + o)*NN + n] = v;
    if (ftNext) ftNext[(size_t)bn*ldNext + foff + o] = v;
}

// ---------------- conv5 BN stats (block per channel, double accum) -----------
__global__ void k_stats5() {
    int d = blockIdx.x, t = threadIdx.x;
    double s = 0.0, ss = 0.0;
    for (int b = 0; b < BB; b++) {
        const float* yp = g_y + ((size_t)(b*1024 + d))*NN;
        for (int n = t; n < NN; n += 256) {
            double v = (double)yp[n];
            s += v; ss += v*v;
        }
    }
    __shared__ double sred[8], ssred[8];
    for (int off = 16; off; off >>= 1) {
        s  += __shfl_xor_sync(0xffffffffu, s, off);
        ss += __shfl_xor_sync(0xffffffffu, ss, off);
    }
    if ((t & 31) == 0) { sred[t >> 5] = s; ssred[t >> 5] = ss; }
    __syncthreads();
    if (t == 0) {
        s = 0.0; ss = 0.0;
        for (int i = 0; i < 8; i++) { s += sred[i]; ss += ssred[i]; }
        double mu = s*(1.0/16384.0);
        double var = ss*(1.0/16384.0) - mu*mu;
        g_mu[d] = (float)mu;
        g_rs[d] = rsqrtf((float)var + EPSV);
    }
}

// ---------------- BN+leaky+patch max-pool + cls token ------------------------
__global__ void k_pool(const float* __restrict__ g5, const float* __restrict__ b5,
                       const float* __restrict__ cls) {
    int id = blockIdx.x*256 + threadIdx.x;
    if (id >= BB*DD*PP) return;
    int p = id % PP, d = (id / PP) % DD, b = id / (PP*DD);
    float mu = g_mu[d], r = g_rs[d], gg = g5[d], bv = b5[d];
    const float* yp = g_y + ((size_t)(b*1024 + d))*NN + p*PSZ;
    float mx = -INFINITY;
    #pragma unroll
    for (int s_ = 0; s_ < PSZ; s_++) {
        float v = (yp[s_] - mu)*r*gg + bv;
        v = v >= 0.f ? v : 0.2f*v;
        mx = fmaxf(mx, v);
    }
    g_t[((size_t)(b*TT + 1 + p))*DD + d] = mx;
    if (p == 0) g_t[((size_t)(b*TT))*DD + d] = cls[d];
}

// ---------------- two-pass LN (optional fused +pos residual into t) ----------
__global__ void k_ln(const float* __restrict__ pos, const float* __restrict__ g,
                     const float* __restrict__ b, float* __restrict__ out) {
    int row = blockIdx.x, t = threadIdx.x;
    float* xp = g_t + (size_t)row*DD;
    float v0 = xp[t], v1 = xp[t+256], v2 = xp[t+512], v3 = xp[t+768];
    if (pos) {
        const float* pp = pos + (size_t)row*DD;
        v0 += pp[t]; v1 += pp[t+256]; v2 += pp[t+512]; v3 += pp[t+768];
        xp[t] = v0; xp[t+256] = v1; xp[t+512] = v2; xp[t+768] = v3;
    }
    __shared__ float red[8];
    __shared__ float bc[2];
    float s = v0+v1+v2+v3;
    for (int off = 16; off; off >>= 1) s += __shfl_xor_sync(0xffffffffu, s, off);
    if ((t & 31) == 0) red[t >> 5] = s;
    __syncthreads();
    if (t == 0) {
        s = 0.f;
        for (int i = 0; i < 8; i++) s += red[i];
        bc[0] = s*(1.0f/1024.0f);
    }
    __syncthreads();
    float mu = bc[0];
    float d0 = v0-mu, d1 = v1-mu, d2 = v2-mu, d3 = v3-mu;
    float ss = d0*d0 + d1*d1 + d2*d2 + d3*d3;
    for (int off = 16; off; off >>= 1) ss += __shfl_xor_sync(0xffffffffu, ss, off);
    if ((t & 31) == 0) red[t >> 5] = ss;
    __syncthreads();
    if (t == 0) {
        ss = 0.f;
        for (int i = 0; i < 8; i++) ss += red[i];
        bc[1] = rsqrtf(ss*(1.0f/1024.0f) + EPSV);
    }
    __syncthreads();
    float r = bc[1];
    float* op = out + (size_t)row*DD;
    op[t]     = d0*r*g[t]     + b[t];
    op[t+256] = d1*r*g[t+256] + b[t+256];
    op[t+512] = d2*r*g[t+512] + b[t+512];
    op[t+768] = d3*r*g[t+768] + b[t+768];
}

// block per (b,h); 256 threads; qkv read directly from 2 split-K partials
__global__ void __launch_bounds__(256) k_attn(const float* __restrict__ part, long sP,
                                              float* __restrict__ z) {
    extern __shared__ float sm[];
    float* q = sm;
    float* k = q + TT*DHEAD;
    float* v = k + TT*DHEAD;
    float* s = v + TT*DHEAD;        // [65][66]
    int b = blockIdx.x >> 3, h = blockIdx.x & 7;
    int t = threadIdx.x;            // 256
    for (int e = t; e < TT*DHEAD; e += 256) {
        int tt = e >> 6, d = e & 63;
        size_t base = ((size_t)(b*TT + tt))*(3*INNER) + h*64 + d;
        q[e] = part[base]        + part[sP + base];
        k[e] = part[base + 512]  + part[sP + base + 512];
        v[e] = part[base + 1024] + part[sP + base + 1024];
    }
    __syncthreads();
    for (int e = t; e < TT*TT; e += 256) {
        int i = e / TT, j = e - i*TT;
        float acc = 0.f;
        #pragma unroll
        for (int d = 0; d < 64; d++) acc = fmaf(q[i*64+d], k[j*64+d], acc);
        s[i*66 + j] = acc*0.125f;
    }
    __syncthreads();
    int w = t >> 5, lane = t & 31;
    for (int i = w; i < TT; i += 8) {
        float a0 = s[i*66 + lane], a1 = s[i*66 + 32 + lane];
        float a2 = (lane == 0) ? s[i*66 + 64] : -INFINITY;
        float mx = fmaxf(fmaxf(a0, a1), a2);
        for (int off = 16; off; off >>= 1) mx = fmaxf(mx, __shfl_xor_sync(0xffffffffu, mx, off));
        float e0 = expf(a0 - mx), e1 = expf(a1 - mx);
        float e2 = (lane == 0) ? expf(a2 - mx) : 0.f;
        float sum = e0 + e1 + e2;
        for (int off = 16; off; off >>= 1) sum += __shfl_xor_sync(0xffffffffu, sum, off);
        float inv = 1.0f / sum;
        s[i*66 + lane] = e0*inv; s[i*66 + 32 + lane] = e1*inv;
        if (lane == 0) s[i*66 + 64] = e2*inv;
    }
    __syncthreads();
    for (int e = t; e < TT*DHEAD; e += 256) {
        int i = e >> 6, d = e & 63;
        float acc = 0.f;
        for (int j = 0; j < TT; j++) acc = fmaf(s[i*66 + j], v[j*64 + d], acc);
        z[((size_t)(b*TT + i))*INNER + h*64 + d] = acc;
    }
}

__global__ void k_out(float* __restrict__ out) {
    int id = blockIdx.x*256 + threadIdx.x;
    if (id >= BB*PP*DD) return;
    int d = id % DD, p = (id / DD) % PP, b = id / (DD*PP);
    out[id] = g_t[((size_t)(b*TT + 1 + p))*DD + d];
}

// =============================================================================
extern "C" void kernel_launch(void* const* d_in, const int* in_sizes, int n_in,
                              void* d_out, int out_size) {
    const float* x    = (const float*)d_in[0];
    const float* pos  = (const float*)d_in[1];
    const float* w1   = (const float*)d_in[2];
    const float* g1   = (const float*)d_in[3];
    const float* b1   = (const float*)d_in[4];
    const float* w2   = (const float*)d_in[5];
    const float* g2   = (const float*)d_in[6];
    const float* b2   = (const float*)d_in[7];
    const float* w3   = (const float*)d_in[8];
    const float* g3   = (const float*)d_in[9];
    const float* b3   = (const float*)d_in[10];
    const float* w4   = (const float*)d_in[11];
    const float* g4   = (const float*)d_in[12];
    const float* b4   = (const float*)d_in[13];
    const float* w5   = (const float*)d_in[14];
    const float* g5   = (const float*)d_in[15];
    const float* b5   = (const float*)d_in[16];
    const float* cls  = (const float*)d_in[17];
    const float* ln1g = (const float*)d_in[18];
    const float* ln1b = (const float*)d_in[19];
    const float* wqkv = (const float*)d_in[20];
    const float* wout = (const float*)d_in[21];
    const float* bout = (const float*)d_in[22];
    const float* ln2g = (const float*)d_in[23];
    const float* ln2b = (const float*)d_in[24];
    const float* wff1 = (const float*)d_in[25];
    const float* bff1 = (const float*)d_in[26];
    const float* wff2 = (const float*)d_in[27];
    const float* bff2 = (const float*)d_in[28];

    void* p;
    float *h0P, *HP, *xxP, *yP, *ftP, *fbP, *wcP, *tP, *hnP, *qkvP, *zP, *ffP;
    double *sumdP, *ssqdP;
    cudaGetSymbolAddress(&p, g_h0);    h0P   = (float*)p;
    cudaGetSymbolAddress(&p, g_H);     HP    = (float*)p;
    cudaGetSymbolAddress(&p, g_xx);    xxP   = (float*)p;
    cudaGetSymbolAddress(&p, g_y);     yP    = (float*)p;
    cudaGetSymbolAddress(&p, g_ft);    ftP   = (float*)p;
    cudaGetSymbolAddress(&p, g_fpadB); fbP   = (float*)p;
    cudaGetSymbolAddress(&p, g_wc);    wcP   = (float*)p;
    cudaGetSymbolAddress(&p, g_sumd);  sumdP = (double*)p;
    cudaGetSymbolAddress(&p, g_ssqd);  ssqdP = (double*)p;
    cudaGetSymbolAddress(&p, g_t);     tP    = (float*)p;
    cudaGetSymbolAddress(&p, g_hn);    hnP   = (float*)p;
    cudaGetSymbolAddress(&p, g_qkv);   qkvP  = (float*)p;
    cudaGetSymbolAddress(&p, g_z);     zP    = (float*)p;
    cudaGetSymbolAddress(&p, g_ff);    ffP   = (float*)p;
    float* vuP = yP + (size_t)BB*NN*NN;   // vu scratch beyond dist matrix

    int attn_smem = (3*TT*DHEAD + TT*66) * sizeof(float);
    cudaFuncSetAttribute(k_attn, cudaFuncAttributeMaxDynamicSharedMemorySize, attn_smem);

    k_transpose_x<<<(BB*NN + 255)/256, 256>>>(x);
    cudaMemsetAsync(sumdP, 0, 256*NBIN*sizeof(double));
    cudaMemsetAsync(ssqdP, 0, 256*NBIN*sizeof(double));

    dim3 gDist64(NN/64, NN/64, BB);
    dim3 gDist128(NN/128, NN/128, BB);

    // ---- EdgeConv 1: C=3 (Kpad 16) -> O=64 ----
    k_xx<<<(BB*NN + 255)/256, 256>>>(h0P, 3, 0, 3);
    k_gemm<<<gDist64, 256>>>(ftP, fbP, xxP, yP,
        NN, NN, 16, 16, (long)NN*16, (long)16*NN, (long)NN*NN, 4);
    k_topk3<<<BB*NN, 256>>>(yP);
    k_wcat<<<(16*128 + 255)/256, 256>>>(w1, 3, 16, 64, wcP);
    k_gemm128<<<dim3(1, BB*NN/128, 1), 256>>>(ftP, wcP, nullptr, vuP,
        BB*NN, 128, 16, 0L, 0L, 0L, 16, 128, 0, 0);
    k_edgemax<64><<<BB*NN/4, 256>>>(vuP);
    k_finstats<64><<<1, 64>>>();
    k_bnmax<64><<<(BB*NN*64 + 255)/256, 256>>>(g1, b1, 0, ftP, 64, 0);

    // ---- EdgeConv 2: x1 (C=64) -> O=64 ----
    k_xx<<<(BB*NN + 255)/256, 256>>>(HP, 512, 0, 64);
    k_gemm128<<<gDist128, 256>>>(ftP, HP, xxP, yP,
        NN, NN, 64, (long)NN*64, (long)512*NN, (long)NN*NN, 64, NN, 4, 1);
    k_topk3<<<BB*NN, 256>>>(yP);
    k_wcat<<<(64*128 + 255)/256, 256>>>(w2, 64, 64, 64, wcP);
    k_gemm128<<<dim3(1, BB*NN/128, 1), 256>>>(ftP, wcP, nullptr, vuP,
        BB*NN, 128, 64, 0L, 0L, 0L, 64, 128, 0, 0);
    k_edgemax<64><<<BB*NN/4, 256>>>(vuP);
    k_finstats<64><<<1, 64>>>();
    k_bnmax<64><<<(BB*NN*64 + 255)/256, 256>>>(g2, b2, 64, ftP, 64, 0);

    // ---- EdgeConv 3: x2 (C=64) -> O=128 ----
    k_xx<<<(BB*NN + 255)/256, 256>>>(HP, 512, 64, 64);
    k_gemm128<<<gDist128, 256>>>(ftP, HP + (size_t)64*NN, xxP, yP,
        NN, NN, 64, (long)NN*64, (long)512*NN, (long)NN*NN, 64, NN, 4, 1);
    k_topk3<<<BB*NN, 256>>>(yP);
    k_wcat<<<(64*256 + 255)/256, 256>>>(w3, 64, 64, 128, wcP);
    k_gemm128<<<dim3(2, BB*NN/128, 1), 256>>>(ftP, wcP, nullptr, vuP,
        BB*NN, 256, 64, 0L, 0L, 0L, 64, 256, 0, 0);
    k_edgemax<128><<<BB*NN/2, 256>>>(vuP);
    k_finstats<128><<<1, 128>>>();
    k_bnmax<128><<<(BB*NN*128 + 255)/256, 256>>>(g3, b3, 128, ftP, 128, 0);

    // ---- EdgeConv 4: x3 (C=128) -> O=256 ----
    k_xx<<<(BB*NN + 255)/256, 256>>>(HP, 512, 128, 128);
    k_gemm128<<<gDist128, 256>>>(ftP, HP + (size_t)128*NN, xxP, yP,
        NN, NN, 128, (long)NN*128, (long)512*NN, (long)NN*NN, 128, NN, 4, 1);
    k_topk3<<<BB*NN, 256>>>(yP);
    k_wcat<<<(128*512 + 255)/256, 256>>>(w4, 128, 128, 256, wcP);
    k_gemm128<<<dim3(4, BB*NN/128, 1), 256>>>(ftP, wcP, nullptr, vuP,
        BB*NN, 512, 128, 0L, 0L, 0L, 128, 512, 0, 0);
    k_edgemax<256><<<BB*NN, 256>>>(vuP);
    k_finstats<256><<<1, 256>>>();
    k_bnmax<256><<<(BB*NN*256 + 255)/256, 256>>>(g4, b4, 256, nullptr, 0, 0);

    // ---- conv5: y[b] = w5[1024,512] @ H[b][512,2048] ----
    k_gemm128<<<dim3(NN/128, 1024/128, BB), 256>>>(
        w5, HP, nullptr, yP, 1024, NN, 512,
        0L, (long)512*NN, (long)1024*NN, 512, NN, 0, 0);
    k_stats5<<<1024, 256>>>();
    k_pool<<<(BB*DD*PP + 255)/256, 256>>>(g5, b5, cls);

    // ---- transformer: split-K DB GEMMs + reduce epilogues -------------------
    int mrows = (TOK + 63)/64;   // 9
    for (int i = 0; i < DEPTH; i++) {
        k_ln<<<TOK, 256>>>(pos, ln1g + (size_t)i*DD, ln1b + (size_t)i*DD, hnP);
        // qkv: 520x1536, K=1024 split 2; partials consumed directly by k_attn
        k_gemmDB<<<dim3((3*INNER)/64, mrows, 2), 256>>>(
            hnP, wqkv + (size_t)i*DD*3*INNER, yP,
            TOK, 3*INNER, 512, DD, 512L, (long)512*3*INNER, (long)TOK*3*INNER);
        k_attn<<<BB*NHEAD, 256, attn_smem>>>(yP, (long)TOK*3*INNER, zP);
        // out: 520x1024, K=512 split 2, residual
        k_gemmDB<<<dim3(DD/64, mrows, 2), 256>>>(
            zP, wout + (size_t)i*INNER*DD, yP,
            TOK, DD, 256, INNER, 256L, (long)256*DD, (long)TOK*DD);
        k_reduce<<<(TOK*DD + 255)/256, 256>>>(
            yP, (long)TOK*DD, 2, bout + (size_t)i*DD, tP, DD, TOK*DD, 3);
        k_ln<<<TOK, 256>>>(nullptr, ln2g + (size_t)i*DD, ln2b + (size_t)i*DD, hnP);
        // ff1: 520x2048, K=1024 split 2, gelu
        k_gemmDB<<<dim3(MLPD/64, mrows, 2), 256>>>(
            hnP, wff1 + (size_t)i*DD*MLPD, yP,
            TOK, MLPD, 512, DD, 512L, (long)512*MLPD, (long)TOK*MLPD);
        k_reduce<<<(TOK*MLPD + 255)/256, 256>>>(
            yP, (long)TOK*MLPD, 2, bff1 + (size_t)i*MLPD, ffP, MLPD, TOK*MLPD, 2);
        // ff2: 520x1024, K=2048 split 4, residual
        k_gemmDB<<<dim3(DD/64, mrows, 4), 256>>>(
            ffP, wff2 + (size_t)i*MLPD*DD, yP,
            TOK, DD, 512, MLPD, 512L, (long)512*DD, (long)TOK*DD);
        k_reduce<<<(TOK*DD + 255)/256, 256>>>(
            yP, (long)TOK*DD, 4, bff2 + (size_t)i*DD, tP, DD, TOK*DD, 3);
    }

    k_out<<<(BB*PP*DD + 255)/256, 256>>>((float*)d_out);
}